// round 10
// baseline (speedup 1.0000x reference)
#include <cuda_runtime.h>
#include <math.h>
#include <stdint.h>

// ---------------- problem constants ----------------
#define DIMN     1024
#define HEADS    16
#define HEAD_DIM 64
#define LAYERS   4
#define HIDDEN   4096
#define VOCAB    32000
#define BATCH    2
#define SEQ      1024
#define MTOK     (BATCH*SEQ)
#define EPS      1e-6f

// ---------------- scratch ----------------
__device__ float g_h   [MTOK*DIMN];
__device__ float g_q   [MTOK*DIMN];
__device__ float g_k   [MTOK*DIMN];
__device__ float g_vt  [MTOK*DIMN];
__device__ float g_y   [MTOK*DIMN];
__device__ float g_gate[MTOK*HIDDEN];
__device__ float g_rs  [MTOK];

// ---------------- PTX helpers ----------------
__device__ __forceinline__ uint32_t smem_u32(const void* p) {
    uint32_t a;
    asm("{ .reg .u64 t; cvta.to.shared.u64 t, %1; cvt.u32.u64 %0, t; }"
        : "=r"(a) : "l"(p));
    return a;
}

__device__ __forceinline__ void ldm4(uint32_t* r, uint32_t addr) {
    asm volatile("ldmatrix.sync.aligned.m8n8.x4.shared.b16 {%0,%1,%2,%3}, [%4];"
                 : "=r"(r[0]), "=r"(r[1]), "=r"(r[2]), "=r"(r[3]) : "r"(addr));
}

__device__ __forceinline__ void mma16816(float* c, const uint32_t* a, const uint32_t* b) {
    asm volatile("mma.sync.aligned.m16n8k16.row.col.f32.bf16.bf16.f32 "
                 "{%0,%1,%2,%3}, {%4,%5,%6,%7}, {%8,%9}, {%0,%1,%2,%3};"
                 : "+f"(c[0]), "+f"(c[1]), "+f"(c[2]), "+f"(c[3])
                 : "r"(a[0]), "r"(a[1]), "r"(a[2]), "r"(a[3]),
                   "r"(b[0]), "r"(b[1]));
}

__device__ __forceinline__ uint32_t pk_hi(float a, float b) {
    return __byte_perm(__float_as_uint(a), __float_as_uint(b), 0x7632);
}
__device__ __forceinline__ uint32_t pk_lo(float a, float b) {
    float la = a - __uint_as_float(__float_as_uint(a) & 0xFFFF0000u);
    float lb = b - __uint_as_float(__float_as_uint(b) & 0xFFFF0000u);
    return __byte_perm(__float_as_uint(la), __float_as_uint(lb), 0x7632);
}

__device__ __forceinline__ void split_store(uint32_t hi_base, uint32_t lo_base,
                                            int row, int k4, float4 f) {
    uint32_t h01 = pk_hi(f.x, f.y), h23 = pk_hi(f.z, f.w);
    uint32_t l01 = pk_lo(f.x, f.y), l23 = pk_lo(f.z, f.w);
    int chunk = k4 >> 1, half = k4 & 1;
    uint32_t off = (uint32_t)(row * 64 + ((chunk ^ ((row >> 1) & 3)) << 4) + half * 8);
    asm volatile("st.shared.v2.b32 [%0], {%1,%2};" :: "r"(hi_base + off), "r"(h01), "r"(h23));
    asm volatile("st.shared.v2.b32 [%0], {%1,%2};" :: "r"(lo_base + off), "r"(l01), "r"(l23));
}

// ---------------- GEMM body (mainloop validated since R4) -----------------
// EPI: 0 = store, 1 = accumulate into C, 2 = C = silu(C)*acc, 3 = vt scatter.
// NORMA: A rows scaled by rs[row] * wln[k] (fused rmsnorm).
template<int BN, int EPI, bool NORMA>
__device__ __forceinline__ void gemm_body(
    const float* __restrict__ A, int lda,
    const float* __restrict__ B, int ldb,
    float*       __restrict__ C, int ldc,
    int K, float alpha, int m0, int n0,
    const float* __restrict__ rs, const float* __restrict__ wln)
{
    constexpr int WN    = BN / 4;
    constexpr int NA    = WN / 8;
    constexpr int NB4   = BN / 32;
    constexpr int A_LO  = 8192;
    constexpr int B_HI  = 16384;
    constexpr int BLO_D = BN * 64;
    constexpr int STAGE = 16384 + BN * 128;

    extern __shared__ char smem[];
    const uint32_t sb0 = smem_u32(smem);

    const int tid = threadIdx.x, lane = tid & 31, wid = tid >> 5;
    const int wm = wid & 1, wn = wid >> 1;

    uint32_t offA[4][2], offB[NA / 2][2];
    #pragma unroll
    for (int am = 0; am < 4; am++)
        #pragma unroll
        for (int kh = 0; kh < 2; kh++) {
            int mrow  = wm * 64 + am * 16 + (lane & 7) + ((lane >> 3) & 1) * 8;
            int chunk = kh * 2 + ((lane >> 4) & 1);
            offA[am][kh] = (uint32_t)(mrow * 64 + ((chunk ^ ((mrow >> 1) & 3)) << 4));
        }
    #pragma unroll
    for (int p = 0; p < NA / 2; p++)
        #pragma unroll
        for (int kh = 0; kh < 2; kh++) {
            int nrow  = wn * WN + p * 16 + (lane & 7) + ((lane >> 4) & 1) * 8;
            int chunk = kh * 2 + ((lane >> 3) & 1);
            offB[p][kh] = (uint32_t)(B_HI + nrow * 64 + ((chunk ^ ((nrow >> 1) & 3)) << 4));
        }

    float acc[4][NA][4];
    #pragma unroll
    for (int i = 0; i < 4; i++)
        #pragma unroll
        for (int j = 0; j < NA; j++)
            #pragma unroll
            for (int e = 0; e < 4; e++) acc[i][j][e] = 0.0f;

    float4 pa[4], pb[NB4];
    auto LOADG = [&](int k0) {
        #pragma unroll
        for (int i = 0; i < 4; i++) {
            int idx = i * 256 + tid, row = idx >> 3, k4 = idx & 7;
            float4 f = *(const float4*)&A[(long)(m0 + row) * lda + k0 + k4 * 4];
            if (NORMA) {
                float s = rs[m0 + row];
                float4 wv = *(const float4*)&wln[k0 + k4 * 4];
                f.x *= s * wv.x; f.y *= s * wv.y;
                f.z *= s * wv.z; f.w *= s * wv.w;
            }
            pa[i] = f;
        }
        #pragma unroll
        for (int i = 0; i < NB4; i++) {
            int idx = i * 256 + tid, row = idx >> 3, k4 = idx & 7;
            pb[i] = *(const float4*)&B[(long)(n0 + row) * ldb + k0 + k4 * 4];
        }
    };
    auto STORES = [&](uint32_t base) {
        #pragma unroll
        for (int i = 0; i < 4; i++) {
            int idx = i * 256 + tid, row = idx >> 3, k4 = idx & 7;
            split_store(base, base + A_LO, row, k4, pa[i]);
        }
        #pragma unroll
        for (int i = 0; i < NB4; i++) {
            int idx = i * 256 + tid, row = idx >> 3, k4 = idx & 7;
            split_store(base + B_HI, base + B_HI + BLO_D, row, k4, pb[i]);
        }
    };

    const int nk = K >> 5;
    LOADG(0);
    STORES(sb0);
    __syncthreads();

    for (int t = 0; t < nk; t++) {
        const uint32_t sb = sb0 + (uint32_t)(t & 1) * STAGE;
        if (t + 1 < nk) LOADG((t + 1) * 32);

        #pragma unroll
        for (int kh = 0; kh < 2; kh++) {
            uint32_t ah[4][4], al[4][4];
            #pragma unroll
            for (int am = 0; am < 4; am++) {
                ldm4(ah[am], sb + offA[am][kh]);
                ldm4(al[am], sb + offA[am][kh] + A_LO);
            }
            uint32_t bh[NA / 2][4], bl[NA / 2][4];
            #pragma unroll
            for (int p = 0; p < NA / 2; p++) {
                ldm4(bh[p], sb + offB[p][kh]);
                ldm4(bl[p], sb + offB[p][kh] + BLO_D);
            }
            #pragma unroll
            for (int am = 0; am < 4; am++)
                #pragma unroll
                for (int na = 0; na < NA; na++) {
                    const uint32_t* bhp = &bh[na >> 1][(na & 1) * 2];
                    const uint32_t* blp = &bl[na >> 1][(na & 1) * 2];
                    mma16816(acc[am][na], ah[am], bhp);
                    mma16816(acc[am][na], ah[am], blp);
                    mma16816(acc[am][na], al[am], bhp);
                }
        }

        if (t + 1 < nk) STORES(sb0 + (uint32_t)((t & 1) ^ 1) * STAGE);
        __syncthreads();
    }

    #pragma unroll
    for (int am = 0; am < 4; am++)
        #pragma unroll
        for (int na = 0; na < NA; na++) {
            int row = m0 + wm * 64 + am * 16 + (lane >> 2);
            int col = n0 + wn * WN + na * 8 + (lane & 3) * 2;
            float2 r0 = { alpha * acc[am][na][0], alpha * acc[am][na][1] };
            float2 r1 = { alpha * acc[am][na][2], alpha * acc[am][na][3] };
            if constexpr (EPI == 3) {
                // vt[(b*16+h)*64+d][s] = value
                int hidx = col >> 6, d = col & 63;
                int b0 = row >> 10, s0 = row & 1023;
                long base = ((long)(b0 * HEADS + hidx) * HEAD_DIM + d) * SEQ + s0;
                C[base]           = r0.x;
                C[base + SEQ]     = r0.y;
                C[base + 8]       = r1.x;
                C[base + SEQ + 8] = r1.y;
            } else {
                float* base0 = &C[(long)row * ldc + col];
                float* base1 = &C[(long)(row + 8) * ldc + col];
                if constexpr (EPI == 1) {
                    float2 o0 = *(float2*)base0, o1 = *(float2*)base1;
                    r0.x += o0.x; r0.y += o0.y; r1.x += o1.x; r1.y += o1.y;
                } else if constexpr (EPI == 2) {
                    float2 g0 = *(float2*)base0, g1 = *(float2*)base1;
                    r0.x *= g0.x / (1.0f + __expf(-g0.x));
                    r0.y *= g0.y / (1.0f + __expf(-g0.y));
                    r1.x *= g1.x / (1.0f + __expf(-g1.x));
                    r1.y *= g1.y / (1.0f + __expf(-g1.y));
                }
                *(float2*)base0 = r0;
                *(float2*)base1 = r1;
            }
        }
}

template<int BN, int EPI, bool NORMA>
__global__ void __launch_bounds__(256, 1)
gemm_std(const float* __restrict__ A, int lda,
         const float* __restrict__ B, int ldb,
         float*       __restrict__ C, int ldc,
         int K, float alpha,
         const float* __restrict__ rs, const float* __restrict__ wln)
{
    gemm_body<BN, EPI, NORMA>(A, lda, B, ldb, C, ldc, K, alpha,
                              blockIdx.x * 128, blockIdx.y * BN, rs, wln);
}

struct P3 {
    const float *B0, *B1, *B2;
    float *C0, *C1, *C2;
};

// fused QKV: z=0 -> q, z=1 -> k, z=2 -> vt (transposed scatter)
__global__ void __launch_bounds__(256, 1)
gemm_qkv(const float* __restrict__ A, int lda, P3 p, int ldb, int ldc,
         int K, const float* __restrict__ rs, const float* __restrict__ wln)
{
    const int z = blockIdx.z;
    const int m0 = blockIdx.x * 128, n0 = blockIdx.y * 128;
    if (z == 0)
        gemm_body<128, 0, true>(A, lda, p.B0, ldb, p.C0, ldc, K, 1.0f, m0, n0, rs, wln);
    else if (z == 1)
        gemm_body<128, 0, true>(A, lda, p.B1, ldb, p.C1, ldc, K, 1.0f, m0, n0, rs, wln);
    else
        gemm_body<128, 3, true>(A, lda, p.B2, ldb, p.C2, ldc, K, 1.0f, m0, n0, rs, wln);
}

// ================= flash attention (validated R9) =========================
#define FA_QH 0
#define FA_QL 16384
#define FA_KH 32768
#define FA_KL 49152
#define FA_VH 65536
#define FA_VL 81920
#define FA_PH 98304
#define FA_PL 131072
#define FA_SMX 163840
#define FA_SSM 165888
#define FA_BYTES 167936

__global__ void __launch_bounds__(256, 1)
flash_attn(const float* __restrict__ q, const float* __restrict__ k,
           const float* __restrict__ vt, float* __restrict__ y)
{
    extern __shared__ char smem[];
    const uint32_t sb = smem_u32(smem);
    float* smx = (float*)(smem + FA_SMX);
    float* ssm = (float*)(smem + FA_SSM);

    const int tid = threadIdx.x, lane = tid & 31, wid = tid >> 5;
    const int wm = wid & 1, wn = wid >> 1;
    const int bh = blockIdx.z, b = bh >> 4, hh = bh & 15;
    const int q0 = blockIdx.x * 128;

    uint32_t offA[4][2];
    #pragma unroll
    for (int am = 0; am < 4; am++)
        #pragma unroll
        for (int khi = 0; khi < 2; khi++) {
            int arow  = wm * 64 + am * 16 + (lane & 7) + ((lane >> 3) & 1) * 8;
            int chunk = khi * 2 + ((lane >> 4) & 1);
            offA[am][khi] = (uint32_t)(arow * 64 + ((chunk ^ ((arow >> 1) & 3)) << 4));
        }
    uint32_t offK[2][2], offV[2];
    #pragma unroll
    for (int p = 0; p < 2; p++)
        #pragma unroll
        for (int khi = 0; khi < 2; khi++) {
            int brow  = wn * 32 + p * 16 + (lane & 7) + ((lane >> 4) & 1) * 8;
            int chunk = khi * 2 + ((lane >> 3) & 1);
            offK[p][khi] = (uint32_t)(brow * 64 + ((chunk ^ ((brow >> 1) & 3)) << 4));
        }
    #pragma unroll
    for (int khi = 0; khi < 2; khi++) {
        int brow  = wn * 16 + (lane & 7) + ((lane >> 4) & 1) * 8;
        int chunk = khi * 2 + ((lane >> 3) & 1);
        offV[khi] = (uint32_t)(brow * 64 + ((chunk ^ ((brow >> 1) & 3)) << 4));
    }

    #pragma unroll
    for (int i = 0; i < 8; i++) {
        int idx = i * 256 + tid, row = idx >> 4, k4 = idx & 15;
        float4 f = *(const float4*)&q[(long)(b * SEQ + q0 + row) * DIMN + hh * 64 + k4 * 4];
        f.x *= 0.125f; f.y *= 0.125f; f.z *= 0.125f; f.w *= 0.125f;
        split_store(sb + FA_QH + (k4 >> 3) * 8192, sb + FA_QL + (k4 >> 3) * 8192,
                    row, k4 & 7, f);
    }

    float o[4][2][4];
    float m_r[4][2], l_r[4][2];
    #pragma unroll
    for (int am = 0; am < 4; am++) {
        m_r[am][0] = m_r[am][1] = -1e30f;
        l_r[am][0] = l_r[am][1] = 0.0f;
        #pragma unroll
        for (int na = 0; na < 2; na++)
            #pragma unroll
            for (int e = 0; e < 4; e++) o[am][na][e] = 0.0f;
    }

    const int rb = wm * 64 + (lane >> 2);

    for (int s0 = 0; s0 < SEQ; s0 += 128) {
        __syncthreads();

        #pragma unroll
        for (int i = 0; i < 8; i++) {
            int idx = i * 256 + tid, row = idx >> 4, k4 = idx & 15;
            float4 f = *(const float4*)&k[(long)(b * SEQ + s0 + row) * DIMN + hh * 64 + k4 * 4];
            split_store(sb + FA_KH + (k4 >> 3) * 8192, sb + FA_KL + (k4 >> 3) * 8192,
                        row, k4 & 7, f);
        }
        #pragma unroll
        for (int i = 0; i < 8; i++) {
            int idx = i * 256 + tid, row = idx >> 5, sc = idx & 31;
            float4 f = *(const float4*)&vt[((long)bh * 64 + row) * SEQ + s0 + sc * 4];
            split_store(sb + FA_VH + (sc >> 3) * 4096, sb + FA_VL + (sc >> 3) * 4096,
                        row, sc & 7, f);
        }
        __syncthreads();

        float sf[4][4][4];
        #pragma unroll
        for (int am = 0; am < 4; am++)
            #pragma unroll
            for (int na = 0; na < 4; na++)
                #pragma unroll
                for (int e = 0; e < 4; e++) sf[am][na][e] = 0.0f;

        #pragma unroll
        for (int kb = 0; kb < 2; kb++)
            #pragma unroll
            for (int khi = 0; khi < 2; khi++) {
                uint32_t ah[4][4], al[4][4];
                #pragma unroll
                for (int am = 0; am < 4; am++) {
                    ldm4(ah[am], sb + FA_QH + kb * 8192 + offA[am][khi]);
                    ldm4(al[am], sb + FA_QL + kb * 8192 + offA[am][khi]);
                }
                uint32_t bhf[2][4], blf[2][4];
                #pragma unroll
                for (int p = 0; p < 2; p++) {
                    ldm4(bhf[p], sb + FA_KH + kb * 8192 + offK[p][khi]);
                    ldm4(blf[p], sb + FA_KL + kb * 8192 + offK[p][khi]);
                }
                #pragma unroll
                for (int am = 0; am < 4; am++)
                    #pragma unroll
                    for (int na = 0; na < 4; na++) {
                        const uint32_t* bhp = &bhf[na >> 1][(na & 1) * 2];
                        const uint32_t* blp = &blf[na >> 1][(na & 1) * 2];
                        mma16816(sf[am][na], ah[am], bhp);
                        mma16816(sf[am][na], ah[am], blp);
                        mma16816(sf[am][na], al[am], bhp);
                    }
            }

        #pragma unroll
        for (int am = 0; am < 4; am++) {
            float v0 = -1e30f, v1 = -1e30f;
            #pragma unroll
            for (int na = 0; na < 4; na++) {
                v0 = fmaxf(v0, fmaxf(sf[am][na][0], sf[am][na][1]));
                v1 = fmaxf(v1, fmaxf(sf[am][na][2], sf[am][na][3]));
            }
            v0 = fmaxf(v0, __shfl_xor_sync(0xFFFFFFFFu, v0, 1));
            v0 = fmaxf(v0, __shfl_xor_sync(0xFFFFFFFFu, v0, 2));
            v1 = fmaxf(v1, __shfl_xor_sync(0xFFFFFFFFu, v1, 1));
            v1 = fmaxf(v1, __shfl_xor_sync(0xFFFFFFFFu, v1, 2));
            if ((lane & 3) == 0) {
                smx[(rb + am * 16) * 4 + wn] = v0;
                smx[(rb + am * 16 + 8) * 4 + wn] = v1;
            }
        }
        __syncthreads();

        float csc[4][2];
        #pragma unroll
        for (int am = 0; am < 4; am++) {
            int r0 = rb + am * 16, r1 = r0 + 8;
            float tm0 = fmaxf(fmaxf(smx[r0 * 4 + 0], smx[r0 * 4 + 1]),
                              fmaxf(smx[r0 * 4 + 2], smx[r0 * 4 + 3]));
            float tm1 = fmaxf(fmaxf(smx[r1 * 4 + 0], smx[r1 * 4 + 1]),
                              fmaxf(smx[r1 * 4 + 2], smx[r1 * 4 + 3]));
            float mn0 = fmaxf(m_r[am][0], tm0);
            float mn1 = fmaxf(m_r[am][1], tm1);
            csc[am][0] = __expf(m_r[am][0] - mn0);
            csc[am][1] = __expf(m_r[am][1] - mn1);
            m_r[am][0] = mn0; m_r[am][1] = mn1;

            float rs0 = 0.0f, rs1 = 0.0f;
            #pragma unroll
            for (int na = 0; na < 4; na++) {
                float p0 = __expf(sf[am][na][0] - mn0);
                float p1 = __expf(sf[am][na][1] - mn0);
                float p2 = __expf(sf[am][na][2] - mn1);
                float p3 = __expf(sf[am][na][3] - mn1);
                rs0 += p0 + p1; rs1 += p2 + p3;
                int c0col = wn * 32 + na * 8 + (lane & 3) * 2;
                int kb = c0col >> 5, cc = c0col & 31;
                uint32_t o0 = (uint32_t)(kb * 8192 + r0 * 64 +
                              (((cc >> 3) ^ ((r0 >> 1) & 3)) << 4) +
                              ((cc >> 2) & 1) * 8 + (cc & 3) * 2);
                uint32_t o1 = (uint32_t)(kb * 8192 + r1 * 64 +
                              (((cc >> 3) ^ ((r1 >> 1) & 3)) << 4) +
                              ((cc >> 2) & 1) * 8 + (cc & 3) * 2);
                *(uint32_t*)(smem + FA_PH + o0) = pk_hi(p0, p1);
                *(uint32_t*)(smem + FA_PL + o0) = pk_lo(p0, p1);
                *(uint32_t*)(smem + FA_PH + o1) = pk_hi(p2, p3);
                *(uint32_t*)(smem + FA_PL + o1) = pk_lo(p2, p3);
            }
            rs0 += __shfl_xor_sync(0xFFFFFFFFu, rs0, 1);
            rs0 += __shfl_xor_sync(0xFFFFFFFFu, rs0, 2);
            rs1 += __shfl_xor_sync(0xFFFFFFFFu, rs1, 1);
            rs1 += __shfl_xor_sync(0xFFFFFFFFu, rs1, 2);
            if ((lane & 3) == 0) {
                ssm[r0 * 4 + wn] = rs0;
                ssm[r1 * 4 + wn] = rs1;
            }
        }
        __syncthreads();

        #pragma unroll
        for (int am = 0; am < 4; am++) {
            int r0 = rb + am * 16, r1 = r0 + 8;
            float s0s = ssm[r0 * 4 + 0] + ssm[r0 * 4 + 1] + ssm[r0 * 4 + 2] + ssm[r0 * 4 + 3];
            float s1s = ssm[r1 * 4 + 0] + ssm[r1 * 4 + 1] + ssm[r1 * 4 + 2] + ssm[r1 * 4 + 3];
            l_r[am][0] = l_r[am][0] * csc[am][0] + s0s;
            l_r[am][1] = l_r[am][1] * csc[am][1] + s1s;
            #pragma unroll
            for (int na = 0; na < 2; na++) {
                o[am][na][0] *= csc[am][0]; o[am][na][1] *= csc[am][0];
                o[am][na][2] *= csc[am][1]; o[am][na][3] *= csc[am][1];
            }
        }

        #pragma unroll
        for (int kb = 0; kb < 4; kb++)
            #pragma unroll
            for (int khi = 0; khi < 2; khi++) {
                uint32_t ah[4][4], al[4][4];
                #pragma unroll
                for (int am = 0; am < 4; am++) {
                    ldm4(ah[am], sb + FA_PH + kb * 8192 + offA[am][khi]);
                    ldm4(al[am], sb + FA_PL + kb * 8192 + offA[am][khi]);
                }
                uint32_t bhf[4], blf[4];
                ldm4(bhf, sb + FA_VH + kb * 4096 + offV[khi]);
                ldm4(blf, sb + FA_VL + kb * 4096 + offV[khi]);
                #pragma unroll
                for (int am = 0; am < 4; am++)
                    #pragma unroll
                    for (int na = 0; na < 2; na++) {
                        const uint32_t* bhp = &bhf[na * 2];
                        const uint32_t* blp = &blf[na * 2];
                        mma16816(o[am][na], ah[am], bhp);
                        mma16816(o[am][na], ah[am], blp);
                        mma16816(o[am][na], al[am], bhp);
                    }
            }
    }

    #pragma unroll
    for (int am = 0; am < 4; am++) {
        float inv0 = 1.0f / l_r[am][0];
        float inv1 = 1.0f / l_r[am][1];
        long tok0 = (long)(b * SEQ + q0 + wm * 64 + am * 16 + (lane >> 2));
        #pragma unroll
        for (int na = 0; na < 2; na++) {
            int col = hh * 64 + wn * 16 + na * 8 + (lane & 3) * 2;
            float2 r0 = { o[am][na][0] * inv0, o[am][na][1] * inv0 };
            float2 r1 = { o[am][na][2] * inv1, o[am][na][3] * inv1 };
            *(float2*)&y[tok0 * DIMN + col] = r0;
            *(float2*)&y[(tok0 + 8) * DIMN + col] = r1;
        }
    }
}

// ---------------- small kernels ----------------
__global__ void embed_kernel(const int* __restrict__ tokens,
                             const float* __restrict__ embed,
                             float* __restrict__ h)
{
    int row = blockIdx.x;
    int tok = tokens[row];
    ((float4*)(h + (long)row * DIMN))[threadIdx.x] =
        ((const float4*)(embed + (long)tok * DIMN))[threadIdx.x];
}

// rs[t] = rsqrt(mean(h[t]^2)+eps); one warp per row
__global__ void rs_kernel(const float* __restrict__ x, float* __restrict__ rs)
{
    int row = blockIdx.x * 8 + (threadIdx.x >> 5);
    int lane = threadIdx.x & 31;
    const float4* xr = (const float4*)(x + (long)row * DIMN);
    float ss = 0.0f;
    #pragma unroll
    for (int i = 0; i < 8; i++) {
        float4 v = xr[lane + i * 32];
        ss += v.x*v.x + v.y*v.y + v.z*v.z + v.w*v.w;
    }
    #pragma unroll
    for (int o = 16; o > 0; o >>= 1) ss += __shfl_xor_sync(0xFFFFFFFFu, ss, o);
    if (lane == 0) rs[row] = rsqrtf(ss * (1.0f / DIMN) + EPS);
}

// ---------------- launcher ----------------
extern "C" void kernel_launch(void* const* d_in, const int* in_sizes, int n_in,
                              void* d_out, int out_size)
{
    const int*   tokens  = (const int*)  d_in[0];
    const float* embed   = (const float*)d_in[1];
    const float* Wq      = (const float*)d_in[2];
    const float* Wk      = (const float*)d_in[3];
    const float* Wv      = (const float*)d_in[4];
    const float* Wo      = (const float*)d_in[5];
    const float* Wg      = (const float*)d_in[6];
    const float* Wu      = (const float*)d_in[7];
    const float* Wd      = (const float*)d_in[8];
    const float* ln1     = (const float*)d_in[9];
    const float* ln2     = (const float*)d_in[10];
    const float* norm_w  = (const float*)d_in[11];
    const float* lm_head = (const float*)d_in[12];
    float* out = (float*)d_out;

    float *h, *q, *k, *vt, *y, *gate, *rsb;
    cudaGetSymbolAddress((void**)&h,    g_h);
    cudaGetSymbolAddress((void**)&q,    g_q);
    cudaGetSymbolAddress((void**)&k,    g_k);
    cudaGetSymbolAddress((void**)&vt,   g_vt);
    cudaGetSymbolAddress((void**)&y,    g_y);
    cudaGetSymbolAddress((void**)&gate, g_gate);
    cudaGetSymbolAddress((void**)&rsb,  g_rs);

    const int DYN128 = 2 * (16384 + 128 * 128);   // 65536
    cudaFuncSetAttribute(gemm_std<128, 0, true>,  cudaFuncAttributeMaxDynamicSharedMemorySize, DYN128);
    cudaFuncSetAttribute(gemm_std<128, 2, true>,  cudaFuncAttributeMaxDynamicSharedMemorySize, DYN128);
    cudaFuncSetAttribute(gemm_std<128, 1, false>, cudaFuncAttributeMaxDynamicSharedMemorySize, DYN128);
    cudaFuncSetAttribute(gemm_qkv, cudaFuncAttributeMaxDynamicSharedMemorySize, DYN128);
    cudaFuncSetAttribute(flash_attn, cudaFuncAttributeMaxDynamicSharedMemorySize, FA_BYTES);

    embed_kernel<<<MTOK, 256>>>(tokens, embed, h);

    dim3 gQKV (MTOK / 128, DIMN / 128, 3);
    dim3 gFfn (MTOK / 128, HIDDEN / 128, 1);
    dim3 gProj(MTOK / 128, DIMN / 128, 1);
    dim3 gHead(MTOK / 128, VOCAB / 128, 1);
    dim3 gFa  (SEQ / 128, 1, BATCH * HEADS);

    for (int l = 0; l < LAYERS; l++) {
        const float* wq = Wq + (long)l * DIMN * DIMN;
        const float* wk = Wk + (long)l * DIMN * DIMN;
        const float* wv = Wv + (long)l * DIMN * DIMN;
        const float* wo = Wo + (long)l * DIMN * DIMN;
        const float* wg = Wg + (long)l * HIDDEN * DIMN;
        const float* wu = Wu + (long)l * HIDDEN * DIMN;
        const float* wd = Wd + (long)l * DIMN * HIDDEN;

        rs_kernel<<<MTOK / 8, 256>>>(h, rsb);

        // q,k = rmsnorm(h)@W^T; vt = (rmsnorm(h)@Wv^T) transposed scatter
        {
            P3 p = { wq, wk, wv, q, k, vt };
            gemm_qkv<<<gQKV, 256, DYN128>>>(h, DIMN, p, DIMN, DIMN, DIMN,
                                            rsb, ln1 + (long)l * DIMN);
        }

        flash_attn<<<gFa, 256, FA_BYTES>>>(q, k, vt, y);

        // h += y @ Wo^T
        gemm_std<128, 1, false><<<gProj, 256, DYN128>>>(
            y, DIMN, wo, DIMN, h, DIMN, DIMN, 1.0f, nullptr, nullptr);

        rs_kernel<<<MTOK / 8, 256>>>(h, rsb);

        // gate = rmsnorm(h) @ Wg^T
        gemm_std<128, 0, true><<<gFfn, 256, DYN128>>>(
            h, DIMN, wg, DIMN, gate, HIDDEN, DIMN, 1.0f,
            rsb, ln2 + (long)l * DIMN);
        // gate = silu(gate) * (rmsnorm(h) @ Wu^T)
        gemm_std<128, 2, true><<<gFfn, 256, DYN128>>>(
            h, DIMN, wu, DIMN, gate, HIDDEN, DIMN, 1.0f,
            rsb, ln2 + (long)l * DIMN);

        // h += gate @ Wd^T
        gemm_std<128, 1, false><<<gProj, 256, DYN128>>>(
            gate, HIDDEN, wd, HIDDEN, h, DIMN, HIDDEN, 1.0f, nullptr, nullptr);
    }

    rs_kernel<<<MTOK / 8, 256>>>(h, rsb);
    gemm_std<128, 0, true><<<gHead, 256, DYN128>>>(
        h, DIMN, lm_head, DIMN, out, VOCAB, DIMN, 1.0f, rsb, norm_w);
}

// round 11
// speedup vs baseline: 1.1481x; 1.1481x over previous
#include <cuda_runtime.h>
#include <math.h>
#include <stdint.h>

// ---------------- problem constants ----------------
#define DIMN     1024
#define HEADS    16
#define HEAD_DIM 64
#define LAYERS   4
#define HIDDEN   4096
#define VOCAB    32000
#define BATCH    2
#define SEQ      1024
#define MTOK     (BATCH*SEQ)
#define EPS      1e-6f

// ---------------- scratch ----------------
__device__ float g_h   [MTOK*DIMN];
__device__ float g_x   [MTOK*DIMN];
__device__ float g_q   [MTOK*DIMN];
__device__ float g_k   [MTOK*DIMN];
__device__ float g_v   [MTOK*DIMN];
__device__ float g_vt  [MTOK*DIMN];
__device__ float g_y   [MTOK*DIMN];
__device__ float g_gate[MTOK*HIDDEN];

// ---------------- PTX helpers ----------------
__device__ __forceinline__ uint32_t smem_u32(const void* p) {
    uint32_t a;
    asm("{ .reg .u64 t; cvta.to.shared.u64 t, %1; cvt.u32.u64 %0, t; }"
        : "=r"(a) : "l"(p));
    return a;
}

__device__ __forceinline__ void ldm4(uint32_t* r, uint32_t addr) {
    asm volatile("ldmatrix.sync.aligned.m8n8.x4.shared.b16 {%0,%1,%2,%3}, [%4];"
                 : "=r"(r[0]), "=r"(r[1]), "=r"(r[2]), "=r"(r[3]) : "r"(addr));
}

__device__ __forceinline__ void mma16816(float* c, const uint32_t* a, const uint32_t* b) {
    asm volatile("mma.sync.aligned.m16n8k16.row.col.f32.bf16.bf16.f32 "
                 "{%0,%1,%2,%3}, {%4,%5,%6,%7}, {%8,%9}, {%0,%1,%2,%3};"
                 : "+f"(c[0]), "+f"(c[1]), "+f"(c[2]), "+f"(c[3])
                 : "r"(a[0]), "r"(a[1]), "r"(a[2]), "r"(a[3]),
                   "r"(b[0]), "r"(b[1]));
}

__device__ __forceinline__ uint32_t pk_hi(float a, float b) {
    return __byte_perm(__float_as_uint(a), __float_as_uint(b), 0x7632);
}
__device__ __forceinline__ uint32_t pk_lo(float a, float b) {
    float la = a - __uint_as_float(__float_as_uint(a) & 0xFFFF0000u);
    float lb = b - __uint_as_float(__float_as_uint(b) & 0xFFFF0000u);
    return __byte_perm(__float_as_uint(la), __float_as_uint(lb), 0x7632);
}

__device__ __forceinline__ void split_store(uint32_t hi_base, uint32_t lo_base,
                                            int row, int k4, float4 f) {
    uint32_t h01 = pk_hi(f.x, f.y), h23 = pk_hi(f.z, f.w);
    uint32_t l01 = pk_lo(f.x, f.y), l23 = pk_lo(f.z, f.w);
    int chunk = k4 >> 1, half = k4 & 1;
    uint32_t off = (uint32_t)(row * 64 + ((chunk ^ ((row >> 1) & 3)) << 4) + half * 8);
    asm volatile("st.shared.v2.b32 [%0], {%1,%2};" :: "r"(hi_base + off), "r"(h01), "r"(h23));
    asm volatile("st.shared.v2.b32 [%0], {%1,%2};" :: "r"(lo_base + off), "r"(l01), "r"(l23));
}

// ---------------- GEMM body (validated since R4) -----------------
// EPI: 0 = store, 1 = accumulate into C, 2 = C = silu(C) * result
template<int BN, int EPI>
__device__ __forceinline__ void gemm_body(
    const float* __restrict__ A, int lda,
    const float* __restrict__ B, int ldb,
    float*       __restrict__ C, int ldc,
    int K, float alpha, int m0, int n0)
{
    constexpr int WN    = BN / 4;
    constexpr int NA    = WN / 8;
    constexpr int NB4   = BN / 32;
    constexpr int A_LO  = 8192;
    constexpr int B_HI  = 16384;
    constexpr int BLO_D = BN * 64;
    constexpr int STAGE = 16384 + BN * 128;

    extern __shared__ char smem[];
    const uint32_t sb0 = smem_u32(smem);

    const int tid = threadIdx.x, lane = tid & 31, wid = tid >> 5;
    const int wm = wid & 1, wn = wid >> 1;

    uint32_t offA[4][2], offB[NA / 2][2];
    #pragma unroll
    for (int am = 0; am < 4; am++)
        #pragma unroll
        for (int kh = 0; kh < 2; kh++) {
            int mrow  = wm * 64 + am * 16 + (lane & 7) + ((lane >> 3) & 1) * 8;
            int chunk = kh * 2 + ((lane >> 4) & 1);
            offA[am][kh] = (uint32_t)(mrow * 64 + ((chunk ^ ((mrow >> 1) & 3)) << 4));
        }
    #pragma unroll
    for (int p = 0; p < NA / 2; p++)
        #pragma unroll
        for (int kh = 0; kh < 2; kh++) {
            int nrow  = wn * WN + p * 16 + (lane & 7) + ((lane >> 4) & 1) * 8;
            int chunk = kh * 2 + ((lane >> 3) & 1);
            offB[p][kh] = (uint32_t)(B_HI + nrow * 64 + ((chunk ^ ((nrow >> 1) & 3)) << 4));
        }

    float acc[4][NA][4];
    #pragma unroll
    for (int i = 0; i < 4; i++)
        #pragma unroll
        for (int j = 0; j < NA; j++)
            #pragma unroll
            for (int e = 0; e < 4; e++) acc[i][j][e] = 0.0f;

    float4 pa[4], pb[NB4];
    auto LOADG = [&](int k0) {
        #pragma unroll
        for (int i = 0; i < 4; i++) {
            int idx = i * 256 + tid, row = idx >> 3, k4 = idx & 7;
            pa[i] = *(const float4*)&A[(long)(m0 + row) * lda + k0 + k4 * 4];
        }
        #pragma unroll
        for (int i = 0; i < NB4; i++) {
            int idx = i * 256 + tid, row = idx >> 3, k4 = idx & 7;
            pb[i] = *(const float4*)&B[(long)(n0 + row) * ldb + k0 + k4 * 4];
        }
    };
    auto STORES = [&](uint32_t base) {
        #pragma unroll
        for (int i = 0; i < 4; i++) {
            int idx = i * 256 + tid, row = idx >> 3, k4 = idx & 7;
            split_store(base, base + A_LO, row, k4, pa[i]);
        }
        #pragma unroll
        for (int i = 0; i < NB4; i++) {
            int idx = i * 256 + tid, row = idx >> 3, k4 = idx & 7;
            split_store(base + B_HI, base + B_HI + BLO_D, row, k4, pb[i]);
        }
    };

    const int nk = K >> 5;
    LOADG(0);
    STORES(sb0);
    __syncthreads();

    for (int t = 0; t < nk; t++) {
        const uint32_t sb = sb0 + (uint32_t)(t & 1) * STAGE;
        if (t + 1 < nk) LOADG((t + 1) * 32);

        #pragma unroll
        for (int kh = 0; kh < 2; kh++) {
            uint32_t ah[4][4], al[4][4];
            #pragma unroll
            for (int am = 0; am < 4; am++) {
                ldm4(ah[am], sb + offA[am][kh]);
                ldm4(al[am], sb + offA[am][kh] + A_LO);
            }
            uint32_t bh[NA / 2][4], bl[NA / 2][4];
            #pragma unroll
            for (int p = 0; p < NA / 2; p++) {
                ldm4(bh[p], sb + offB[p][kh]);
                ldm4(bl[p], sb + offB[p][kh] + BLO_D);
            }
            #pragma unroll
            for (int am = 0; am < 4; am++)
                #pragma unroll
                for (int na = 0; na < NA; na++) {
                    const uint32_t* bhp = &bh[na >> 1][(na & 1) * 2];
                    const uint32_t* blp = &bl[na >> 1][(na & 1) * 2];
                    mma16816(acc[am][na], ah[am], bhp);
                    mma16816(acc[am][na], ah[am], blp);
                    mma16816(acc[am][na], al[am], bhp);
                }
        }

        if (t + 1 < nk) STORES(sb0 + (uint32_t)((t & 1) ^ 1) * STAGE);
        __syncthreads();
    }

    #pragma unroll
    for (int am = 0; am < 4; am++)
        #pragma unroll
        for (int na = 0; na < NA; na++) {
            int row = m0 + wm * 64 + am * 16 + (lane >> 2);
            int col = n0 + wn * WN + na * 8 + (lane & 3) * 2;
            float* base0 = &C[(long)row * ldc + col];
            float* base1 = &C[(long)(row + 8) * ldc + col];
            float2 r0 = { alpha * acc[am][na][0], alpha * acc[am][na][1] };
            float2 r1 = { alpha * acc[am][na][2], alpha * acc[am][na][3] };
            if constexpr (EPI == 1) {
                float2 o0 = *(float2*)base0, o1 = *(float2*)base1;
                r0.x += o0.x; r0.y += o0.y; r1.x += o1.x; r1.y += o1.y;
            } else if constexpr (EPI == 2) {
                float2 g0 = *(float2*)base0, g1 = *(float2*)base1;
                r0.x *= g0.x / (1.0f + __expf(-g0.x));
                r0.y *= g0.y / (1.0f + __expf(-g0.y));
                r1.x *= g1.x / (1.0f + __expf(-g1.x));
                r1.y *= g1.y / (1.0f + __expf(-g1.y));
            }
            *(float2*)base0 = r0;
            *(float2*)base1 = r1;
        }
}

template<int BN, int EPI>
__global__ void __launch_bounds__(256, 1)
mma_gemm(const float* __restrict__ A, int lda,
         const float* __restrict__ B, int ldb,
         float*       __restrict__ C, int ldc,
         int K, float alpha)
{
    gemm_body<BN, EPI>(A, lda, B, ldb, C, ldc, K, alpha,
                       blockIdx.x * 128, blockIdx.y * BN);
}

struct P3 {
    const float *B0, *B1, *B2;
    float *C0, *C1, *C2;
};

__global__ void __launch_bounds__(256, 1)
mma_gemm_multi(const float* __restrict__ A, int lda, P3 p,
               int ldb, int ldc, int K, float alpha)
{
    const int z = blockIdx.z;
    const float* B = (z == 0) ? p.B0 : (z == 1) ? p.B1 : p.B2;
    float*       C = (z == 0) ? p.C0 : (z == 1) ? p.C1 : p.C2;
    gemm_body<128, 0>(A, lda, B, ldb, C, ldc, K, alpha,
                      blockIdx.x * 128, blockIdx.y * 128);
}

// ================= flash attention (validated R9) =========================
#define FA_QH 0
#define FA_QL 16384
#define FA_KH 32768
#define FA_KL 49152
#define FA_VH 65536
#define FA_VL 81920
#define FA_PH 98304
#define FA_PL 131072
#define FA_SMX 163840
#define FA_SSM 165888
#define FA_BYTES 167936

__global__ void __launch_bounds__(256, 1)
flash_attn(const float* __restrict__ q, const float* __restrict__ k,
           const float* __restrict__ vt, float* __restrict__ y)
{
    extern __shared__ char smem[];
    const uint32_t sb = smem_u32(smem);
    float* smx = (float*)(smem + FA_SMX);
    float* ssm = (float*)(smem + FA_SSM);

    const int tid = threadIdx.x, lane = tid & 31, wid = tid >> 5;
    const int wm = wid & 1, wn = wid >> 1;
    const int bh = blockIdx.z, b = bh >> 4, hh = bh & 15;
    const int q0 = blockIdx.x * 128;

    uint32_t offA[4][2];
    #pragma unroll
    for (int am = 0; am < 4; am++)
        #pragma unroll
        for (int khi = 0; khi < 2; khi++) {
            int arow  = wm * 64 + am * 16 + (lane & 7) + ((lane >> 3) & 1) * 8;
            int chunk = khi * 2 + ((lane >> 4) & 1);
            offA[am][khi] = (uint32_t)(arow * 64 + ((chunk ^ ((arow >> 1) & 3)) << 4));
        }
    uint32_t offK[2][2], offV[2];
    #pragma unroll
    for (int p = 0; p < 2; p++)
        #pragma unroll
        for (int khi = 0; khi < 2; khi++) {
            int brow  = wn * 32 + p * 16 + (lane & 7) + ((lane >> 4) & 1) * 8;
            int chunk = khi * 2 + ((lane >> 3) & 1);
            offK[p][khi] = (uint32_t)(brow * 64 + ((chunk ^ ((brow >> 1) & 3)) << 4));
        }
    #pragma unroll
    for (int khi = 0; khi < 2; khi++) {
        int brow  = wn * 16 + (lane & 7) + ((lane >> 4) & 1) * 8;
        int chunk = khi * 2 + ((lane >> 3) & 1);
        offV[khi] = (uint32_t)(brow * 64 + ((chunk ^ ((brow >> 1) & 3)) << 4));
    }

    #pragma unroll
    for (int i = 0; i < 8; i++) {
        int idx = i * 256 + tid, row = idx >> 4, k4 = idx & 15;
        float4 f = *(const float4*)&q[(long)(b * SEQ + q0 + row) * DIMN + hh * 64 + k4 * 4];
        f.x *= 0.125f; f.y *= 0.125f; f.z *= 0.125f; f.w *= 0.125f;
        split_store(sb + FA_QH + (k4 >> 3) * 8192, sb + FA_QL + (k4 >> 3) * 8192,
                    row, k4 & 7, f);
    }

    float o[4][2][4];
    float m_r[4][2], l_r[4][2];
    #pragma unroll
    for (int am = 0; am < 4; am++) {
        m_r[am][0] = m_r[am][1] = -1e30f;
        l_r[am][0] = l_r[am][1] = 0.0f;
        #pragma unroll
        for (int na = 0; na < 2; na++)
            #pragma unroll
            for (int e = 0; e < 4; e++) o[am][na][e] = 0.0f;
    }

    const int rb = wm * 64 + (lane >> 2);

    for (int s0 = 0; s0 < SEQ; s0 += 128) {
        __syncthreads();

        #pragma unroll
        for (int i = 0; i < 8; i++) {
            int idx = i * 256 + tid, row = idx >> 4, k4 = idx & 15;
            float4 f = *(const float4*)&k[(long)(b * SEQ + s0 + row) * DIMN + hh * 64 + k4 * 4];
            split_store(sb + FA_KH + (k4 >> 3) * 8192, sb + FA_KL + (k4 >> 3) * 8192,
                        row, k4 & 7, f);
        }
        #pragma unroll
        for (int i = 0; i < 8; i++) {
            int idx = i * 256 + tid, row = idx >> 5, sc = idx & 31;
            float4 f = *(const float4*)&vt[((long)bh * 64 + row) * SEQ + s0 + sc * 4];
            split_store(sb + FA_VH + (sc >> 3) * 4096, sb + FA_VL + (sc >> 3) * 4096,
                        row, sc & 7, f);
        }
        __syncthreads();

        float sf[4][4][4];
        #pragma unroll
        for (int am = 0; am < 4; am++)
            #pragma unroll
            for (int na = 0; na < 4; na++)
                #pragma unroll
                for (int e = 0; e < 4; e++) sf[am][na][e] = 0.0f;

        #pragma unroll
        for (int kb = 0; kb < 2; kb++)
            #pragma unroll
            for (int khi = 0; khi < 2; khi++) {
                uint32_t ah[4][4], al[4][4];
                #pragma unroll
                for (int am = 0; am < 4; am++) {
                    ldm4(ah[am], sb + FA_QH + kb * 8192 + offA[am][khi]);
                    ldm4(al[am], sb + FA_QL + kb * 8192 + offA[am][khi]);
                }
                uint32_t bhf[2][4], blf[2][4];
                #pragma unroll
                for (int p = 0; p < 2; p++) {
                    ldm4(bhf[p], sb + FA_KH + kb * 8192 + offK[p][khi]);
                    ldm4(blf[p], sb + FA_KL + kb * 8192 + offK[p][khi]);
                }
                #pragma unroll
                for (int am = 0; am < 4; am++)
                    #pragma unroll
                    for (int na = 0; na < 4; na++) {
                        const uint32_t* bhp = &bhf[na >> 1][(na & 1) * 2];
                        const uint32_t* blp = &blf[na >> 1][(na & 1) * 2];
                        mma16816(sf[am][na], ah[am], bhp);
                        mma16816(sf[am][na], ah[am], blp);
                        mma16816(sf[am][na], al[am], bhp);
                    }
            }

        #pragma unroll
        for (int am = 0; am < 4; am++) {
            float v0 = -1e30f, v1 = -1e30f;
            #pragma unroll
            for (int na = 0; na < 4; na++) {
                v0 = fmaxf(v0, fmaxf(sf[am][na][0], sf[am][na][1]));
                v1 = fmaxf(v1, fmaxf(sf[am][na][2], sf[am][na][3]));
            }
            v0 = fmaxf(v0, __shfl_xor_sync(0xFFFFFFFFu, v0, 1));
            v0 = fmaxf(v0, __shfl_xor_sync(0xFFFFFFFFu, v0, 2));
            v1 = fmaxf(v1, __shfl_xor_sync(0xFFFFFFFFu, v1, 1));
            v1 = fmaxf(v1, __shfl_xor_sync(0xFFFFFFFFu, v1, 2));
            if ((lane & 3) == 0) {
                smx[(rb + am * 16) * 4 + wn] = v0;
                smx[(rb + am * 16 + 8) * 4 + wn] = v1;
            }
        }
        __syncthreads();

        float csc[4][2];
        #pragma unroll
        for (int am = 0; am < 4; am++) {
            int r0 = rb + am * 16, r1 = r0 + 8;
            float tm0 = fmaxf(fmaxf(smx[r0 * 4 + 0], smx[r0 * 4 + 1]),
                              fmaxf(smx[r0 * 4 + 2], smx[r0 * 4 + 3]));
            float tm1 = fmaxf(fmaxf(smx[r1 * 4 + 0], smx[r1 * 4 + 1]),
                              fmaxf(smx[r1 * 4 + 2], smx[r1 * 4 + 3]));
            float mn0 = fmaxf(m_r[am][0], tm0);
            float mn1 = fmaxf(m_r[am][1], tm1);
            csc[am][0] = __expf(m_r[am][0] - mn0);
            csc[am][1] = __expf(m_r[am][1] - mn1);
            m_r[am][0] = mn0; m_r[am][1] = mn1;

            float rs0 = 0.0f, rs1 = 0.0f;
            #pragma unroll
            for (int na = 0; na < 4; na++) {
                float p0 = __expf(sf[am][na][0] - mn0);
                float p1 = __expf(sf[am][na][1] - mn0);
                float p2 = __expf(sf[am][na][2] - mn1);
                float p3 = __expf(sf[am][na][3] - mn1);
                rs0 += p0 + p1; rs1 += p2 + p3;
                int c0col = wn * 32 + na * 8 + (lane & 3) * 2;
                int kb = c0col >> 5, cc = c0col & 31;
                uint32_t o0 = (uint32_t)(kb * 8192 + r0 * 64 +
                              (((cc >> 3) ^ ((r0 >> 1) & 3)) << 4) +
                              ((cc >> 2) & 1) * 8 + (cc & 3) * 2);
                uint32_t o1 = (uint32_t)(kb * 8192 + r1 * 64 +
                              (((cc >> 3) ^ ((r1 >> 1) & 3)) << 4) +
                              ((cc >> 2) & 1) * 8 + (cc & 3) * 2);
                *(uint32_t*)(smem + FA_PH + o0) = pk_hi(p0, p1);
                *(uint32_t*)(smem + FA_PL + o0) = pk_lo(p0, p1);
                *(uint32_t*)(smem + FA_PH + o1) = pk_hi(p2, p3);
                *(uint32_t*)(smem + FA_PL + o1) = pk_lo(p2, p3);
            }
            rs0 += __shfl_xor_sync(0xFFFFFFFFu, rs0, 1);
            rs0 += __shfl_xor_sync(0xFFFFFFFFu, rs0, 2);
            rs1 += __shfl_xor_sync(0xFFFFFFFFu, rs1, 1);
            rs1 += __shfl_xor_sync(0xFFFFFFFFu, rs1, 2);
            if ((lane & 3) == 0) {
                ssm[r0 * 4 + wn] = rs0;
                ssm[r1 * 4 + wn] = rs1;
            }
        }
        __syncthreads();

        #pragma unroll
        for (int am = 0; am < 4; am++) {
            int r0 = rb + am * 16, r1 = r0 + 8;
            float s0s = ssm[r0 * 4 + 0] + ssm[r0 * 4 + 1] + ssm[r0 * 4 + 2] + ssm[r0 * 4 + 3];
            float s1s = ssm[r1 * 4 + 0] + ssm[r1 * 4 + 1] + ssm[r1 * 4 + 2] + ssm[r1 * 4 + 3];
            l_r[am][0] = l_r[am][0] * csc[am][0] + s0s;
            l_r[am][1] = l_r[am][1] * csc[am][1] + s1s;
            #pragma unroll
            for (int na = 0; na < 2; na++) {
                o[am][na][0] *= csc[am][0]; o[am][na][1] *= csc[am][0];
                o[am][na][2] *= csc[am][1]; o[am][na][3] *= csc[am][1];
            }
        }

        #pragma unroll
        for (int kb = 0; kb < 4; kb++)
            #pragma unroll
            for (int khi = 0; khi < 2; khi++) {
                uint32_t ah[4][4], al[4][4];
                #pragma unroll
                for (int am = 0; am < 4; am++) {
                    ldm4(ah[am], sb + FA_PH + kb * 8192 + offA[am][khi]);
                    ldm4(al[am], sb + FA_PL + kb * 8192 + offA[am][khi]);
                }
                uint32_t bhf[4], blf[4];
                ldm4(bhf, sb + FA_VH + kb * 4096 + offV[khi]);
                ldm4(blf, sb + FA_VL + kb * 4096 + offV[khi]);
                #pragma unroll
                for (int am = 0; am < 4; am++)
                    #pragma unroll
                    for (int na = 0; na < 2; na++) {
                        const uint32_t* bhp = &bhf[na * 2];
                        const uint32_t* blp = &blf[na * 2];
                        mma16816(o[am][na], ah[am], bhp);
                        mma16816(o[am][na], ah[am], blp);
                        mma16816(o[am][na], al[am], bhp);
                    }
            }
    }

    #pragma unroll
    for (int am = 0; am < 4; am++) {
        float inv0 = 1.0f / l_r[am][0];
        float inv1 = 1.0f / l_r[am][1];
        long tok0 = (long)(b * SEQ + q0 + wm * 64 + am * 16 + (lane >> 2));
        #pragma unroll
        for (int na = 0; na < 2; na++) {
            int col = hh * 64 + wn * 16 + na * 8 + (lane & 3) * 2;
            float2 r0 = { o[am][na][0] * inv0, o[am][na][1] * inv0 };
            float2 r1 = { o[am][na][2] * inv1, o[am][na][3] * inv1 };
            *(float2*)&y[tok0 * DIMN + col] = r0;
            *(float2*)&y[(tok0 + 8) * DIMN + col] = r1;
        }
    }
}

// ---------------- elementwise kernels ----------------
__global__ void embed_kernel(const int* __restrict__ tokens,
                             const float* __restrict__ embed,
                             float* __restrict__ h)
{
    int row = blockIdx.x;
    int tok = tokens[row];
    ((float4*)(h + (long)row * DIMN))[threadIdx.x] =
        ((const float4*)(embed + (long)tok * DIMN))[threadIdx.x];
}

__global__ void rmsnorm_kernel(const float* __restrict__ x,
                               const float* __restrict__ w,
                               float* __restrict__ out)
{
    int row = blockIdx.x;
    float4 v = ((const float4*)(x + (long)row * DIMN))[threadIdx.x];
    float ss = v.x*v.x + v.y*v.y + v.z*v.z + v.w*v.w;
    __shared__ float red[8];
    #pragma unroll
    for (int o = 16; o > 0; o >>= 1) ss += __shfl_xor_sync(0xFFFFFFFFu, ss, o);
    if ((threadIdx.x & 31) == 0) red[threadIdx.x >> 5] = ss;
    __syncthreads();
    if (threadIdx.x < 8) {
        float s = red[threadIdx.x];
        #pragma unroll
        for (int o = 4; o > 0; o >>= 1) s += __shfl_xor_sync(0xFFu, s, o);
        if (threadIdx.x == 0) red[0] = s;
    }
    __syncthreads();
    float scale = rsqrtf(red[0] * (1.0f / DIMN) + EPS);
    float4 wv = ((const float4*)w)[threadIdx.x];
    float4 o4 = { v.x*scale*wv.x, v.y*scale*wv.y, v.z*scale*wv.z, v.w*scale*wv.w };
    ((float4*)(out + (long)row * DIMN))[threadIdx.x] = o4;
}

// vt[(b*H+h)][d][s] = v[b*SEQ+s][h*64+d]
__global__ void transpose_v_kernel(const float* __restrict__ v, float* __restrict__ vt)
{
    __shared__ float t[32][33];
    int bh = blockIdx.z, b = bh >> 4, hh = bh & 15;
    int s0 = blockIdx.x * 32, d0 = blockIdx.y * 32;
    int tx = threadIdx.x, ty = threadIdx.y;    // 32 x 8
    #pragma unroll
    for (int j = 0; j < 32; j += 8)
        t[ty + j][tx] = v[(long)(b * SEQ + s0 + ty + j) * DIMN + hh * HEAD_DIM + d0 + tx];
    __syncthreads();
    #pragma unroll
    for (int j = 0; j < 32; j += 8)
        vt[((long)bh * HEAD_DIM + d0 + ty + j) * SEQ + s0 + tx] = t[tx][ty + j];
}

// ---------------- launcher ----------------
extern "C" void kernel_launch(void* const* d_in, const int* in_sizes, int n_in,
                              void* d_out, int out_size)
{
    const int*   tokens  = (const int*)  d_in[0];
    const float* embed   = (const float*)d_in[1];
    const float* Wq      = (const float*)d_in[2];
    const float* Wk      = (const float*)d_in[3];
    const float* Wv      = (const float*)d_in[4];
    const float* Wo      = (const float*)d_in[5];
    const float* Wg      = (const float*)d_in[6];
    const float* Wu      = (const float*)d_in[7];
    const float* Wd      = (const float*)d_in[8];
    const float* ln1     = (const float*)d_in[9];
    const float* ln2     = (const float*)d_in[10];
    const float* norm_w  = (const float*)d_in[11];
    const float* lm_head = (const float*)d_in[12];
    float* out = (float*)d_out;

    float *h, *x, *q, *k, *v, *vt, *y, *gate;
    cudaGetSymbolAddress((void**)&h,    g_h);
    cudaGetSymbolAddress((void**)&x,    g_x);
    cudaGetSymbolAddress((void**)&q,    g_q);
    cudaGetSymbolAddress((void**)&k,    g_k);
    cudaGetSymbolAddress((void**)&v,    g_v);
    cudaGetSymbolAddress((void**)&vt,   g_vt);
    cudaGetSymbolAddress((void**)&y,    g_y);
    cudaGetSymbolAddress((void**)&gate, g_gate);

    const int DYN128 = 2 * (16384 + 128 * 128);   // 65536
    cudaFuncSetAttribute(mma_gemm<128, 0>, cudaFuncAttributeMaxDynamicSharedMemorySize, DYN128);
    cudaFuncSetAttribute(mma_gemm<128, 1>, cudaFuncAttributeMaxDynamicSharedMemorySize, DYN128);
    cudaFuncSetAttribute(mma_gemm<128, 2>, cudaFuncAttributeMaxDynamicSharedMemorySize, DYN128);
    cudaFuncSetAttribute(mma_gemm_multi,   cudaFuncAttributeMaxDynamicSharedMemorySize, DYN128);
    cudaFuncSetAttribute(flash_attn, cudaFuncAttributeMaxDynamicSharedMemorySize, FA_BYTES);

    embed_kernel<<<MTOK, 256>>>(tokens, embed, h);

    dim3 gQKV (MTOK / 128, DIMN / 128, 3);
    dim3 gFfn (MTOK / 128, HIDDEN / 128, 1);
    dim3 gProj(MTOK / 128, DIMN / 128, 1);
    dim3 gHead(MTOK / 128, VOCAB / 128, 1);
    dim3 gFa  (SEQ / 128, 1, BATCH * HEADS);
    dim3 gTr  (SEQ / 32, HEAD_DIM / 32, BATCH * HEADS);

    for (int l = 0; l < LAYERS; l++) {
        const float* wq = Wq + (long)l * DIMN * DIMN;
        const float* wk = Wk + (long)l * DIMN * DIMN;
        const float* wv = Wv + (long)l * DIMN * DIMN;
        const float* wo = Wo + (long)l * DIMN * DIMN;
        const float* wg = Wg + (long)l * HIDDEN * DIMN;
        const float* wu = Wu + (long)l * HIDDEN * DIMN;
        const float* wd = Wd + (long)l * DIMN * HIDDEN;

        rmsnorm_kernel<<<MTOK, 256>>>(h, ln1 + (long)l * DIMN, x);

        {
            P3 p = { wq, wk, wv, q, k, v };
            mma_gemm_multi<<<gQKV, 256, DYN128>>>(x, DIMN, p, DIMN, DIMN, DIMN, 1.0f);
        }

        transpose_v_kernel<<<gTr, dim3(32, 8)>>>(v, vt);
        flash_attn<<<gFa, 256, FA_BYTES>>>(q, k, vt, y);

        // h += y @ Wo^T
        mma_gemm<128, 1><<<gProj, 256, DYN128>>>(y, DIMN, wo, DIMN,
                                                 h, DIMN, DIMN, 1.0f);

        rmsnorm_kernel<<<MTOK, 256>>>(h, ln2 + (long)l * DIMN, x);

        // gate = x @ Wg^T
        mma_gemm<128, 0><<<gFfn, 256, DYN128>>>(x, DIMN, wg, DIMN,
                                                gate, HIDDEN, DIMN, 1.0f);
        // gate = silu(gate) * (x @ Wu^T)   (epilogue fusion, sequential launch)
        mma_gemm<128, 2><<<gFfn, 256, DYN128>>>(x, DIMN, wu, DIMN,
                                                gate, HIDDEN, DIMN, 1.0f);

        // h += gate @ Wd^T
        mma_gemm<128, 1><<<gProj, 256, DYN128>>>(gate, HIDDEN, wd, HIDDEN,
                                                 h, DIMN, HIDDEN, 1.0f);
    }

    rmsnorm_kernel<<<MTOK, 256>>>(h, norm_w, x);
    mma_gemm<128, 0><<<gHead, 256, DYN128>>>(x, DIMN, lm_head, DIMN,
                                             out, VOCAB, DIMN, 1.0f);
}

// round 12
// speedup vs baseline: 1.2139x; 1.0573x over previous
#include <cuda_runtime.h>
#include <math.h>
#include <stdint.h>

// ---------------- problem constants ----------------
#define DIMN     1024
#define HEADS    16
#define HEAD_DIM 64
#define LAYERS   4
#define HIDDEN   4096
#define VOCAB    32000
#define BATCH    2
#define SEQ      1024
#define MTOK     (BATCH*SEQ)
#define EPS      1e-6f

// ---------------- scratch ----------------
__device__ float g_h   [MTOK*DIMN];
__device__ float g_x   [MTOK*DIMN];
__device__ float g_q   [MTOK*DIMN];
__device__ float g_k   [MTOK*DIMN];
__device__ float g_v   [MTOK*DIMN];
__device__ float g_vt  [MTOK*DIMN];
__device__ float g_y   [MTOK*DIMN];
__device__ float g_gate[MTOK*HIDDEN];
__device__ float g_up  [MTOK*HIDDEN];

// ---------------- PTX helpers ----------------
__device__ __forceinline__ uint32_t smem_u32(const void* p) {
    uint32_t a;
    asm("{ .reg .u64 t; cvta.to.shared.u64 t, %1; cvt.u32.u64 %0, t; }"
        : "=r"(a) : "l"(p));
    return a;
}

__device__ __forceinline__ void ldm4(uint32_t* r, uint32_t addr) {
    asm volatile("ldmatrix.sync.aligned.m8n8.x4.shared.b16 {%0,%1,%2,%3}, [%4];"
                 : "=r"(r[0]), "=r"(r[1]), "=r"(r[2]), "=r"(r[3]) : "r"(addr));
}

__device__ __forceinline__ void mma16816(float* c, const uint32_t* a, const uint32_t* b) {
    asm volatile("mma.sync.aligned.m16n8k16.row.col.f32.bf16.bf16.f32 "
                 "{%0,%1,%2,%3}, {%4,%5,%6,%7}, {%8,%9}, {%0,%1,%2,%3};"
                 : "+f"(c[0]), "+f"(c[1]), "+f"(c[2]), "+f"(c[3])
                 : "r"(a[0]), "r"(a[1]), "r"(a[2]), "r"(a[3]),
                   "r"(b[0]), "r"(b[1]));
}

__device__ __forceinline__ uint32_t pk_hi(float a, float b) {
    return __byte_perm(__float_as_uint(a), __float_as_uint(b), 0x7632);
}
__device__ __forceinline__ uint32_t pk_lo(float a, float b) {
    float la = a - __uint_as_float(__float_as_uint(a) & 0xFFFF0000u);
    float lb = b - __uint_as_float(__float_as_uint(b) & 0xFFFF0000u);
    return __byte_perm(__float_as_uint(la), __float_as_uint(lb), 0x7632);
}

__device__ __forceinline__ void split_store(uint32_t hi_base, uint32_t lo_base,
                                            int row, int k4, float4 f) {
    uint32_t h01 = pk_hi(f.x, f.y), h23 = pk_hi(f.z, f.w);
    uint32_t l01 = pk_lo(f.x, f.y), l23 = pk_lo(f.z, f.w);
    int chunk = k4 >> 1, half = k4 & 1;
    uint32_t off = (uint32_t)(row * 64 + ((chunk ^ ((row >> 1) & 3)) << 4) + half * 8);
    asm volatile("st.shared.v2.b32 [%0], {%1,%2};" :: "r"(hi_base + off), "r"(h01), "r"(h23));
    asm volatile("st.shared.v2.b32 [%0], {%1,%2};" :: "r"(lo_base + off), "r"(l01), "r"(l23));
}

// ---------------- GEMM body (validated since R4) -----------------
template<int BN, bool ACCUM>
__device__ __forceinline__ void gemm_body(
    const float* __restrict__ A, int lda,
    const float* __restrict__ B, int ldb,
    float*       __restrict__ C, int ldc,
    int K, float alpha, int m0, int n0)
{
    constexpr int WN    = BN / 4;
    constexpr int NA    = WN / 8;
    constexpr int NB4   = BN / 32;
    constexpr int A_LO  = 8192;
    constexpr int B_HI  = 16384;
    constexpr int BLO_D = BN * 64;
    constexpr int STAGE = 16384 + BN * 128;

    extern __shared__ char smem[];
    const uint32_t sb0 = smem_u32(smem);

    const int tid = threadIdx.x, lane = tid & 31, wid = tid >> 5;
    const int wm = wid & 1, wn = wid >> 1;

    uint32_t offA[4][2], offB[NA / 2][2];
    #pragma unroll
    for (int am = 0; am < 4; am++)
        #pragma unroll
        for (int kh = 0; kh < 2; kh++) {
            int mrow  = wm * 64 + am * 16 + (lane & 7) + ((lane >> 3) & 1) * 8;
            int chunk = kh * 2 + ((lane >> 4) & 1);
            offA[am][kh] = (uint32_t)(mrow * 64 + ((chunk ^ ((mrow >> 1) & 3)) << 4));
        }
    #pragma unroll
    for (int p = 0; p < NA / 2; p++)
        #pragma unroll
        for (int kh = 0; kh < 2; kh++) {
            int nrow  = wn * WN + p * 16 + (lane & 7) + ((lane >> 4) & 1) * 8;
            int chunk = kh * 2 + ((lane >> 3) & 1);
            offB[p][kh] = (uint32_t)(B_HI + nrow * 64 + ((chunk ^ ((nrow >> 1) & 3)) << 4));
        }

    float acc[4][NA][4];
    #pragma unroll
    for (int i = 0; i < 4; i++)
        #pragma unroll
        for (int j = 0; j < NA; j++)
            #pragma unroll
            for (int e = 0; e < 4; e++) acc[i][j][e] = 0.0f;

    float4 pa[4], pb[NB4];
    auto LOADG = [&](int k0) {
        #pragma unroll
        for (int i = 0; i < 4; i++) {
            int idx = i * 256 + tid, row = idx >> 3, k4 = idx & 7;
            pa[i] = *(const float4*)&A[(long)(m0 + row) * lda + k0 + k4 * 4];
        }
        #pragma unroll
        for (int i = 0; i < NB4; i++) {
            int idx = i * 256 + tid, row = idx >> 3, k4 = idx & 7;
            pb[i] = *(const float4*)&B[(long)(n0 + row) * ldb + k0 + k4 * 4];
        }
    };
    auto STORES = [&](uint32_t base) {
        #pragma unroll
        for (int i = 0; i < 4; i++) {
            int idx = i * 256 + tid, row = idx >> 3, k4 = idx & 7;
            split_store(base, base + A_LO, row, k4, pa[i]);
        }
        #pragma unroll
        for (int i = 0; i < NB4; i++) {
            int idx = i * 256 + tid, row = idx >> 3, k4 = idx & 7;
            split_store(base + B_HI, base + B_HI + BLO_D, row, k4, pb[i]);
        }
    };

    const int nk = K >> 5;
    LOADG(0);
    STORES(sb0);
    __syncthreads();

    for (int t = 0; t < nk; t++) {
        const uint32_t sb = sb0 + (uint32_t)(t & 1) * STAGE;
        if (t + 1 < nk) LOADG((t + 1) * 32);

        #pragma unroll
        for (int kh = 0; kh < 2; kh++) {
            uint32_t ah[4][4], al[4][4];
            #pragma unroll
            for (int am = 0; am < 4; am++) {
                ldm4(ah[am], sb + offA[am][kh]);
                ldm4(al[am], sb + offA[am][kh] + A_LO);
            }
            uint32_t bh[NA / 2][4], bl[NA / 2][4];
            #pragma unroll
            for (int p = 0; p < NA / 2; p++) {
                ldm4(bh[p], sb + offB[p][kh]);
                ldm4(bl[p], sb + offB[p][kh] + BLO_D);
            }
            #pragma unroll
            for (int am = 0; am < 4; am++)
                #pragma unroll
                for (int na = 0; na < NA; na++) {
                    const uint32_t* bhp = &bh[na >> 1][(na & 1) * 2];
                    const uint32_t* blp = &bl[na >> 1][(na & 1) * 2];
                    mma16816(acc[am][na], ah[am], bhp);
                    mma16816(acc[am][na], ah[am], blp);
                    mma16816(acc[am][na], al[am], bhp);
                }
        }

        if (t + 1 < nk) STORES(sb0 + (uint32_t)((t & 1) ^ 1) * STAGE);
        __syncthreads();
    }

    #pragma unroll
    for (int am = 0; am < 4; am++)
        #pragma unroll
        for (int na = 0; na < NA; na++) {
            int row = m0 + wm * 64 + am * 16 + (lane >> 2);
            int col = n0 + wn * WN + na * 8 + (lane & 3) * 2;
            float* base0 = &C[(long)row * ldc + col];
            float* base1 = &C[(long)(row + 8) * ldc + col];
            float2 r0 = { alpha * acc[am][na][0], alpha * acc[am][na][1] };
            float2 r1 = { alpha * acc[am][na][2], alpha * acc[am][na][3] };
            if (ACCUM) {
                float2 o0 = *(float2*)base0, o1 = *(float2*)base1;
                r0.x += o0.x; r0.y += o0.y; r1.x += o1.x; r1.y += o1.y;
            }
            *(float2*)base0 = r0;
            *(float2*)base1 = r1;
        }
}

template<int BN, bool ACCUM>
__global__ void __launch_bounds__(256, 1)
mma_gemm(const float* __restrict__ A, int lda,
         const float* __restrict__ B, int ldb,
         float*       __restrict__ C, int ldc,
         int K, float alpha)
{
    gemm_body<BN, ACCUM>(A, lda, B, ldb, C, ldc, K, alpha,
                         blockIdx.x * 128, blockIdx.y * BN);
}

struct P3 {
    const float *B0, *B1, *B2;
    float *C0, *C1, *C2;
};

__global__ void __launch_bounds__(256, 1)
mma_gemm_multi(const float* __restrict__ A, int lda, P3 p,
               int ldb, int ldc, int K, float alpha)
{
    const int z = blockIdx.z;
    const float* B = (z == 0) ? p.B0 : (z == 1) ? p.B1 : p.B2;
    float*       C = (z == 0) ? p.C0 : (z == 1) ? p.C1 : p.C2;
    gemm_body<128, false>(A, lda, B, ldb, C, ldc, K, alpha,
                          blockIdx.x * 128, blockIdx.y * 128);
}

// ================= flash attention, s-tile 64, 2 CTAs/SM ==================
// grid (SEQ/128, 1, BATCH*HEADS); 256 threads (8 warps, 2m x 4n).
// smem 100KB -> 2 CTAs resident; whole grid co-resident (256 <= 296).
#define FA_QH  0        // 16KB (2 kb-blocks x 8192)
#define FA_QL  16384
#define FA_KH  32768    // 8KB (2 kb-blocks x 4096, 64 rows)
#define FA_KL  40960
#define FA_VH  49152    // 8KB
#define FA_VL  57344
#define FA_PH  65536    // 16KB
#define FA_PL  81920
#define FA_SMX 98304
#define FA_SSM 100352
#define FA_BYTES 102400

__global__ void __launch_bounds__(256, 2)
flash_attn(const float* __restrict__ q, const float* __restrict__ k,
           const float* __restrict__ vt, float* __restrict__ y)
{
    extern __shared__ char smem[];
    const uint32_t sb = smem_u32(smem);
    float* smx = (float*)(smem + FA_SMX);
    float* ssm = (float*)(smem + FA_SSM);

    const int tid = threadIdx.x, lane = tid & 31, wid = tid >> 5;
    const int wm = wid & 1, wn = wid >> 1;
    const int bh = blockIdx.z, b = bh >> 4, hh = bh & 15;
    const int q0 = blockIdx.x * 128;

    uint32_t offA[4][2];
    #pragma unroll
    for (int am = 0; am < 4; am++)
        #pragma unroll
        for (int khi = 0; khi < 2; khi++) {
            int arow  = wm * 64 + am * 16 + (lane & 7) + ((lane >> 3) & 1) * 8;
            int chunk = khi * 2 + ((lane >> 4) & 1);
            offA[am][khi] = (uint32_t)(arow * 64 + ((chunk ^ ((arow >> 1) & 3)) << 4));
        }
    // K/V: warp n-tile = 16 rows, single ldmatrix.x4 per khi
    uint32_t offK[2], offV[2];
    #pragma unroll
    for (int khi = 0; khi < 2; khi++) {
        int brow  = wn * 16 + (lane & 7) + ((lane >> 4) & 1) * 8;
        int chunk = khi * 2 + ((lane >> 3) & 1);
        uint32_t o = (uint32_t)(brow * 64 + ((chunk ^ ((brow >> 1) & 3)) << 4));
        offK[khi] = o;
        offV[khi] = o;
    }

    // load Q tile (scaled by 1/8, exact), split hi/lo
    #pragma unroll
    for (int i = 0; i < 8; i++) {
        int idx = i * 256 + tid, row = idx >> 4, k4 = idx & 15;
        float4 f = *(const float4*)&q[(long)(b * SEQ + q0 + row) * DIMN + hh * 64 + k4 * 4];
        f.x *= 0.125f; f.y *= 0.125f; f.z *= 0.125f; f.w *= 0.125f;
        split_store(sb + FA_QH + (k4 >> 3) * 8192, sb + FA_QL + (k4 >> 3) * 8192,
                    row, k4 & 7, f);
    }

    float o[4][2][4];
    float m_r[4][2], l_r[4][2];
    #pragma unroll
    for (int am = 0; am < 4; am++) {
        m_r[am][0] = m_r[am][1] = -1e30f;
        l_r[am][0] = l_r[am][1] = 0.0f;
        #pragma unroll
        for (int na = 0; na < 2; na++)
            #pragma unroll
            for (int e = 0; e < 4; e++) o[am][na][e] = 0.0f;
    }

    const int rb = wm * 64 + (lane >> 2);

    for (int s0 = 0; s0 < SEQ; s0 += 64) {
        __syncthreads();   // prev iter's MMAs done before overwriting K/V/P

        #pragma unroll
        for (int i = 0; i < 4; i++) {     // K tile: 64 rows x 64 d
            int idx = i * 256 + tid, row = idx >> 4, k4 = idx & 15;
            float4 f = *(const float4*)&k[(long)(b * SEQ + s0 + row) * DIMN + hh * 64 + k4 * 4];
            split_store(sb + FA_KH + (k4 >> 3) * 4096, sb + FA_KL + (k4 >> 3) * 4096,
                        row, k4 & 7, f);
        }
        #pragma unroll
        for (int i = 0; i < 4; i++) {     // V tile: 64 d-rows x 64 s
            int idx = i * 256 + tid, row = idx >> 4, s4 = idx & 15;
            float4 f = *(const float4*)&vt[((long)bh * 64 + row) * SEQ + s0 + s4 * 4];
            split_store(sb + FA_VH + (s4 >> 3) * 4096, sb + FA_VL + (s4 >> 3) * 4096,
                        row, s4 & 7, f);
        }
        __syncthreads();

        // S = Qs K^T  (128 x 64, K=64)
        float sf[4][2][4];
        #pragma unroll
        for (int am = 0; am < 4; am++)
            #pragma unroll
            for (int na = 0; na < 2; na++)
                #pragma unroll
                for (int e = 0; e < 4; e++) sf[am][na][e] = 0.0f;

        #pragma unroll
        for (int kb = 0; kb < 2; kb++)
            #pragma unroll
            for (int khi = 0; khi < 2; khi++) {
                uint32_t ah[4][4], al[4][4];
                #pragma unroll
                for (int am = 0; am < 4; am++) {
                    ldm4(ah[am], sb + FA_QH + kb * 8192 + offA[am][khi]);
                    ldm4(al[am], sb + FA_QL + kb * 8192 + offA[am][khi]);
                }
                uint32_t bhf[4], blf[4];
                ldm4(bhf, sb + FA_KH + kb * 4096 + offK[khi]);
                ldm4(blf, sb + FA_KL + kb * 4096 + offK[khi]);
                #pragma unroll
                for (int am = 0; am < 4; am++)
                    #pragma unroll
                    for (int na = 0; na < 2; na++) {
                        const uint32_t* bhp = &bhf[na * 2];
                        const uint32_t* blp = &blf[na * 2];
                        mma16816(sf[am][na], ah[am], bhp);
                        mma16816(sf[am][na], ah[am], blp);
                        mma16816(sf[am][na], al[am], bhp);
                    }
            }

        // row max partials
        #pragma unroll
        for (int am = 0; am < 4; am++) {
            float v0 = -1e30f, v1 = -1e30f;
            #pragma unroll
            for (int na = 0; na < 2; na++) {
                v0 = fmaxf(v0, fmaxf(sf[am][na][0], sf[am][na][1]));
                v1 = fmaxf(v1, fmaxf(sf[am][na][2], sf[am][na][3]));
            }
            v0 = fmaxf(v0, __shfl_xor_sync(0xFFFFFFFFu, v0, 1));
            v0 = fmaxf(v0, __shfl_xor_sync(0xFFFFFFFFu, v0, 2));
            v1 = fmaxf(v1, __shfl_xor_sync(0xFFFFFFFFu, v1, 1));
            v1 = fmaxf(v1, __shfl_xor_sync(0xFFFFFFFFu, v1, 2));
            if ((lane & 3) == 0) {
                smx[(rb + am * 16) * 4 + wn] = v0;
                smx[(rb + am * 16 + 8) * 4 + wn] = v1;
            }
        }
        __syncthreads();

        float csc[4][2];
        #pragma unroll
        for (int am = 0; am < 4; am++) {
            int r0 = rb + am * 16, r1 = r0 + 8;
            float tm0 = fmaxf(fmaxf(smx[r0 * 4 + 0], smx[r0 * 4 + 1]),
                              fmaxf(smx[r0 * 4 + 2], smx[r0 * 4 + 3]));
            float tm1 = fmaxf(fmaxf(smx[r1 * 4 + 0], smx[r1 * 4 + 1]),
                              fmaxf(smx[r1 * 4 + 2], smx[r1 * 4 + 3]));
            float mn0 = fmaxf(m_r[am][0], tm0);
            float mn1 = fmaxf(m_r[am][1], tm1);
            csc[am][0] = __expf(m_r[am][0] - mn0);
            csc[am][1] = __expf(m_r[am][1] - mn1);
            m_r[am][0] = mn0; m_r[am][1] = mn1;

            float rs0 = 0.0f, rs1 = 0.0f;
            #pragma unroll
            for (int na = 0; na < 2; na++) {
                float p0 = __expf(sf[am][na][0] - mn0);
                float p1 = __expf(sf[am][na][1] - mn0);
                float p2 = __expf(sf[am][na][2] - mn1);
                float p3 = __expf(sf[am][na][3] - mn1);
                rs0 += p0 + p1; rs1 += p2 + p3;
                int c0col = wn * 16 + na * 8 + (lane & 3) * 2;    // 0..63
                int kb = c0col >> 5, cc = c0col & 31;
                uint32_t o0 = (uint32_t)(kb * 8192 + r0 * 64 +
                              (((cc >> 3) ^ ((r0 >> 1) & 3)) << 4) +
                              ((cc >> 2) & 1) * 8 + (cc & 3) * 2);
                uint32_t o1 = (uint32_t)(kb * 8192 + r1 * 64 +
                              (((cc >> 3) ^ ((r1 >> 1) & 3)) << 4) +
                              ((cc >> 2) & 1) * 8 + (cc & 3) * 2);
                *(uint32_t*)(smem + FA_PH + o0) = pk_hi(p0, p1);
                *(uint32_t*)(smem + FA_PL + o0) = pk_lo(p0, p1);
                *(uint32_t*)(smem + FA_PH + o1) = pk_hi(p2, p3);
                *(uint32_t*)(smem + FA_PL + o1) = pk_lo(p2, p3);
            }
            rs0 += __shfl_xor_sync(0xFFFFFFFFu, rs0, 1);
            rs0 += __shfl_xor_sync(0xFFFFFFFFu, rs0, 2);
            rs1 += __shfl_xor_sync(0xFFFFFFFFu, rs1, 1);
            rs1 += __shfl_xor_sync(0xFFFFFFFFu, rs1, 2);
            if ((lane & 3) == 0) {
                ssm[r0 * 4 + wn] = rs0;
                ssm[r1 * 4 + wn] = rs1;
            }
        }
        __syncthreads();

        #pragma unroll
        for (int am = 0; am < 4; am++) {
            int r0 = rb + am * 16, r1 = r0 + 8;
            float s0s = ssm[r0 * 4 + 0] + ssm[r0 * 4 + 1] + ssm[r0 * 4 + 2] + ssm[r0 * 4 + 3];
            float s1s = ssm[r1 * 4 + 0] + ssm[r1 * 4 + 1] + ssm[r1 * 4 + 2] + ssm[r1 * 4 + 3];
            l_r[am][0] = l_r[am][0] * csc[am][0] + s0s;
            l_r[am][1] = l_r[am][1] * csc[am][1] + s1s;
            #pragma unroll
            for (int na = 0; na < 2; na++) {
                o[am][na][0] *= csc[am][0]; o[am][na][1] *= csc[am][0];
                o[am][na][2] *= csc[am][1]; o[am][na][3] *= csc[am][1];
            }
        }

        // O += P V   (128 x 64, K=64)
        #pragma unroll
        for (int kb = 0; kb < 2; kb++)
            #pragma unroll
            for (int khi = 0; khi < 2; khi++) {
                uint32_t ah[4][4], al[4][4];
                #pragma unroll
                for (int am = 0; am < 4; am++) {
                    ldm4(ah[am], sb + FA_PH + kb * 8192 + offA[am][khi]);
                    ldm4(al[am], sb + FA_PL + kb * 8192 + offA[am][khi]);
                }
                uint32_t bhf[4], blf[4];
                ldm4(bhf, sb + FA_VH + kb * 4096 + offV[khi]);
                ldm4(blf, sb + FA_VL + kb * 4096 + offV[khi]);
                #pragma unroll
                for (int am = 0; am < 4; am++)
                    #pragma unroll
                    for (int na = 0; na < 2; na++) {
                        const uint32_t* bhp = &bhf[na * 2];
                        const uint32_t* blp = &blf[na * 2];
                        mma16816(o[am][na], ah[am], bhp);
                        mma16816(o[am][na], ah[am], blp);
                        mma16816(o[am][na], al[am], bhp);
                    }
            }
    }

    // epilogue: y = O / l
    #pragma unroll
    for (int am = 0; am < 4; am++) {
        float inv0 = 1.0f / l_r[am][0];
        float inv1 = 1.0f / l_r[am][1];
        long tok0 = (long)(b * SEQ + q0 + wm * 64 + am * 16 + (lane >> 2));
        #pragma unroll
        for (int na = 0; na < 2; na++) {
            int col = hh * 64 + wn * 16 + na * 8 + (lane & 3) * 2;
            float2 r0 = { o[am][na][0] * inv0, o[am][na][1] * inv0 };
            float2 r1 = { o[am][na][2] * inv1, o[am][na][3] * inv1 };
            *(float2*)&y[tok0 * DIMN + col] = r0;
            *(float2*)&y[(tok0 + 8) * DIMN + col] = r1;
        }
    }
}

// ---------------- elementwise kernels ----------------
__global__ void embed_kernel(const int* __restrict__ tokens,
                             const float* __restrict__ embed,
                             float* __restrict__ h)
{
    int row = blockIdx.x;
    int tok = tokens[row];
    ((float4*)(h + (long)row * DIMN))[threadIdx.x] =
        ((const float4*)(embed + (long)tok * DIMN))[threadIdx.x];
}

__global__ void rmsnorm_kernel(const float* __restrict__ x,
                               const float* __restrict__ w,
                               float* __restrict__ out)
{
    int row = blockIdx.x;
    float4 v = ((const float4*)(x + (long)row * DIMN))[threadIdx.x];
    float ss = v.x*v.x + v.y*v.y + v.z*v.z + v.w*v.w;
    __shared__ float red[8];
    #pragma unroll
    for (int o = 16; o > 0; o >>= 1) ss += __shfl_xor_sync(0xFFFFFFFFu, ss, o);
    if ((threadIdx.x & 31) == 0) red[threadIdx.x >> 5] = ss;
    __syncthreads();
    if (threadIdx.x < 8) {
        float s = red[threadIdx.x];
        #pragma unroll
        for (int o = 4; o > 0; o >>= 1) s += __shfl_xor_sync(0xFFu, s, o);
        if (threadIdx.x == 0) red[0] = s;
    }
    __syncthreads();
    float scale = rsqrtf(red[0] * (1.0f / DIMN) + EPS);
    float4 wv = ((const float4*)w)[threadIdx.x];
    float4 o4 = { v.x*scale*wv.x, v.y*scale*wv.y, v.z*scale*wv.z, v.w*scale*wv.w };
    ((float4*)(out + (long)row * DIMN))[threadIdx.x] = o4;
}

__global__ void silu_mul_kernel(float4* __restrict__ g, const float4* __restrict__ u)
{
    long i = (long)blockIdx.x * blockDim.x + threadIdx.x;
    float4 gv = g[i], uv = u[i];
    gv.x = gv.x / (1.0f + __expf(-gv.x)) * uv.x;
    gv.y = gv.y / (1.0f + __expf(-gv.y)) * uv.y;
    gv.z = gv.z / (1.0f + __expf(-gv.z)) * uv.z;
    gv.w = gv.w / (1.0f + __expf(-gv.w)) * uv.w;
    g[i] = gv;
}

// vt[(b*H+h)][d][s] = v[b*SEQ+s][h*64+d]
__global__ void transpose_v_kernel(const float* __restrict__ v, float* __restrict__ vt)
{
    __shared__ float t[32][33];
    int bh = blockIdx.z, b = bh >> 4, hh = bh & 15;
    int s0 = blockIdx.x * 32, d0 = blockIdx.y * 32;
    int tx = threadIdx.x, ty = threadIdx.y;    // 32 x 8
    #pragma unroll
    for (int j = 0; j < 32; j += 8)
        t[ty + j][tx] = v[(long)(b * SEQ + s0 + ty + j) * DIMN + hh * HEAD_DIM + d0 + tx];
    __syncthreads();
    #pragma unroll
    for (int j = 0; j < 32; j += 8)
        vt[((long)bh * HEAD_DIM + d0 + ty + j) * SEQ + s0 + tx] = t[tx][ty + j];
}

// ---------------- launcher ----------------
extern "C" void kernel_launch(void* const* d_in, const int* in_sizes, int n_in,
                              void* d_out, int out_size)
{
    const int*   tokens  = (const int*)  d_in[0];
    const float* embed   = (const float*)d_in[1];
    const float* Wq      = (const float*)d_in[2];
    const float* Wk      = (const float*)d_in[3];
    const float* Wv      = (const float*)d_in[4];
    const float* Wo      = (const float*)d_in[5];
    const float* Wg      = (const float*)d_in[6];
    const float* Wu      = (const float*)d_in[7];
    const float* Wd      = (const float*)d_in[8];
    const float* ln1     = (const float*)d_in[9];
    const float* ln2     = (const float*)d_in[10];
    const float* norm_w  = (const float*)d_in[11];
    const float* lm_head = (const float*)d_in[12];
    float* out = (float*)d_out;

    float *h, *x, *q, *k, *v, *vt, *y, *gate, *up;
    cudaGetSymbolAddress((void**)&h,    g_h);
    cudaGetSymbolAddress((void**)&x,    g_x);
    cudaGetSymbolAddress((void**)&q,    g_q);
    cudaGetSymbolAddress((void**)&k,    g_k);
    cudaGetSymbolAddress((void**)&v,    g_v);
    cudaGetSymbolAddress((void**)&vt,   g_vt);
    cudaGetSymbolAddress((void**)&y,    g_y);
    cudaGetSymbolAddress((void**)&gate, g_gate);
    cudaGetSymbolAddress((void**)&up,   g_up);

    const int DYN128 = 2 * (16384 + 128 * 128);   // 65536
    cudaFuncSetAttribute(mma_gemm<128, false>, cudaFuncAttributeMaxDynamicSharedMemorySize, DYN128);
    cudaFuncSetAttribute(mma_gemm<128, true>,  cudaFuncAttributeMaxDynamicSharedMemorySize, DYN128);
    cudaFuncSetAttribute(mma_gemm_multi,       cudaFuncAttributeMaxDynamicSharedMemorySize, DYN128);
    cudaFuncSetAttribute(flash_attn, cudaFuncAttributeMaxDynamicSharedMemorySize, FA_BYTES);

    embed_kernel<<<MTOK, 256>>>(tokens, embed, h);

    dim3 gQKV (MTOK / 128, DIMN / 128, 3);
    dim3 gGU  (MTOK / 128, HIDDEN / 128, 2);
    dim3 gProj(MTOK / 128, DIMN / 128, 1);
    dim3 gHead(MTOK / 128, VOCAB / 128, 1);
    dim3 gFa  (SEQ / 128, 1, BATCH * HEADS);
    dim3 gTr  (SEQ / 32, HEAD_DIM / 32, BATCH * HEADS);

    for (int l = 0; l < LAYERS; l++) {
        const float* wq = Wq + (long)l * DIMN * DIMN;
        const float* wk = Wk + (long)l * DIMN * DIMN;
        const float* wv = Wv + (long)l * DIMN * DIMN;
        const float* wo = Wo + (long)l * DIMN * DIMN;
        const float* wg = Wg + (long)l * HIDDEN * DIMN;
        const float* wu = Wu + (long)l * HIDDEN * DIMN;
        const float* wd = Wd + (long)l * DIMN * HIDDEN;

        rmsnorm_kernel<<<MTOK, 256>>>(h, ln1 + (long)l * DIMN, x);

        {
            P3 p = { wq, wk, wv, q, k, v };
            mma_gemm_multi<<<gQKV, 256, DYN128>>>(x, DIMN, p, DIMN, DIMN, DIMN, 1.0f);
        }

        transpose_v_kernel<<<gTr, dim3(32, 8)>>>(v, vt);
        flash_attn<<<gFa, 256, FA_BYTES>>>(q, k, vt, y);

        // h += y @ Wo^T
        mma_gemm<128, true><<<gProj, 256, DYN128>>>(y, DIMN, wo, DIMN,
                                                    h, DIMN, DIMN, 1.0f);

        rmsnorm_kernel<<<MTOK, 256>>>(h, ln2 + (long)l * DIMN, x);

        // fused gate,up = x @ {Wg,Wu}^T  (one launch, 1024 CTAs)
        {
            P3 p = { wg, wu, wu, gate, up, up };
            mma_gemm_multi<<<gGU, 256, DYN128>>>(x, DIMN, p, DIMN, HIDDEN, DIMN, 1.0f);
        }

        silu_mul_kernel<<<(MTOK * (long)HIDDEN / 4) / 256, 256>>>((float4*)gate, (const float4*)up);

        // h += gate @ Wd^T
        mma_gemm<128, true><<<gProj, 256, DYN128>>>(gate, HIDDEN, wd, HIDDEN,
                                                    h, DIMN, HIDDEN, 1.0f);
    }

    rmsnorm_kernel<<<MTOK, 256>>>(h, norm_w, x);
    mma_gemm<128, false><<<gHead, 256, DYN128>>>(x, DIMN, lm_head, DIMN,
                                                 out, VOCAB, DIMN, 1.0f);
}

// round 13
// speedup vs baseline: 1.2999x; 1.0708x over previous
#include <cuda_runtime.h>
#include <cuda_fp16.h>
#include <math.h>
#include <stdint.h>

// ---------------- problem constants ----------------
#define DIMN     1024
#define HEADS    16
#define HEAD_DIM 64
#define LAYERS   4
#define HIDDEN   4096
#define VOCAB    32000
#define BATCH    2
#define SEQ      1024
#define MTOK     (BATCH*SEQ)
#define EPS      1e-6f

// ---------------- scratch ----------------
__device__ float g_h   [MTOK*DIMN];
__device__ float g_x   [MTOK*DIMN];
__device__ float g_q   [MTOK*DIMN];
__device__ float g_k   [MTOK*DIMN];
__device__ float g_v   [MTOK*DIMN];
__device__ float g_vt  [MTOK*DIMN];
__device__ float g_y   [MTOK*DIMN];
__device__ float g_gate[MTOK*HIDDEN];
__device__ float g_up  [MTOK*HIDDEN];

// ---------------- PTX helpers ----------------
__device__ __forceinline__ uint32_t smem_u32(const void* p) {
    uint32_t a;
    asm("{ .reg .u64 t; cvta.to.shared.u64 t, %1; cvt.u32.u64 %0, t; }"
        : "=r"(a) : "l"(p));
    return a;
}

__device__ __forceinline__ void ldm4(uint32_t* r, uint32_t addr) {
    asm volatile("ldmatrix.sync.aligned.m8n8.x4.shared.b16 {%0,%1,%2,%3}, [%4];"
                 : "=r"(r[0]), "=r"(r[1]), "=r"(r[2]), "=r"(r[3]) : "r"(addr));
}

__device__ __forceinline__ void mma16816(float* c, const uint32_t* a, const uint32_t* b) {
    asm volatile("mma.sync.aligned.m16n8k16.row.col.f32.bf16.bf16.f32 "
                 "{%0,%1,%2,%3}, {%4,%5,%6,%7}, {%8,%9}, {%0,%1,%2,%3};"
                 : "+f"(c[0]), "+f"(c[1]), "+f"(c[2]), "+f"(c[3])
                 : "r"(a[0]), "r"(a[1]), "r"(a[2]), "r"(a[3]),
                   "r"(b[0]), "r"(b[1]));
}

__device__ __forceinline__ void mma16816h(float* c, const uint32_t* a, const uint32_t* b) {
    asm volatile("mma.sync.aligned.m16n8k16.row.col.f32.f16.f16.f32 "
                 "{%0,%1,%2,%3}, {%4,%5,%6,%7}, {%8,%9}, {%0,%1,%2,%3};"
                 : "+f"(c[0]), "+f"(c[1]), "+f"(c[2]), "+f"(c[3])
                 : "r"(a[0]), "r"(a[1]), "r"(a[2]), "r"(a[3]),
                   "r"(b[0]), "r"(b[1]));
}

__device__ __forceinline__ uint32_t pk_hi(float a, float b) {
    return __byte_perm(__float_as_uint(a), __float_as_uint(b), 0x7632);
}
__device__ __forceinline__ uint32_t pk_lo(float a, float b) {
    float la = a - __uint_as_float(__float_as_uint(a) & 0xFFFF0000u);
    float lb = b - __uint_as_float(__float_as_uint(b) & 0xFFFF0000u);
    return __byte_perm(__float_as_uint(la), __float_as_uint(lb), 0x7632);
}

__device__ __forceinline__ void split_store(uint32_t hi_base, uint32_t lo_base,
                                            int row, int k4, float4 f) {
    uint32_t h01 = pk_hi(f.x, f.y), h23 = pk_hi(f.z, f.w);
    uint32_t l01 = pk_lo(f.x, f.y), l23 = pk_lo(f.z, f.w);
    int chunk = k4 >> 1, half = k4 & 1;
    uint32_t off = (uint32_t)(row * 64 + ((chunk ^ ((row >> 1) & 3)) << 4) + half * 8);
    asm volatile("st.shared.v2.b32 [%0], {%1,%2};" :: "r"(hi_base + off), "r"(h01), "r"(h23));
    asm volatile("st.shared.v2.b32 [%0], {%1,%2};" :: "r"(lo_base + off), "r"(l01), "r"(l23));
}

// fp16 single-plane store (for lm_head GEMM)
__device__ __forceinline__ void half_store(uint32_t base, int row, int k4, float4 f) {
    __half2 a = __floats2half2_rn(f.x, f.y);   // x -> lower, y -> upper
    __half2 b = __floats2half2_rn(f.z, f.w);
    uint32_t h01 = *(uint32_t*)&a, h23 = *(uint32_t*)&b;
    int chunk = k4 >> 1, half = k4 & 1;
    uint32_t off = (uint32_t)(row * 64 + ((chunk ^ ((row >> 1) & 3)) << 4) + half * 8);
    asm volatile("st.shared.v2.b32 [%0], {%1,%2};" :: "r"(base + off), "r"(h01), "r"(h23));
}

// ---------------- bf16 3-term GEMM body (validated since R4) -----------------
template<int BN, bool ACCUM>
__device__ __forceinline__ void gemm_body(
    const float* __restrict__ A, int lda,
    const float* __restrict__ B, int ldb,
    float*       __restrict__ C, int ldc,
    int K, float alpha, int m0, int n0)
{
    constexpr int WN    = BN / 4;
    constexpr int NA    = WN / 8;
    constexpr int NB4   = BN / 32;
    constexpr int A_LO  = 8192;
    constexpr int B_HI  = 16384;
    constexpr int BLO_D = BN * 64;
    constexpr int STAGE = 16384 + BN * 128;

    extern __shared__ char smem[];
    const uint32_t sb0 = smem_u32(smem);

    const int tid = threadIdx.x, lane = tid & 31, wid = tid >> 5;
    const int wm = wid & 1, wn = wid >> 1;

    uint32_t offA[4][2], offB[NA / 2][2];
    #pragma unroll
    for (int am = 0; am < 4; am++)
        #pragma unroll
        for (int kh = 0; kh < 2; kh++) {
            int mrow  = wm * 64 + am * 16 + (lane & 7) + ((lane >> 3) & 1) * 8;
            int chunk = kh * 2 + ((lane >> 4) & 1);
            offA[am][kh] = (uint32_t)(mrow * 64 + ((chunk ^ ((mrow >> 1) & 3)) << 4));
        }
    #pragma unroll
    for (int p = 0; p < NA / 2; p++)
        #pragma unroll
        for (int kh = 0; kh < 2; kh++) {
            int nrow  = wn * WN + p * 16 + (lane & 7) + ((lane >> 4) & 1) * 8;
            int chunk = kh * 2 + ((lane >> 3) & 1);
            offB[p][kh] = (uint32_t)(B_HI + nrow * 64 + ((chunk ^ ((nrow >> 1) & 3)) << 4));
        }

    float acc[4][NA][4];
    #pragma unroll
    for (int i = 0; i < 4; i++)
        #pragma unroll
        for (int j = 0; j < NA; j++)
            #pragma unroll
            for (int e = 0; e < 4; e++) acc[i][j][e] = 0.0f;

    float4 pa[4], pb[NB4];
    auto LOADG = [&](int k0) {
        #pragma unroll
        for (int i = 0; i < 4; i++) {
            int idx = i * 256 + tid, row = idx >> 3, k4 = idx & 7;
            pa[i] = *(const float4*)&A[(long)(m0 + row) * lda + k0 + k4 * 4];
        }
        #pragma unroll
        for (int i = 0; i < NB4; i++) {
            int idx = i * 256 + tid, row = idx >> 3, k4 = idx & 7;
            pb[i] = *(const float4*)&B[(long)(n0 + row) * ldb + k0 + k4 * 4];
        }
    };
    auto STORES = [&](uint32_t base) {
        #pragma unroll
        for (int i = 0; i < 4; i++) {
            int idx = i * 256 + tid, row = idx >> 3, k4 = idx & 7;
            split_store(base, base + A_LO, row, k4, pa[i]);
        }
        #pragma unroll
        for (int i = 0; i < NB4; i++) {
            int idx = i * 256 + tid, row = idx >> 3, k4 = idx & 7;
            split_store(base + B_HI, base + B_HI + BLO_D, row, k4, pb[i]);
        }
    };

    const int nk = K >> 5;
    LOADG(0);
    STORES(sb0);
    __syncthreads();

    for (int t = 0; t < nk; t++) {
        const uint32_t sb = sb0 + (uint32_t)(t & 1) * STAGE;
        if (t + 1 < nk) LOADG((t + 1) * 32);

        #pragma unroll
        for (int kh = 0; kh < 2; kh++) {
            uint32_t ah[4][4], al[4][4];
            #pragma unroll
            for (int am = 0; am < 4; am++) {
                ldm4(ah[am], sb + offA[am][kh]);
                ldm4(al[am], sb + offA[am][kh] + A_LO);
            }
            uint32_t bh[NA / 2][4], bl[NA / 2][4];
            #pragma unroll
            for (int p = 0; p < NA / 2; p++) {
                ldm4(bh[p], sb + offB[p][kh]);
                ldm4(bl[p], sb + offB[p][kh] + BLO_D);
            }
            #pragma unroll
            for (int am = 0; am < 4; am++)
                #pragma unroll
                for (int na = 0; na < NA; na++) {
                    const uint32_t* bhp = &bh[na >> 1][(na & 1) * 2];
                    const uint32_t* blp = &bl[na >> 1][(na & 1) * 2];
                    mma16816(acc[am][na], ah[am], bhp);
                    mma16816(acc[am][na], ah[am], blp);
                    mma16816(acc[am][na], al[am], bhp);
                }
        }

        if (t + 1 < nk) STORES(sb0 + (uint32_t)((t & 1) ^ 1) * STAGE);
        __syncthreads();
    }

    #pragma unroll
    for (int am = 0; am < 4; am++)
        #pragma unroll
        for (int na = 0; na < NA; na++) {
            int row = m0 + wm * 64 + am * 16 + (lane >> 2);
            int col = n0 + wn * WN + na * 8 + (lane & 3) * 2;
            float* base0 = &C[(long)row * ldc + col];
            float* base1 = &C[(long)(row + 8) * ldc + col];
            float2 r0 = { alpha * acc[am][na][0], alpha * acc[am][na][1] };
            float2 r1 = { alpha * acc[am][na][2], alpha * acc[am][na][3] };
            if (ACCUM) {
                float2 o0 = *(float2*)base0, o1 = *(float2*)base1;
                r0.x += o0.x; r0.y += o0.y; r1.x += o1.x; r1.y += o1.y;
            }
            *(float2*)base0 = r0;
            *(float2*)base1 = r1;
        }
}

template<int BN, bool ACCUM>
__global__ void __launch_bounds__(256, 1)
mma_gemm(const float* __restrict__ A, int lda,
         const float* __restrict__ B, int ldb,
         float*       __restrict__ C, int ldc,
         int K, float alpha)
{
    gemm_body<BN, ACCUM>(A, lda, B, ldb, C, ldc, K, alpha,
                         blockIdx.x * 128, blockIdx.y * BN);
}

struct P3 {
    const float *B0, *B1, *B2;
    float *C0, *C1, *C2;
};

__global__ void __launch_bounds__(256, 1)
mma_gemm_multi(const float* __restrict__ A, int lda, P3 p,
               int ldb, int ldc, int K, float alpha)
{
    const int z = blockIdx.z;
    const float* B = (z == 0) ? p.B0 : (z == 1) ? p.B1 : p.B2;
    float*       C = (z == 0) ? p.C0 : (z == 1) ? p.C1 : p.C2;
    gemm_body<128, false>(A, lda, B, ldb, C, ldc, K, alpha,
                          blockIdx.x * 128, blockIdx.y * 128);
}

// ---------------- fp16 single-term GEMM (lm_head) -----------------
// C = A * B^T, fp32 in/out, fp16 operands (1 MMA per fragment pair).
__global__ void __launch_bounds__(256, 1)
mma_gemm_h(const float* __restrict__ A, int lda,
           const float* __restrict__ B, int ldb,
           float*       __restrict__ C, int ldc,
           int K)
{
    constexpr int B_OFF = 8192;
    constexpr int STAGE = 16384;

    extern __shared__ char smem[];
    const uint32_t sb0 = smem_u32(smem);

    const int tid = threadIdx.x, lane = tid & 31, wid = tid >> 5;
    const int wm = wid & 1, wn = wid >> 1;
    const int m0 = blockIdx.x * 128;
    const int n0 = blockIdx.y * 128;

    uint32_t offA[4][2], offB[2][2];
    #pragma unroll
    for (int am = 0; am < 4; am++)
        #pragma unroll
        for (int kh = 0; kh < 2; kh++) {
            int mrow  = wm * 64 + am * 16 + (lane & 7) + ((lane >> 3) & 1) * 8;
            int chunk = kh * 2 + ((lane >> 4) & 1);
            offA[am][kh] = (uint32_t)(mrow * 64 + ((chunk ^ ((mrow >> 1) & 3)) << 4));
        }
    #pragma unroll
    for (int p = 0; p < 2; p++)
        #pragma unroll
        for (int kh = 0; kh < 2; kh++) {
            int nrow  = wn * 32 + p * 16 + (lane & 7) + ((lane >> 4) & 1) * 8;
            int chunk = kh * 2 + ((lane >> 3) & 1);
            offB[p][kh] = (uint32_t)(B_OFF + nrow * 64 + ((chunk ^ ((nrow >> 1) & 3)) << 4));
        }

    float acc[4][4][4];
    #pragma unroll
    for (int i = 0; i < 4; i++)
        #pragma unroll
        for (int j = 0; j < 4; j++)
            #pragma unroll
            for (int e = 0; e < 4; e++) acc[i][j][e] = 0.0f;

    float4 pa[4], pb[4];
    auto LOADG = [&](int k0) {
        #pragma unroll
        for (int i = 0; i < 4; i++) {
            int idx = i * 256 + tid, row = idx >> 3, k4 = idx & 7;
            pa[i] = *(const float4*)&A[(long)(m0 + row) * lda + k0 + k4 * 4];
        }
        #pragma unroll
        for (int i = 0; i < 4; i++) {
            int idx = i * 256 + tid, row = idx >> 3, k4 = idx & 7;
            pb[i] = *(const float4*)&B[(long)(n0 + row) * ldb + k0 + k4 * 4];
        }
    };
    auto STORES = [&](uint32_t base) {
        #pragma unroll
        for (int i = 0; i < 4; i++) {
            int idx = i * 256 + tid, row = idx >> 3, k4 = idx & 7;
            half_store(base, row, k4, pa[i]);
        }
        #pragma unroll
        for (int i = 0; i < 4; i++) {
            int idx = i * 256 + tid, row = idx >> 3, k4 = idx & 7;
            half_store(base + B_OFF, row, k4, pb[i]);
        }
    };

    const int nk = K >> 5;
    LOADG(0);
    STORES(sb0);
    __syncthreads();

    for (int t = 0; t < nk; t++) {
        const uint32_t sb = sb0 + (uint32_t)(t & 1) * STAGE;
        if (t + 1 < nk) LOADG((t + 1) * 32);

        #pragma unroll
        for (int kh = 0; kh < 2; kh++) {
            uint32_t ah[4][4];
            #pragma unroll
            for (int am = 0; am < 4; am++)
                ldm4(ah[am], sb + offA[am][kh]);
            uint32_t bh[2][4];
            #pragma unroll
            for (int p = 0; p < 2; p++)
                ldm4(bh[p], sb + offB[p][kh]);
            #pragma unroll
            for (int am = 0; am < 4; am++)
                #pragma unroll
                for (int na = 0; na < 4; na++)
                    mma16816h(acc[am][na], ah[am], &bh[na >> 1][(na & 1) * 2]);
        }

        if (t + 1 < nk) STORES(sb0 + (uint32_t)((t & 1) ^ 1) * STAGE);
        __syncthreads();
    }

    #pragma unroll
    for (int am = 0; am < 4; am++)
        #pragma unroll
        for (int na = 0; na < 4; na++) {
            int row = m0 + wm * 64 + am * 16 + (lane >> 2);
            int col = n0 + wn * 32 + na * 8 + (lane & 3) * 2;
            float2 r0 = { acc[am][na][0], acc[am][na][1] };
            float2 r1 = { acc[am][na][2], acc[am][na][3] };
            *(float2*)&C[(long)row * ldc + col] = r0;
            *(float2*)&C[(long)(row + 8) * ldc + col] = r1;
        }
}

// ================= flash attention, s-tile 64, 2 CTAs/SM (validated R12) ==
#define FA_QH  0
#define FA_QL  16384
#define FA_KH  32768
#define FA_KL  40960
#define FA_VH  49152
#define FA_VL  57344
#define FA_PH  65536
#define FA_PL  81920
#define FA_SMX 98304
#define FA_SSM 100352
#define FA_BYTES 102400

__global__ void __launch_bounds__(256, 2)
flash_attn(const float* __restrict__ q, const float* __restrict__ k,
           const float* __restrict__ vt, float* __restrict__ y)
{
    extern __shared__ char smem[];
    const uint32_t sb = smem_u32(smem);
    float* smx = (float*)(smem + FA_SMX);
    float* ssm = (float*)(smem + FA_SSM);

    const int tid = threadIdx.x, lane = tid & 31, wid = tid >> 5;
    const int wm = wid & 1, wn = wid >> 1;
    const int bh = blockIdx.z, b = bh >> 4, hh = bh & 15;
    const int q0 = blockIdx.x * 128;

    uint32_t offA[4][2];
    #pragma unroll
    for (int am = 0; am < 4; am++)
        #pragma unroll
        for (int khi = 0; khi < 2; khi++) {
            int arow  = wm * 64 + am * 16 + (lane & 7) + ((lane >> 3) & 1) * 8;
            int chunk = khi * 2 + ((lane >> 4) & 1);
            offA[am][khi] = (uint32_t)(arow * 64 + ((chunk ^ ((arow >> 1) & 3)) << 4));
        }
    uint32_t offK[2], offV[2];
    #pragma unroll
    for (int khi = 0; khi < 2; khi++) {
        int brow  = wn * 16 + (lane & 7) + ((lane >> 4) & 1) * 8;
        int chunk = khi * 2 + ((lane >> 3) & 1);
        uint32_t o = (uint32_t)(brow * 64 + ((chunk ^ ((brow >> 1) & 3)) << 4));
        offK[khi] = o;
        offV[khi] = o;
    }

    #pragma unroll
    for (int i = 0; i < 8; i++) {
        int idx = i * 256 + tid, row = idx >> 4, k4 = idx & 15;
        float4 f = *(const float4*)&q[(long)(b * SEQ + q0 + row) * DIMN + hh * 64 + k4 * 4];
        f.x *= 0.125f; f.y *= 0.125f; f.z *= 0.125f; f.w *= 0.125f;
        split_store(sb + FA_QH + (k4 >> 3) * 8192, sb + FA_QL + (k4 >> 3) * 8192,
                    row, k4 & 7, f);
    }

    float o[4][2][4];
    float m_r[4][2], l_r[4][2];
    #pragma unroll
    for (int am = 0; am < 4; am++) {
        m_r[am][0] = m_r[am][1] = -1e30f;
        l_r[am][0] = l_r[am][1] = 0.0f;
        #pragma unroll
        for (int na = 0; na < 2; na++)
            #pragma unroll
            for (int e = 0; e < 4; e++) o[am][na][e] = 0.0f;
    }

    const int rb = wm * 64 + (lane >> 2);

    for (int s0 = 0; s0 < SEQ; s0 += 64) {
        __syncthreads();

        #pragma unroll
        for (int i = 0; i < 4; i++) {
            int idx = i * 256 + tid, row = idx >> 4, k4 = idx & 15;
            float4 f = *(const float4*)&k[(long)(b * SEQ + s0 + row) * DIMN + hh * 64 + k4 * 4];
            split_store(sb + FA_KH + (k4 >> 3) * 4096, sb + FA_KL + (k4 >> 3) * 4096,
                        row, k4 & 7, f);
        }
        #pragma unroll
        for (int i = 0; i < 4; i++) {
            int idx = i * 256 + tid, row = idx >> 4, s4 = idx & 15;
            float4 f = *(const float4*)&vt[((long)bh * 64 + row) * SEQ + s0 + s4 * 4];
            split_store(sb + FA_VH + (s4 >> 3) * 4096, sb + FA_VL + (s4 >> 3) * 4096,
                        row, s4 & 7, f);
        }
        __syncthreads();

        float sf[4][2][4];
        #pragma unroll
        for (int am = 0; am < 4; am++)
            #pragma unroll
            for (int na = 0; na < 2; na++)
                #pragma unroll
                for (int e = 0; e < 4; e++) sf[am][na][e] = 0.0f;

        #pragma unroll
        for (int kb = 0; kb < 2; kb++)
            #pragma unroll
            for (int khi = 0; khi < 2; khi++) {
                uint32_t ah[4][4], al[4][4];
                #pragma unroll
                for (int am = 0; am < 4; am++) {
                    ldm4(ah[am], sb + FA_QH + kb * 8192 + offA[am][khi]);
                    ldm4(al[am], sb + FA_QL + kb * 8192 + offA[am][khi]);
                }
                uint32_t bhf[4], blf[4];
                ldm4(bhf, sb + FA_KH + kb * 4096 + offK[khi]);
                ldm4(blf, sb + FA_KL + kb * 4096 + offK[khi]);
                #pragma unroll
                for (int am = 0; am < 4; am++)
                    #pragma unroll
                    for (int na = 0; na < 2; na++) {
                        const uint32_t* bhp = &bhf[na * 2];
                        const uint32_t* blp = &blf[na * 2];
                        mma16816(sf[am][na], ah[am], bhp);
                        mma16816(sf[am][na], ah[am], blp);
                        mma16816(sf[am][na], al[am], bhp);
                    }
            }

        #pragma unroll
        for (int am = 0; am < 4; am++) {
            float v0 = -1e30f, v1 = -1e30f;
            #pragma unroll
            for (int na = 0; na < 2; na++) {
                v0 = fmaxf(v0, fmaxf(sf[am][na][0], sf[am][na][1]));
                v1 = fmaxf(v1, fmaxf(sf[am][na][2], sf[am][na][3]));
            }
            v0 = fmaxf(v0, __shfl_xor_sync(0xFFFFFFFFu, v0, 1));
            v0 = fmaxf(v0, __shfl_xor_sync(0xFFFFFFFFu, v0, 2));
            v1 = fmaxf(v1, __shfl_xor_sync(0xFFFFFFFFu, v1, 1));
            v1 = fmaxf(v1, __shfl_xor_sync(0xFFFFFFFFu, v1, 2));
            if ((lane & 3) == 0) {
                smx[(rb + am * 16) * 4 + wn] = v0;
                smx[(rb + am * 16 + 8) * 4 + wn] = v1;
            }
        }
        __syncthreads();

        float csc[4][2];
        #pragma unroll
        for (int am = 0; am < 4; am++) {
            int r0 = rb + am * 16, r1 = r0 + 8;
            float tm0 = fmaxf(fmaxf(smx[r0 * 4 + 0], smx[r0 * 4 + 1]),
                              fmaxf(smx[r0 * 4 + 2], smx[r0 * 4 + 3]));
            float tm1 = fmaxf(fmaxf(smx[r1 * 4 + 0], smx[r1 * 4 + 1]),
                              fmaxf(smx[r1 * 4 + 2], smx[r1 * 4 + 3]));
            float mn0 = fmaxf(m_r[am][0], tm0);
            float mn1 = fmaxf(m_r[am][1], tm1);
            csc[am][0] = __expf(m_r[am][0] - mn0);
            csc[am][1] = __expf(m_r[am][1] - mn1);
            m_r[am][0] = mn0; m_r[am][1] = mn1;

            float rs0 = 0.0f, rs1 = 0.0f;
            #pragma unroll
            for (int na = 0; na < 2; na++) {
                float p0 = __expf(sf[am][na][0] - mn0);
                float p1 = __expf(sf[am][na][1] - mn0);
                float p2 = __expf(sf[am][na][2] - mn1);
                float p3 = __expf(sf[am][na][3] - mn1);
                rs0 += p0 + p1; rs1 += p2 + p3;
                int c0col = wn * 16 + na * 8 + (lane & 3) * 2;
                int kb = c0col >> 5, cc = c0col & 31;
                uint32_t o0 = (uint32_t)(kb * 8192 + r0 * 64 +
                              (((cc >> 3) ^ ((r0 >> 1) & 3)) << 4) +
                              ((cc >> 2) & 1) * 8 + (cc & 3) * 2);
                uint32_t o1 = (uint32_t)(kb * 8192 + r1 * 64 +
                              (((cc >> 3) ^ ((r1 >> 1) & 3)) << 4) +
                              ((cc >> 2) & 1) * 8 + (cc & 3) * 2);
                *(uint32_t*)(smem + FA_PH + o0) = pk_hi(p0, p1);
                *(uint32_t*)(smem + FA_PL + o0) = pk_lo(p0, p1);
                *(uint32_t*)(smem + FA_PH + o1) = pk_hi(p2, p3);
                *(uint32_t*)(smem + FA_PL + o1) = pk_lo(p2, p3);
            }
            rs0 += __shfl_xor_sync(0xFFFFFFFFu, rs0, 1);
            rs0 += __shfl_xor_sync(0xFFFFFFFFu, rs0, 2);
            rs1 += __shfl_xor_sync(0xFFFFFFFFu, rs1, 1);
            rs1 += __shfl_xor_sync(0xFFFFFFFFu, rs1, 2);
            if ((lane & 3) == 0) {
                ssm[r0 * 4 + wn] = rs0;
                ssm[r1 * 4 + wn] = rs1;
            }
        }
        __syncthreads();

        #pragma unroll
        for (int am = 0; am < 4; am++) {
            int r0 = rb + am * 16, r1 = r0 + 8;
            float s0s = ssm[r0 * 4 + 0] + ssm[r0 * 4 + 1] + ssm[r0 * 4 + 2] + ssm[r0 * 4 + 3];
            float s1s = ssm[r1 * 4 + 0] + ssm[r1 * 4 + 1] + ssm[r1 * 4 + 2] + ssm[r1 * 4 + 3];
            l_r[am][0] = l_r[am][0] * csc[am][0] + s0s;
            l_r[am][1] = l_r[am][1] * csc[am][1] + s1s;
            #pragma unroll
            for (int na = 0; na < 2; na++) {
                o[am][na][0] *= csc[am][0]; o[am][na][1] *= csc[am][0];
                o[am][na][2] *= csc[am][1]; o[am][na][3] *= csc[am][1];
            }
        }

        #pragma unroll
        for (int kb = 0; kb < 2; kb++)
            #pragma unroll
            for (int khi = 0; khi < 2; khi++) {
                uint32_t ah[4][4], al[4][4];
                #pragma unroll
                for (int am = 0; am < 4; am++) {
                    ldm4(ah[am], sb + FA_PH + kb * 8192 + offA[am][khi]);
                    ldm4(al[am], sb + FA_PL + kb * 8192 + offA[am][khi]);
                }
                uint32_t bhf[4], blf[4];
                ldm4(bhf, sb + FA_VH + kb * 4096 + offV[khi]);
                ldm4(blf, sb + FA_VL + kb * 4096 + offV[khi]);
                #pragma unroll
                for (int am = 0; am < 4; am++)
                    #pragma unroll
                    for (int na = 0; na < 2; na++) {
                        const uint32_t* bhp = &bhf[na * 2];
                        const uint32_t* blp = &blf[na * 2];
                        mma16816(o[am][na], ah[am], bhp);
                        mma16816(o[am][na], ah[am], blp);
                        mma16816(o[am][na], al[am], bhp);
                    }
            }
    }

    #pragma unroll
    for (int am = 0; am < 4; am++) {
        float inv0 = 1.0f / l_r[am][0];
        float inv1 = 1.0f / l_r[am][1];
        long tok0 = (long)(b * SEQ + q0 + wm * 64 + am * 16 + (lane >> 2));
        #pragma unroll
        for (int na = 0; na < 2; na++) {
            int col = hh * 64 + wn * 16 + na * 8 + (lane & 3) * 2;
            float2 r0 = { o[am][na][0] * inv0, o[am][na][1] * inv0 };
            float2 r1 = { o[am][na][2] * inv1, o[am][na][3] * inv1 };
            *(float2*)&y[tok0 * DIMN + col] = r0;
            *(float2*)&y[(tok0 + 8) * DIMN + col] = r1;
        }
    }
}

// ---------------- elementwise kernels ----------------
__global__ void embed_kernel(const int* __restrict__ tokens,
                             const float* __restrict__ embed,
                             float* __restrict__ h)
{
    int row = blockIdx.x;
    int tok = tokens[row];
    ((float4*)(h + (long)row * DIMN))[threadIdx.x] =
        ((const float4*)(embed + (long)tok * DIMN))[threadIdx.x];
}

__global__ void rmsnorm_kernel(const float* __restrict__ x,
                               const float* __restrict__ w,
                               float* __restrict__ out)
{
    int row = blockIdx.x;
    float4 v = ((const float4*)(x + (long)row * DIMN))[threadIdx.x];
    float ss = v.x*v.x + v.y*v.y + v.z*v.z + v.w*v.w;
    __shared__ float red[8];
    #pragma unroll
    for (int o = 16; o > 0; o >>= 1) ss += __shfl_xor_sync(0xFFFFFFFFu, ss, o);
    if ((threadIdx.x & 31) == 0) red[threadIdx.x >> 5] = ss;
    __syncthreads();
    if (threadIdx.x < 8) {
        float s = red[threadIdx.x];
        #pragma unroll
        for (int o = 4; o > 0; o >>= 1) s += __shfl_xor_sync(0xFFu, s, o);
        if (threadIdx.x == 0) red[0] = s;
    }
    __syncthreads();
    float scale = rsqrtf(red[0] * (1.0f / DIMN) + EPS);
    float4 wv = ((const float4*)w)[threadIdx.x];
    float4 o4 = { v.x*scale*wv.x, v.y*scale*wv.y, v.z*scale*wv.z, v.w*scale*wv.w };
    ((float4*)(out + (long)row * DIMN))[threadIdx.x] = o4;
}

__global__ void silu_mul_kernel(float4* __restrict__ g, const float4* __restrict__ u)
{
    long i = (long)blockIdx.x * blockDim.x + threadIdx.x;
    float4 gv = g[i], uv = u[i];
    gv.x = gv.x / (1.0f + __expf(-gv.x)) * uv.x;
    gv.y = gv.y / (1.0f + __expf(-gv.y)) * uv.y;
    gv.z = gv.z / (1.0f + __expf(-gv.z)) * uv.z;
    gv.w = gv.w / (1.0f + __expf(-gv.w)) * uv.w;
    g[i] = gv;
}

// vt[(b*H+h)][d][s] = v[b*SEQ+s][h*64+d]
__global__ void transpose_v_kernel(const float* __restrict__ v, float* __restrict__ vt)
{
    __shared__ float t[32][33];
    int bh = blockIdx.z, b = bh >> 4, hh = bh & 15;
    int s0 = blockIdx.x * 32, d0 = blockIdx.y * 32;
    int tx = threadIdx.x, ty = threadIdx.y;    // 32 x 8
    #pragma unroll
    for (int j = 0; j < 32; j += 8)
        t[ty + j][tx] = v[(long)(b * SEQ + s0 + ty + j) * DIMN + hh * HEAD_DIM + d0 + tx];
    __syncthreads();
    #pragma unroll
    for (int j = 0; j < 32; j += 8)
        vt[((long)bh * HEAD_DIM + d0 + ty + j) * SEQ + s0 + tx] = t[tx][ty + j];
}

// ---------------- launcher ----------------
extern "C" void kernel_launch(void* const* d_in, const int* in_sizes, int n_in,
                              void* d_out, int out_size)
{
    const int*   tokens  = (const int*)  d_in[0];
    const float* embed   = (const float*)d_in[1];
    const float* Wq      = (const float*)d_in[2];
    const float* Wk      = (const float*)d_in[3];
    const float* Wv      = (const float*)d_in[4];
    const float* Wo      = (const float*)d_in[5];
    const float* Wg      = (const float*)d_in[6];
    const float* Wu      = (const float*)d_in[7];
    const float* Wd      = (const float*)d_in[8];
    const float* ln1     = (const float*)d_in[9];
    const float* ln2     = (const float*)d_in[10];
    const float* norm_w  = (const float*)d_in[11];
    const float* lm_head = (const float*)d_in[12];
    float* out = (float*)d_out;

    float *h, *x, *q, *k, *v, *vt, *y, *gate, *up;
    cudaGetSymbolAddress((void**)&h,    g_h);
    cudaGetSymbolAddress((void**)&x,    g_x);
    cudaGetSymbolAddress((void**)&q,    g_q);
    cudaGetSymbolAddress((void**)&k,    g_k);
    cudaGetSymbolAddress((void**)&v,    g_v);
    cudaGetSymbolAddress((void**)&vt,   g_vt);
    cudaGetSymbolAddress((void**)&y,    g_y);
    cudaGetSymbolAddress((void**)&gate, g_gate);
    cudaGetSymbolAddress((void**)&up,   g_up);

    const int DYN128 = 2 * (16384 + 128 * 128);   // 65536
    const int DYNH   = 2 * 16384;                 // 32768
    cudaFuncSetAttribute(mma_gemm<128, false>, cudaFuncAttributeMaxDynamicSharedMemorySize, DYN128);
    cudaFuncSetAttribute(mma_gemm<128, true>,  cudaFuncAttributeMaxDynamicSharedMemorySize, DYN128);
    cudaFuncSetAttribute(mma_gemm_multi,       cudaFuncAttributeMaxDynamicSharedMemorySize, DYN128);
    cudaFuncSetAttribute(mma_gemm_h,           cudaFuncAttributeMaxDynamicSharedMemorySize, DYNH);
    cudaFuncSetAttribute(flash_attn, cudaFuncAttributeMaxDynamicSharedMemorySize, FA_BYTES);

    embed_kernel<<<MTOK, 256>>>(tokens, embed, h);

    dim3 gQKV (MTOK / 128, DIMN / 128, 3);
    dim3 gGU  (MTOK / 128, HIDDEN / 128, 2);
    dim3 gProj(MTOK / 128, DIMN / 128, 1);
    dim3 gHead(MTOK / 128, VOCAB / 128, 1);
    dim3 gFa  (SEQ / 128, 1, BATCH * HEADS);
    dim3 gTr  (SEQ / 32, HEAD_DIM / 32, BATCH * HEADS);

    for (int l = 0; l < LAYERS; l++) {
        const float* wq = Wq + (long)l * DIMN * DIMN;
        const float* wk = Wk + (long)l * DIMN * DIMN;
        const float* wv = Wv + (long)l * DIMN * DIMN;
        const float* wo = Wo + (long)l * DIMN * DIMN;
        const float* wg = Wg + (long)l * HIDDEN * DIMN;
        const float* wu = Wu + (long)l * HIDDEN * DIMN;
        const float* wd = Wd + (long)l * DIMN * HIDDEN;

        rmsnorm_kernel<<<MTOK, 256>>>(h, ln1 + (long)l * DIMN, x);

        {
            P3 p = { wq, wk, wv, q, k, v };
            mma_gemm_multi<<<gQKV, 256, DYN128>>>(x, DIMN, p, DIMN, DIMN, DIMN, 1.0f);
        }

        transpose_v_kernel<<<gTr, dim3(32, 8)>>>(v, vt);
        flash_attn<<<gFa, 256, FA_BYTES>>>(q, k, vt, y);

        // h += y @ Wo^T
        mma_gemm<128, true><<<gProj, 256, DYN128>>>(y, DIMN, wo, DIMN,
                                                    h, DIMN, DIMN, 1.0f);

        rmsnorm_kernel<<<MTOK, 256>>>(h, ln2 + (long)l * DIMN, x);

        // fused gate,up = x @ {Wg,Wu}^T
        {
            P3 p = { wg, wu, wu, gate, up, up };
            mma_gemm_multi<<<gGU, 256, DYN128>>>(x, DIMN, p, DIMN, HIDDEN, DIMN, 1.0f);
        }

        silu_mul_kernel<<<(MTOK * (long)HIDDEN / 4) / 256, 256>>>((float4*)gate, (const float4*)up);

        // h += gate @ Wd^T
        mma_gemm<128, true><<<gProj, 256, DYN128>>>(gate, HIDDEN, wd, HIDDEN,
                                                    h, DIMN, HIDDEN, 1.0f);
    }

    rmsnorm_kernel<<<MTOK, 256>>>(h, norm_w, x);
    // lm_head: fp16 single-term (terminal GEMM — no downstream error compounding)
    mma_gemm_h<<<gHead, 256, DYNH>>>(x, DIMN, lm_head, DIMN, out, VOCAB, DIMN);
}

// round 14
// speedup vs baseline: 1.3605x; 1.0466x over previous
#include <cuda_runtime.h>
#include <cuda_fp16.h>
#include <math.h>
#include <stdint.h>

// ---------------- problem constants ----------------
#define DIMN     1024
#define HEADS    16
#define HEAD_DIM 64
#define LAYERS   4
#define HIDDEN   4096
#define VOCAB    32000
#define BATCH    2
#define SEQ      1024
#define MTOK     (BATCH*SEQ)
#define EPS      1e-6f

// ---------------- scratch ----------------
__device__ float g_h   [MTOK*DIMN];
__device__ float g_x   [MTOK*DIMN];
__device__ float g_q   [MTOK*DIMN];
__device__ float g_k   [MTOK*DIMN];
__device__ float g_v   [MTOK*DIMN];
__device__ float g_vt  [MTOK*DIMN];
__device__ float g_y   [MTOK*DIMN];
__device__ float g_gate[MTOK*HIDDEN];
__device__ float g_up  [MTOK*HIDDEN];

// ---------------- PTX helpers ----------------
__device__ __forceinline__ uint32_t smem_u32(const void* p) {
    uint32_t a;
    asm("{ .reg .u64 t; cvta.to.shared.u64 t, %1; cvt.u32.u64 %0, t; }"
        : "=r"(a) : "l"(p));
    return a;
}

__device__ __forceinline__ void ldm4(uint32_t* r, uint32_t addr) {
    asm volatile("ldmatrix.sync.aligned.m8n8.x4.shared.b16 {%0,%1,%2,%3}, [%4];"
                 : "=r"(r[0]), "=r"(r[1]), "=r"(r[2]), "=r"(r[3]) : "r"(addr));
}

__device__ __forceinline__ void mma16816(float* c, const uint32_t* a, const uint32_t* b) {
    asm volatile("mma.sync.aligned.m16n8k16.row.col.f32.bf16.bf16.f32 "
                 "{%0,%1,%2,%3}, {%4,%5,%6,%7}, {%8,%9}, {%0,%1,%2,%3};"
                 : "+f"(c[0]), "+f"(c[1]), "+f"(c[2]), "+f"(c[3])
                 : "r"(a[0]), "r"(a[1]), "r"(a[2]), "r"(a[3]),
                   "r"(b[0]), "r"(b[1]));
}

__device__ __forceinline__ void mma16816h(float* c, const uint32_t* a, const uint32_t* b) {
    asm volatile("mma.sync.aligned.m16n8k16.row.col.f32.f16.f16.f32 "
                 "{%0,%1,%2,%3}, {%4,%5,%6,%7}, {%8,%9}, {%0,%1,%2,%3};"
                 : "+f"(c[0]), "+f"(c[1]), "+f"(c[2]), "+f"(c[3])
                 : "r"(a[0]), "r"(a[1]), "r"(a[2]), "r"(a[3]),
                   "r"(b[0]), "r"(b[1]));
}

__device__ __forceinline__ uint32_t pk_hi(float a, float b) {
    return __byte_perm(__float_as_uint(a), __float_as_uint(b), 0x7632);
}
__device__ __forceinline__ uint32_t pk_lo(float a, float b) {
    float la = a - __uint_as_float(__float_as_uint(a) & 0xFFFF0000u);
    float lb = b - __uint_as_float(__float_as_uint(b) & 0xFFFF0000u);
    return __byte_perm(__float_as_uint(la), __float_as_uint(lb), 0x7632);
}

__device__ __forceinline__ void split_store(uint32_t hi_base, uint32_t lo_base,
                                            int row, int k4, float4 f) {
    uint32_t h01 = pk_hi(f.x, f.y), h23 = pk_hi(f.z, f.w);
    uint32_t l01 = pk_lo(f.x, f.y), l23 = pk_lo(f.z, f.w);
    int chunk = k4 >> 1, half = k4 & 1;
    uint32_t off = (uint32_t)(row * 64 + ((chunk ^ ((row >> 1) & 3)) << 4) + half * 8);
    asm volatile("st.shared.v2.b32 [%0], {%1,%2};" :: "r"(hi_base + off), "r"(h01), "r"(h23));
    asm volatile("st.shared.v2.b32 [%0], {%1,%2};" :: "r"(lo_base + off), "r"(l01), "r"(l23));
}

// fp16 single-plane store
__device__ __forceinline__ void half_store(uint32_t base, int row, int k4, float4 f) {
    __half2 a = __floats2half2_rn(f.x, f.y);
    __half2 b = __floats2half2_rn(f.z, f.w);
    uint32_t h01 = *(uint32_t*)&a, h23 = *(uint32_t*)&b;
    int chunk = k4 >> 1, half = k4 & 1;
    uint32_t off = (uint32_t)(row * 64 + ((chunk ^ ((row >> 1) & 3)) << 4) + half * 8);
    asm volatile("st.shared.v2.b32 [%0], {%1,%2};" :: "r"(base + off), "r"(h01), "r"(h23));
}

// fp16 hi/lo split store (22-bit effective)
__device__ __forceinline__ void half_split_store(uint32_t hi_base, uint32_t lo_base,
                                                 int row, int k4, float4 f) {
    __half2 h0 = __floats2half2_rn(f.x, f.y);
    __half2 h1 = __floats2half2_rn(f.z, f.w);
    float lx = f.x - __half2float(__low2half(h0));
    float ly = f.y - __half2float(__high2half(h0));
    float lz = f.z - __half2float(__low2half(h1));
    float lw = f.w - __half2float(__high2half(h1));
    __half2 l0 = __floats2half2_rn(lx, ly);
    __half2 l1 = __floats2half2_rn(lz, lw);
    uint32_t hh01 = *(uint32_t*)&h0, hh23 = *(uint32_t*)&h1;
    uint32_t ll01 = *(uint32_t*)&l0, ll23 = *(uint32_t*)&l1;
    int chunk = k4 >> 1, half = k4 & 1;
    uint32_t off = (uint32_t)(row * 64 + ((chunk ^ ((row >> 1) & 3)) << 4) + half * 8);
    asm volatile("st.shared.v2.b32 [%0], {%1,%2};" :: "r"(hi_base + off), "r"(hh01), "r"(hh23));
    asm volatile("st.shared.v2.b32 [%0], {%1,%2};" :: "r"(lo_base + off), "r"(ll01), "r"(ll23));
}

// ---------------- bf16 3-term GEMM body (validated since R4) --------------
template<int BN, bool ACCUM>
__device__ __forceinline__ void gemm_body(
    const float* __restrict__ A, int lda,
    const float* __restrict__ B, int ldb,
    float*       __restrict__ C, int ldc,
    int K, float alpha, int m0, int n0)
{
    constexpr int WN    = BN / 4;
    constexpr int NA    = WN / 8;
    constexpr int NB4   = BN / 32;
    constexpr int A_LO  = 8192;
    constexpr int B_HI  = 16384;
    constexpr int BLO_D = BN * 64;
    constexpr int STAGE = 16384 + BN * 128;

    extern __shared__ char smem[];
    const uint32_t sb0 = smem_u32(smem);

    const int tid = threadIdx.x, lane = tid & 31, wid = tid >> 5;
    const int wm = wid & 1, wn = wid >> 1;

    uint32_t offA[4][2], offB[NA / 2][2];
    #pragma unroll
    for (int am = 0; am < 4; am++)
        #pragma unroll
        for (int kh = 0; kh < 2; kh++) {
            int mrow  = wm * 64 + am * 16 + (lane & 7) + ((lane >> 3) & 1) * 8;
            int chunk = kh * 2 + ((lane >> 4) & 1);
            offA[am][kh] = (uint32_t)(mrow * 64 + ((chunk ^ ((mrow >> 1) & 3)) << 4));
        }
    #pragma unroll
    for (int p = 0; p < NA / 2; p++)
        #pragma unroll
        for (int kh = 0; kh < 2; kh++) {
            int nrow  = wn * WN + p * 16 + (lane & 7) + ((lane >> 4) & 1) * 8;
            int chunk = kh * 2 + ((lane >> 3) & 1);
            offB[p][kh] = (uint32_t)(B_HI + nrow * 64 + ((chunk ^ ((nrow >> 1) & 3)) << 4));
        }

    float acc[4][NA][4];
    #pragma unroll
    for (int i = 0; i < 4; i++)
        #pragma unroll
        for (int j = 0; j < NA; j++)
            #pragma unroll
            for (int e = 0; e < 4; e++) acc[i][j][e] = 0.0f;

    float4 pa[4], pb[NB4];
    auto LOADG = [&](int k0) {
        #pragma unroll
        for (int i = 0; i < 4; i++) {
            int idx = i * 256 + tid, row = idx >> 3, k4 = idx & 7;
            pa[i] = *(const float4*)&A[(long)(m0 + row) * lda + k0 + k4 * 4];
        }
        #pragma unroll
        for (int i = 0; i < NB4; i++) {
            int idx = i * 256 + tid, row = idx >> 3, k4 = idx & 7;
            pb[i] = *(const float4*)&B[(long)(n0 + row) * ldb + k0 + k4 * 4];
        }
    };
    auto STORES = [&](uint32_t base) {
        #pragma unroll
        for (int i = 0; i < 4; i++) {
            int idx = i * 256 + tid, row = idx >> 3, k4 = idx & 7;
            split_store(base, base + A_LO, row, k4, pa[i]);
        }
        #pragma unroll
        for (int i = 0; i < NB4; i++) {
            int idx = i * 256 + tid, row = idx >> 3, k4 = idx & 7;
            split_store(base + B_HI, base + B_HI + BLO_D, row, k4, pb[i]);
        }
    };

    const int nk = K >> 5;
    LOADG(0);
    STORES(sb0);
    __syncthreads();

    for (int t = 0; t < nk; t++) {
        const uint32_t sb = sb0 + (uint32_t)(t & 1) * STAGE;
        if (t + 1 < nk) LOADG((t + 1) * 32);

        #pragma unroll
        for (int kh = 0; kh < 2; kh++) {
            uint32_t ah[4][4], al[4][4];
            #pragma unroll
            for (int am = 0; am < 4; am++) {
                ldm4(ah[am], sb + offA[am][kh]);
                ldm4(al[am], sb + offA[am][kh] + A_LO);
            }
            uint32_t bh[NA / 2][4], bl[NA / 2][4];
            #pragma unroll
            for (int p = 0; p < NA / 2; p++) {
                ldm4(bh[p], sb + offB[p][kh]);
                ldm4(bl[p], sb + offB[p][kh] + BLO_D);
            }
            #pragma unroll
            for (int am = 0; am < 4; am++)
                #pragma unroll
                for (int na = 0; na < NA; na++) {
                    const uint32_t* bhp = &bh[na >> 1][(na & 1) * 2];
                    const uint32_t* blp = &bl[na >> 1][(na & 1) * 2];
                    mma16816(acc[am][na], ah[am], bhp);
                    mma16816(acc[am][na], ah[am], blp);
                    mma16816(acc[am][na], al[am], bhp);
                }
        }

        if (t + 1 < nk) STORES(sb0 + (uint32_t)((t & 1) ^ 1) * STAGE);
        __syncthreads();
    }

    #pragma unroll
    for (int am = 0; am < 4; am++)
        #pragma unroll
        for (int na = 0; na < NA; na++) {
            int row = m0 + wm * 64 + am * 16 + (lane >> 2);
            int col = n0 + wn * WN + na * 8 + (lane & 3) * 2;
            float* base0 = &C[(long)row * ldc + col];
            float* base1 = &C[(long)(row + 8) * ldc + col];
            float2 r0 = { alpha * acc[am][na][0], alpha * acc[am][na][1] };
            float2 r1 = { alpha * acc[am][na][2], alpha * acc[am][na][3] };
            if (ACCUM) {
                float2 o0 = *(float2*)base0, o1 = *(float2*)base1;
                r0.x += o0.x; r0.y += o0.y; r1.x += o1.x; r1.y += o1.y;
            }
            *(float2*)base0 = r0;
            *(float2*)base1 = r1;
        }
}

template<int BN, bool ACCUM>
__global__ void __launch_bounds__(256, 1)
mma_gemm(const float* __restrict__ A, int lda,
         const float* __restrict__ B, int ldb,
         float*       __restrict__ C, int ldc,
         int K, float alpha)
{
    gemm_body<BN, ACCUM>(A, lda, B, ldb, C, ldc, K, alpha,
                         blockIdx.x * 128, blockIdx.y * BN);
}

struct P3 {
    const float *B0, *B1, *B2;
    float *C0, *C1, *C2;
};

__global__ void __launch_bounds__(256, 1)
mma_gemm_multi(const float* __restrict__ A, int lda, P3 p,
               int ldb, int ldc, int K, float alpha)
{
    const int z = blockIdx.z;
    const float* B = (z == 0) ? p.B0 : (z == 1) ? p.B1 : p.B2;
    float*       C = (z == 0) ? p.C0 : (z == 1) ? p.C1 : p.C2;
    gemm_body<128, false>(A, lda, B, ldb, C, ldc, K, alpha,
                          blockIdx.x * 128, blockIdx.y * 128);
}

// ------------ fp16 2-term GEMM (A hi/lo fp16, B single fp16) --------------
// C = A * B^T. Error ~ weight fp16 rounding (~2e-4). Used for FFN gate/up.
__global__ void __launch_bounds__(256, 1)
mma_gemm_multi_2t(const float* __restrict__ A, int lda,
                  const float* __restrict__ B0g, const float* __restrict__ B1g,
                  float* __restrict__ C0g, float* __restrict__ C1g,
                  int ldb, int ldc, int K)
{
    constexpr int A_LO  = 8192;
    constexpr int B_OFF = 16384;
    constexpr int STAGE = 24576;

    const float* B = (blockIdx.z == 0) ? B0g : B1g;
    float*       C = (blockIdx.z == 0) ? C0g : C1g;

    extern __shared__ char smem[];
    const uint32_t sb0 = smem_u32(smem);

    const int tid = threadIdx.x, lane = tid & 31, wid = tid >> 5;
    const int wm = wid & 1, wn = wid >> 1;
    const int m0 = blockIdx.x * 128;
    const int n0 = blockIdx.y * 128;

    uint32_t offA[4][2], offB[2][2];
    #pragma unroll
    for (int am = 0; am < 4; am++)
        #pragma unroll
        for (int kh = 0; kh < 2; kh++) {
            int mrow  = wm * 64 + am * 16 + (lane & 7) + ((lane >> 3) & 1) * 8;
            int chunk = kh * 2 + ((lane >> 4) & 1);
            offA[am][kh] = (uint32_t)(mrow * 64 + ((chunk ^ ((mrow >> 1) & 3)) << 4));
        }
    #pragma unroll
    for (int p = 0; p < 2; p++)
        #pragma unroll
        for (int kh = 0; kh < 2; kh++) {
            int nrow  = wn * 32 + p * 16 + (lane & 7) + ((lane >> 4) & 1) * 8;
            int chunk = kh * 2 + ((lane >> 3) & 1);
            offB[p][kh] = (uint32_t)(B_OFF + nrow * 64 + ((chunk ^ ((nrow >> 1) & 3)) << 4));
        }

    float acc[4][4][4];
    #pragma unroll
    for (int i = 0; i < 4; i++)
        #pragma unroll
        for (int j = 0; j < 4; j++)
            #pragma unroll
            for (int e = 0; e < 4; e++) acc[i][j][e] = 0.0f;

    float4 pa[4], pb[4];
    auto LOADG = [&](int k0) {
        #pragma unroll
        for (int i = 0; i < 4; i++) {
            int idx = i * 256 + tid, row = idx >> 3, k4 = idx & 7;
            pa[i] = *(const float4*)&A[(long)(m0 + row) * lda + k0 + k4 * 4];
        }
        #pragma unroll
        for (int i = 0; i < 4; i++) {
            int idx = i * 256 + tid, row = idx >> 3, k4 = idx & 7;
            pb[i] = *(const float4*)&B[(long)(n0 + row) * ldb + k0 + k4 * 4];
        }
    };
    auto STORES = [&](uint32_t base) {
        #pragma unroll
        for (int i = 0; i < 4; i++) {
            int idx = i * 256 + tid, row = idx >> 3, k4 = idx & 7;
            half_split_store(base, base + A_LO, row, k4, pa[i]);
        }
        #pragma unroll
        for (int i = 0; i < 4; i++) {
            int idx = i * 256 + tid, row = idx >> 3, k4 = idx & 7;
            half_store(base + B_OFF, row, k4, pb[i]);
        }
    };

    const int nk = K >> 5;
    LOADG(0);
    STORES(sb0);
    __syncthreads();

    for (int t = 0; t < nk; t++) {
        const uint32_t sb = sb0 + (uint32_t)(t & 1) * STAGE;
        if (t + 1 < nk) LOADG((t + 1) * 32);

        #pragma unroll
        for (int kh = 0; kh < 2; kh++) {
            uint32_t ah[4][4], al[4][4];
            #pragma unroll
            for (int am = 0; am < 4; am++) {
                ldm4(ah[am], sb + offA[am][kh]);
                ldm4(al[am], sb + offA[am][kh] + A_LO);
            }
            uint32_t bh[2][4];
            #pragma unroll
            for (int p = 0; p < 2; p++)
                ldm4(bh[p], sb + offB[p][kh]);
            #pragma unroll
            for (int am = 0; am < 4; am++)
                #pragma unroll
                for (int na = 0; na < 4; na++) {
                    const uint32_t* bp = &bh[na >> 1][(na & 1) * 2];
                    mma16816h(acc[am][na], ah[am], bp);
                    mma16816h(acc[am][na], al[am], bp);
                }
        }

        if (t + 1 < nk) STORES(sb0 + (uint32_t)((t & 1) ^ 1) * STAGE);
        __syncthreads();
    }

    #pragma unroll
    for (int am = 0; am < 4; am++)
        #pragma unroll
        for (int na = 0; na < 4; na++) {
            int row = m0 + wm * 64 + am * 16 + (lane >> 2);
            int col = n0 + wn * 32 + na * 8 + (lane & 3) * 2;
            float2 r0 = { acc[am][na][0], acc[am][na][1] };
            float2 r1 = { acc[am][na][2], acc[am][na][3] };
            *(float2*)&C[(long)row * ldc + col] = r0;
            *(float2*)&C[(long)(row + 8) * ldc + col] = r1;
        }
}

// ---------------- fp16 single-term GEMM (lm_head, validated R13) ----------
__global__ void __launch_bounds__(256, 1)
mma_gemm_h(const float* __restrict__ A, int lda,
           const float* __restrict__ B, int ldb,
           float*       __restrict__ C, int ldc,
           int K)
{
    constexpr int B_OFF = 8192;
    constexpr int STAGE = 16384;

    extern __shared__ char smem[];
    const uint32_t sb0 = smem_u32(smem);

    const int tid = threadIdx.x, lane = tid & 31, wid = tid >> 5;
    const int wm = wid & 1, wn = wid >> 1;
    const int m0 = blockIdx.x * 128;
    const int n0 = blockIdx.y * 128;

    uint32_t offA[4][2], offB[2][2];
    #pragma unroll
    for (int am = 0; am < 4; am++)
        #pragma unroll
        for (int kh = 0; kh < 2; kh++) {
            int mrow  = wm * 64 + am * 16 + (lane & 7) + ((lane >> 3) & 1) * 8;
            int chunk = kh * 2 + ((lane >> 4) & 1);
            offA[am][kh] = (uint32_t)(mrow * 64 + ((chunk ^ ((mrow >> 1) & 3)) << 4));
        }
    #pragma unroll
    for (int p = 0; p < 2; p++)
        #pragma unroll
        for (int kh = 0; kh < 2; kh++) {
            int nrow  = wn * 32 + p * 16 + (lane & 7) + ((lane >> 4) & 1) * 8;
            int chunk = kh * 2 + ((lane >> 3) & 1);
            offB[p][kh] = (uint32_t)(B_OFF + nrow * 64 + ((chunk ^ ((nrow >> 1) & 3)) << 4));
        }

    float acc[4][4][4];
    #pragma unroll
    for (int i = 0; i < 4; i++)
        #pragma unroll
        for (int j = 0; j < 4; j++)
            #pragma unroll
            for (int e = 0; e < 4; e++) acc[i][j][e] = 0.0f;

    float4 pa[4], pb[4];
    auto LOADG = [&](int k0) {
        #pragma unroll
        for (int i = 0; i < 4; i++) {
            int idx = i * 256 + tid, row = idx >> 3, k4 = idx & 7;
            pa[i] = *(const float4*)&A[(long)(m0 + row) * lda + k0 + k4 * 4];
        }
        #pragma unroll
        for (int i = 0; i < 4; i++) {
            int idx = i * 256 + tid, row = idx >> 3, k4 = idx & 7;
            pb[i] = *(const float4*)&B[(long)(n0 + row) * ldb + k0 + k4 * 4];
        }
    };
    auto STORES = [&](uint32_t base) {
        #pragma unroll
        for (int i = 0; i < 4; i++) {
            int idx = i * 256 + tid, row = idx >> 3, k4 = idx & 7;
            half_store(base, row, k4, pa[i]);
        }
        #pragma unroll
        for (int i = 0; i < 4; i++) {
            int idx = i * 256 + tid, row = idx >> 3, k4 = idx & 7;
            half_store(base + B_OFF, row, k4, pb[i]);
        }
    };

    const int nk = K >> 5;
    LOADG(0);
    STORES(sb0);
    __syncthreads();

    for (int t = 0; t < nk; t++) {
        const uint32_t sb = sb0 + (uint32_t)(t & 1) * STAGE;
        if (t + 1 < nk) LOADG((t + 1) * 32);

        #pragma unroll
        for (int kh = 0; kh < 2; kh++) {
            uint32_t ah[4][4];
            #pragma unroll
            for (int am = 0; am < 4; am++)
                ldm4(ah[am], sb + offA[am][kh]);
            uint32_t bh[2][4];
            #pragma unroll
            for (int p = 0; p < 2; p++)
                ldm4(bh[p], sb + offB[p][kh]);
            #pragma unroll
            for (int am = 0; am < 4; am++)
                #pragma unroll
                for (int na = 0; na < 4; na++)
                    mma16816h(acc[am][na], ah[am], &bh[na >> 1][(na & 1) * 2]);
        }

        if (t + 1 < nk) STORES(sb0 + (uint32_t)((t & 1) ^ 1) * STAGE);
        __syncthreads();
    }

    #pragma unroll
    for (int am = 0; am < 4; am++)
        #pragma unroll
        for (int na = 0; na < 4; na++) {
            int row = m0 + wm * 64 + am * 16 + (lane >> 2);
            int col = n0 + wn * 32 + na * 8 + (lane & 3) * 2;
            float2 r0 = { acc[am][na][0], acc[am][na][1] };
            float2 r1 = { acc[am][na][2], acc[am][na][3] };
            *(float2*)&C[(long)row * ldc + col] = r0;
            *(float2*)&C[(long)(row + 8) * ldc + col] = r1;
        }
}

// ================= flash attention, s-tile 64, 2 CTAs/SM (validated R12) ==
#define FA_QH  0
#define FA_QL  16384
#define FA_KH  32768
#define FA_KL  40960
#define FA_VH  49152
#define FA_VL  57344
#define FA_PH  65536
#define FA_PL  81920
#define FA_SMX 98304
#define FA_SSM 100352
#define FA_BYTES 102400

__global__ void __launch_bounds__(256, 2)
flash_attn(const float* __restrict__ q, const float* __restrict__ k,
           const float* __restrict__ vt, float* __restrict__ y)
{
    extern __shared__ char smem[];
    const uint32_t sb = smem_u32(smem);
    float* smx = (float*)(smem + FA_SMX);
    float* ssm = (float*)(smem + FA_SSM);

    const int tid = threadIdx.x, lane = tid & 31, wid = tid >> 5;
    const int wm = wid & 1, wn = wid >> 1;
    const int bh = blockIdx.z, b = bh >> 4, hh = bh & 15;
    const int q0 = blockIdx.x * 128;

    uint32_t offA[4][2];
    #pragma unroll
    for (int am = 0; am < 4; am++)
        #pragma unroll
        for (int khi = 0; khi < 2; khi++) {
            int arow  = wm * 64 + am * 16 + (lane & 7) + ((lane >> 3) & 1) * 8;
            int chunk = khi * 2 + ((lane >> 4) & 1);
            offA[am][khi] = (uint32_t)(arow * 64 + ((chunk ^ ((arow >> 1) & 3)) << 4));
        }
    uint32_t offK[2], offV[2];
    #pragma unroll
    for (int khi = 0; khi < 2; khi++) {
        int brow  = wn * 16 + (lane & 7) + ((lane >> 4) & 1) * 8;
        int chunk = khi * 2 + ((lane >> 3) & 1);
        uint32_t o = (uint32_t)(brow * 64 + ((chunk ^ ((brow >> 1) & 3)) << 4));
        offK[khi] = o;
        offV[khi] = o;
    }

    #pragma unroll
    for (int i = 0; i < 8; i++) {
        int idx = i * 256 + tid, row = idx >> 4, k4 = idx & 15;
        float4 f = *(const float4*)&q[(long)(b * SEQ + q0 + row) * DIMN + hh * 64 + k4 * 4];
        f.x *= 0.125f; f.y *= 0.125f; f.z *= 0.125f; f.w *= 0.125f;
        split_store(sb + FA_QH + (k4 >> 3) * 8192, sb + FA_QL + (k4 >> 3) * 8192,
                    row, k4 & 7, f);
    }

    float o[4][2][4];
    float m_r[4][2], l_r[4][2];
    #pragma unroll
    for (int am = 0; am < 4; am++) {
        m_r[am][0] = m_r[am][1] = -1e30f;
        l_r[am][0] = l_r[am][1] = 0.0f;
        #pragma unroll
        for (int na = 0; na < 2; na++)
            #pragma unroll
            for (int e = 0; e < 4; e++) o[am][na][e] = 0.0f;
    }

    const int rb = wm * 64 + (lane >> 2);

    for (int s0 = 0; s0 < SEQ; s0 += 64) {
        __syncthreads();

        #pragma unroll
        for (int i = 0; i < 4; i++) {
            int idx = i * 256 + tid, row = idx >> 4, k4 = idx & 15;
            float4 f = *(const float4*)&k[(long)(b * SEQ + s0 + row) * DIMN + hh * 64 + k4 * 4];
            split_store(sb + FA_KH + (k4 >> 3) * 4096, sb + FA_KL + (k4 >> 3) * 4096,
                        row, k4 & 7, f);
        }
        #pragma unroll
        for (int i = 0; i < 4; i++) {
            int idx = i * 256 + tid, row = idx >> 4, s4 = idx & 15;
            float4 f = *(const float4*)&vt[((long)bh * 64 + row) * SEQ + s0 + s4 * 4];
            split_store(sb + FA_VH + (s4 >> 3) * 4096, sb + FA_VL + (s4 >> 3) * 4096,
                        row, s4 & 7, f);
        }
        __syncthreads();

        float sf[4][2][4];
        #pragma unroll
        for (int am = 0; am < 4; am++)
            #pragma unroll
            for (int na = 0; na < 2; na++)
                #pragma unroll
                for (int e = 0; e < 4; e++) sf[am][na][e] = 0.0f;

        #pragma unroll
        for (int kb = 0; kb < 2; kb++)
            #pragma unroll
            for (int khi = 0; khi < 2; khi++) {
                uint32_t ah[4][4], al[4][4];
                #pragma unroll
                for (int am = 0; am < 4; am++) {
                    ldm4(ah[am], sb + FA_QH + kb * 8192 + offA[am][khi]);
                    ldm4(al[am], sb + FA_QL + kb * 8192 + offA[am][khi]);
                }
                uint32_t bhf[4], blf[4];
                ldm4(bhf, sb + FA_KH + kb * 4096 + offK[khi]);
                ldm4(blf, sb + FA_KL + kb * 4096 + offK[khi]);
                #pragma unroll
                for (int am = 0; am < 4; am++)
                    #pragma unroll
                    for (int na = 0; na < 2; na++) {
                        const uint32_t* bhp = &bhf[na * 2];
                        const uint32_t* blp = &blf[na * 2];
                        mma16816(sf[am][na], ah[am], bhp);
                        mma16816(sf[am][na], ah[am], blp);
                        mma16816(sf[am][na], al[am], bhp);
                    }
            }

        #pragma unroll
        for (int am = 0; am < 4; am++) {
            float v0 = -1e30f, v1 = -1e30f;
            #pragma unroll
            for (int na = 0; na < 2; na++) {
                v0 = fmaxf(v0, fmaxf(sf[am][na][0], sf[am][na][1]));
                v1 = fmaxf(v1, fmaxf(sf[am][na][2], sf[am][na][3]));
            }
            v0 = fmaxf(v0, __shfl_xor_sync(0xFFFFFFFFu, v0, 1));
            v0 = fmaxf(v0, __shfl_xor_sync(0xFFFFFFFFu, v0, 2));
            v1 = fmaxf(v1, __shfl_xor_sync(0xFFFFFFFFu, v1, 1));
            v1 = fmaxf(v1, __shfl_xor_sync(0xFFFFFFFFu, v1, 2));
            if ((lane & 3) == 0) {
                smx[(rb + am * 16) * 4 + wn] = v0;
                smx[(rb + am * 16 + 8) * 4 + wn] = v1;
            }
        }
        __syncthreads();

        float csc[4][2];
        #pragma unroll
        for (int am = 0; am < 4; am++) {
            int r0 = rb + am * 16, r1 = r0 + 8;
            float tm0 = fmaxf(fmaxf(smx[r0 * 4 + 0], smx[r0 * 4 + 1]),
                              fmaxf(smx[r0 * 4 + 2], smx[r0 * 4 + 3]));
            float tm1 = fmaxf(fmaxf(smx[r1 * 4 + 0], smx[r1 * 4 + 1]),
                              fmaxf(smx[r1 * 4 + 2], smx[r1 * 4 + 3]));
            float mn0 = fmaxf(m_r[am][0], tm0);
            float mn1 = fmaxf(m_r[am][1], tm1);
            csc[am][0] = __expf(m_r[am][0] - mn0);
            csc[am][1] = __expf(m_r[am][1] - mn1);
            m_r[am][0] = mn0; m_r[am][1] = mn1;

            float rs0 = 0.0f, rs1 = 0.0f;
            #pragma unroll
            for (int na = 0; na < 2; na++) {
                float p0 = __expf(sf[am][na][0] - mn0);
                float p1 = __expf(sf[am][na][1] - mn0);
                float p2 = __expf(sf[am][na][2] - mn1);
                float p3 = __expf(sf[am][na][3] - mn1);
                rs0 += p0 + p1; rs1 += p2 + p3;
                int c0col = wn * 16 + na * 8 + (lane & 3) * 2;
                int kb = c0col >> 5, cc = c0col & 31;
                uint32_t o0 = (uint32_t)(kb * 8192 + r0 * 64 +
                              (((cc >> 3) ^ ((r0 >> 1) & 3)) << 4) +
                              ((cc >> 2) & 1) * 8 + (cc & 3) * 2);
                uint32_t o1 = (uint32_t)(kb * 8192 + r1 * 64 +
                              (((cc >> 3) ^ ((r1 >> 1) & 3)) << 4) +
                              ((cc >> 2) & 1) * 8 + (cc & 3) * 2);
                *(uint32_t*)(smem + FA_PH + o0) = pk_hi(p0, p1);
                *(uint32_t*)(smem + FA_PL + o0) = pk_lo(p0, p1);
                *(uint32_t*)(smem + FA_PH + o1) = pk_hi(p2, p3);
                *(uint32_t*)(smem + FA_PL + o1) = pk_lo(p2, p3);
            }
            rs0 += __shfl_xor_sync(0xFFFFFFFFu, rs0, 1);
            rs0 += __shfl_xor_sync(0xFFFFFFFFu, rs0, 2);
            rs1 += __shfl_xor_sync(0xFFFFFFFFu, rs1, 1);
            rs1 += __shfl_xor_sync(0xFFFFFFFFu, rs1, 2);
            if ((lane & 3) == 0) {
                ssm[r0 * 4 + wn] = rs0;
                ssm[r1 * 4 + wn] = rs1;
            }
        }
        __syncthreads();

        #pragma unroll
        for (int am = 0; am < 4; am++) {
            int r0 = rb + am * 16, r1 = r0 + 8;
            float s0s = ssm[r0 * 4 + 0] + ssm[r0 * 4 + 1] + ssm[r0 * 4 + 2] + ssm[r0 * 4 + 3];
            float s1s = ssm[r1 * 4 + 0] + ssm[r1 * 4 + 1] + ssm[r1 * 4 + 2] + ssm[r1 * 4 + 3];
            l_r[am][0] = l_r[am][0] * csc[am][0] + s0s;
            l_r[am][1] = l_r[am][1] * csc[am][1] + s1s;
            #pragma unroll
            for (int na = 0; na < 2; na++) {
                o[am][na][0] *= csc[am][0]; o[am][na][1] *= csc[am][0];
                o[am][na][2] *= csc[am][1]; o[am][na][3] *= csc[am][1];
            }
        }

        #pragma unroll
        for (int kb = 0; kb < 2; kb++)
            #pragma unroll
            for (int khi = 0; khi < 2; khi++) {
                uint32_t ah[4][4], al[4][4];
                #pragma unroll
                for (int am = 0; am < 4; am++) {
                    ldm4(ah[am], sb + FA_PH + kb * 8192 + offA[am][khi]);
                    ldm4(al[am], sb + FA_PL + kb * 8192 + offA[am][khi]);
                }
                uint32_t bhf[4], blf[4];
                ldm4(bhf, sb + FA_VH + kb * 4096 + offV[khi]);
                ldm4(blf, sb + FA_VL + kb * 4096 + offV[khi]);
                #pragma unroll
                for (int am = 0; am < 4; am++)
                    #pragma unroll
                    for (int na = 0; na < 2; na++) {
                        const uint32_t* bhp = &bhf[na * 2];
                        const uint32_t* blp = &blf[na * 2];
                        mma16816(o[am][na], ah[am], bhp);
                        mma16816(o[am][na], ah[am], blp);
                        mma16816(o[am][na], al[am], bhp);
                    }
            }
    }

    #pragma unroll
    for (int am = 0; am < 4; am++) {
        float inv0 = 1.0f / l_r[am][0];
        float inv1 = 1.0f / l_r[am][1];
        long tok0 = (long)(b * SEQ + q0 + wm * 64 + am * 16 + (lane >> 2));
        #pragma unroll
        for (int na = 0; na < 2; na++) {
            int col = hh * 64 + wn * 16 + na * 8 + (lane & 3) * 2;
            float2 r0 = { o[am][na][0] * inv0, o[am][na][1] * inv0 };
            float2 r1 = { o[am][na][2] * inv1, o[am][na][3] * inv1 };
            *(float2*)&y[tok0 * DIMN + col] = r0;
            *(float2*)&y[(tok0 + 8) * DIMN + col] = r1;
        }
    }
}

// ---------------- elementwise kernels ----------------
__global__ void embed_kernel(const int* __restrict__ tokens,
                             const float* __restrict__ embed,
                             float* __restrict__ h)
{
    int row = blockIdx.x;
    int tok = tokens[row];
    ((float4*)(h + (long)row * DIMN))[threadIdx.x] =
        ((const float4*)(embed + (long)tok * DIMN))[threadIdx.x];
}

__global__ void rmsnorm_kernel(const float* __restrict__ x,
                               const float* __restrict__ w,
                               float* __restrict__ out)
{
    int row = blockIdx.x;
    float4 v = ((const float4*)(x + (long)row * DIMN))[threadIdx.x];
    float ss = v.x*v.x + v.y*v.y + v.z*v.z + v.w*v.w;
    __shared__ float red[8];
    #pragma unroll
    for (int o = 16; o > 0; o >>= 1) ss += __shfl_xor_sync(0xFFFFFFFFu, ss, o);
    if ((threadIdx.x & 31) == 0) red[threadIdx.x >> 5] = ss;
    __syncthreads();
    if (threadIdx.x < 8) {
        float s = red[threadIdx.x];
        #pragma unroll
        for (int o = 4; o > 0; o >>= 1) s += __shfl_xor_sync(0xFFu, s, o);
        if (threadIdx.x == 0) red[0] = s;
    }
    __syncthreads();
    float scale = rsqrtf(red[0] * (1.0f / DIMN) + EPS);
    float4 wv = ((const float4*)w)[threadIdx.x];
    float4 o4 = { v.x*scale*wv.x, v.y*scale*wv.y, v.z*scale*wv.z, v.w*scale*wv.w };
    ((float4*)(out + (long)row * DIMN))[threadIdx.x] = o4;
}

__global__ void silu_mul_kernel(float4* __restrict__ g, const float4* __restrict__ u)
{
    long i = (long)blockIdx.x * blockDim.x + threadIdx.x;
    float4 gv = g[i], uv = u[i];
    gv.x = gv.x / (1.0f + __expf(-gv.x)) * uv.x;
    gv.y = gv.y / (1.0f + __expf(-gv.y)) * uv.y;
    gv.z = gv.z / (1.0f + __expf(-gv.z)) * uv.z;
    gv.w = gv.w / (1.0f + __expf(-gv.w)) * uv.w;
    g[i] = gv;
}

// vt[(b*H+h)][d][s] = v[b*SEQ+s][h*64+d]
__global__ void transpose_v_kernel(const float* __restrict__ v, float* __restrict__ vt)
{
    __shared__ float t[32][33];
    int bh = blockIdx.z, b = bh >> 4, hh = bh & 15;
    int s0 = blockIdx.x * 32, d0 = blockIdx.y * 32;
    int tx = threadIdx.x, ty = threadIdx.y;    // 32 x 8
    #pragma unroll
    for (int j = 0; j < 32; j += 8)
        t[ty + j][tx] = v[(long)(b * SEQ + s0 + ty + j) * DIMN + hh * HEAD_DIM + d0 + tx];
    __syncthreads();
    #pragma unroll
    for (int j = 0; j < 32; j += 8)
        vt[((long)bh * HEAD_DIM + d0 + ty + j) * SEQ + s0 + tx] = t[tx][ty + j];
}

// ---------------- launcher ----------------
extern "C" void kernel_launch(void* const* d_in, const int* in_sizes, int n_in,
                              void* d_out, int out_size)
{
    const int*   tokens  = (const int*)  d_in[0];
    const float* embed   = (const float*)d_in[1];
    const float* Wq      = (const float*)d_in[2];
    const float* Wk      = (const float*)d_in[3];
    const float* Wv      = (const float*)d_in[4];
    const float* Wo      = (const float*)d_in[5];
    const float* Wg      = (const float*)d_in[6];
    const float* Wu      = (const float*)d_in[7];
    const float* Wd      = (const float*)d_in[8];
    const float* ln1     = (const float*)d_in[9];
    const float* ln2     = (const float*)d_in[10];
    const float* norm_w  = (const float*)d_in[11];
    const float* lm_head = (const float*)d_in[12];
    float* out = (float*)d_out;

    float *h, *x, *q, *k, *v, *vt, *y, *gate, *up;
    cudaGetSymbolAddress((void**)&h,    g_h);
    cudaGetSymbolAddress((void**)&x,    g_x);
    cudaGetSymbolAddress((void**)&q,    g_q);
    cudaGetSymbolAddress((void**)&k,    g_k);
    cudaGetSymbolAddress((void**)&v,    g_v);
    cudaGetSymbolAddress((void**)&vt,   g_vt);
    cudaGetSymbolAddress((void**)&y,    g_y);
    cudaGetSymbolAddress((void**)&gate, g_gate);
    cudaGetSymbolAddress((void**)&up,   g_up);

    const int DYN128 = 2 * (16384 + 128 * 128);   // 65536
    const int DYNH   = 2 * 16384;                 // 32768
    const int DYN2T  = 2 * 24576;                 // 49152
    cudaFuncSetAttribute(mma_gemm<128, false>, cudaFuncAttributeMaxDynamicSharedMemorySize, DYN128);
    cudaFuncSetAttribute(mma_gemm<128, true>,  cudaFuncAttributeMaxDynamicSharedMemorySize, DYN128);
    cudaFuncSetAttribute(mma_gemm_multi,       cudaFuncAttributeMaxDynamicSharedMemorySize, DYN128);
    cudaFuncSetAttribute(mma_gemm_multi_2t,    cudaFuncAttributeMaxDynamicSharedMemorySize, DYN2T);
    cudaFuncSetAttribute(mma_gemm_h,           cudaFuncAttributeMaxDynamicSharedMemorySize, DYNH);
    cudaFuncSetAttribute(flash_attn, cudaFuncAttributeMaxDynamicSharedMemorySize, FA_BYTES);

    embed_kernel<<<MTOK, 256>>>(tokens, embed, h);

    dim3 gQKV (MTOK / 128, DIMN / 128, 3);
    dim3 gGU  (MTOK / 128, HIDDEN / 128, 2);
    dim3 gProj(MTOK / 128, DIMN / 128, 1);
    dim3 gHead(MTOK / 128, VOCAB / 128, 1);
    dim3 gFa  (SEQ / 128, 1, BATCH * HEADS);
    dim3 gTr  (SEQ / 32, HEAD_DIM / 32, BATCH * HEADS);

    for (int l = 0; l < LAYERS; l++) {
        const float* wq = Wq + (long)l * DIMN * DIMN;
        const float* wk = Wk + (long)l * DIMN * DIMN;
        const float* wv = Wv + (long)l * DIMN * DIMN;
        const float* wo = Wo + (long)l * DIMN * DIMN;
        const float* wg = Wg + (long)l * HIDDEN * DIMN;
        const float* wu = Wu + (long)l * HIDDEN * DIMN;
        const float* wd = Wd + (long)l * DIMN * HIDDEN;

        rmsnorm_kernel<<<MTOK, 256>>>(h, ln1 + (long)l * DIMN, x);

        {
            P3 p = { wq, wk, wv, q, k, v };
            mma_gemm_multi<<<gQKV, 256, DYN128>>>(x, DIMN, p, DIMN, DIMN, DIMN, 1.0f);
        }

        transpose_v_kernel<<<gTr, dim3(32, 8)>>>(v, vt);
        flash_attn<<<gFa, 256, FA_BYTES>>>(q, k, vt, y);

        // h += y @ Wo^T
        mma_gemm<128, true><<<gProj, 256, DYN128>>>(y, DIMN, wo, DIMN,
                                                    h, DIMN, DIMN, 1.0f);

        rmsnorm_kernel<<<MTOK, 256>>>(h, ln2 + (long)l * DIMN, x);

        // fused gate,up = x @ {Wg,Wu}^T — fp16 2-term (A hi/lo, W single)
        mma_gemm_multi_2t<<<gGU, 256, DYN2T>>>(x, DIMN, wg, wu, gate, up,
                                               DIMN, HIDDEN, DIMN);

        silu_mul_kernel<<<(MTOK * (long)HIDDEN / 4) / 256, 256>>>((float4*)gate, (const float4*)up);

        // h += gate @ Wd^T
        mma_gemm<128, true><<<gProj, 256, DYN128>>>(gate, HIDDEN, wd, HIDDEN,
                                                    h, DIMN, HIDDEN, 1.0f);
    }

    rmsnorm_kernel<<<MTOK, 256>>>(h, norm_w, x);
    mma_gemm_h<<<gHead, 256, DYNH>>>(x, DIMN, lm_head, DIMN, out, VOCAB, DIMN);
}

// round 15
// speedup vs baseline: 1.4023x; 1.0307x over previous
#include <cuda_runtime.h>
#include <cuda_fp16.h>
#include <math.h>
#include <stdint.h>

// ---------------- problem constants ----------------
#define DIMN     1024
#define HEADS    16
#define HEAD_DIM 64
#define LAYERS   4
#define HIDDEN   4096
#define VOCAB    32000
#define BATCH    2
#define SEQ      1024
#define MTOK     (BATCH*SEQ)
#define EPS      1e-6f

// ---------------- scratch ----------------
__device__ float g_h   [MTOK*DIMN];
__device__ float g_x   [MTOK*DIMN];
__device__ float g_q   [MTOK*DIMN];
__device__ float g_k   [MTOK*DIMN];
__device__ float g_v   [MTOK*DIMN];
__device__ float g_vt  [MTOK*DIMN];
__device__ float g_y   [MTOK*DIMN];
__device__ float g_gate[MTOK*HIDDEN];
__device__ float g_up  [MTOK*HIDDEN];

// ---------------- PTX helpers ----------------
__device__ __forceinline__ uint32_t smem_u32(const void* p) {
    uint32_t a;
    asm("{ .reg .u64 t; cvta.to.shared.u64 t, %1; cvt.u32.u64 %0, t; }"
        : "=r"(a) : "l"(p));
    return a;
}

__device__ __forceinline__ void ldm4(uint32_t* r, uint32_t addr) {
    asm volatile("ldmatrix.sync.aligned.m8n8.x4.shared.b16 {%0,%1,%2,%3}, [%4];"
                 : "=r"(r[0]), "=r"(r[1]), "=r"(r[2]), "=r"(r[3]) : "r"(addr));
}

__device__ __forceinline__ void mma16816(float* c, const uint32_t* a, const uint32_t* b) {
    asm volatile("mma.sync.aligned.m16n8k16.row.col.f32.bf16.bf16.f32 "
                 "{%0,%1,%2,%3}, {%4,%5,%6,%7}, {%8,%9}, {%0,%1,%2,%3};"
                 : "+f"(c[0]), "+f"(c[1]), "+f"(c[2]), "+f"(c[3])
                 : "r"(a[0]), "r"(a[1]), "r"(a[2]), "r"(a[3]),
                   "r"(b[0]), "r"(b[1]));
}

__device__ __forceinline__ void mma16816h(float* c, const uint32_t* a, const uint32_t* b) {
    asm volatile("mma.sync.aligned.m16n8k16.row.col.f32.f16.f16.f32 "
                 "{%0,%1,%2,%3}, {%4,%5,%6,%7}, {%8,%9}, {%0,%1,%2,%3};"
                 : "+f"(c[0]), "+f"(c[1]), "+f"(c[2]), "+f"(c[3])
                 : "r"(a[0]), "r"(a[1]), "r"(a[2]), "r"(a[3]),
                   "r"(b[0]), "r"(b[1]));
}

__device__ __forceinline__ uint32_t pk_hi(float a, float b) {
    return __byte_perm(__float_as_uint(a), __float_as_uint(b), 0x7632);
}
__device__ __forceinline__ uint32_t pk_lo(float a, float b) {
    float la = a - __uint_as_float(__float_as_uint(a) & 0xFFFF0000u);
    float lb = b - __uint_as_float(__float_as_uint(b) & 0xFFFF0000u);
    return __byte_perm(__float_as_uint(la), __float_as_uint(lb), 0x7632);
}

__device__ __forceinline__ void split_store(uint32_t hi_base, uint32_t lo_base,
                                            int row, int k4, float4 f) {
    uint32_t h01 = pk_hi(f.x, f.y), h23 = pk_hi(f.z, f.w);
    uint32_t l01 = pk_lo(f.x, f.y), l23 = pk_lo(f.z, f.w);
    int chunk = k4 >> 1, half = k4 & 1;
    uint32_t off = (uint32_t)(row * 64 + ((chunk ^ ((row >> 1) & 3)) << 4) + half * 8);
    asm volatile("st.shared.v2.b32 [%0], {%1,%2};" :: "r"(hi_base + off), "r"(h01), "r"(h23));
    asm volatile("st.shared.v2.b32 [%0], {%1,%2};" :: "r"(lo_base + off), "r"(l01), "r"(l23));
}

__device__ __forceinline__ void half_store(uint32_t base, int row, int k4, float4 f) {
    __half2 a = __floats2half2_rn(f.x, f.y);
    __half2 b = __floats2half2_rn(f.z, f.w);
    uint32_t h01 = *(uint32_t*)&a, h23 = *(uint32_t*)&b;
    int chunk = k4 >> 1, half = k4 & 1;
    uint32_t off = (uint32_t)(row * 64 + ((chunk ^ ((row >> 1) & 3)) << 4) + half * 8);
    asm volatile("st.shared.v2.b32 [%0], {%1,%2};" :: "r"(base + off), "r"(h01), "r"(h23));
}

__device__ __forceinline__ void half_split_store(uint32_t hi_base, uint32_t lo_base,
                                                 int row, int k4, float4 f) {
    __half2 h0 = __floats2half2_rn(f.x, f.y);
    __half2 h1 = __floats2half2_rn(f.z, f.w);
    float lx = f.x - __half2float(__low2half(h0));
    float ly = f.y - __half2float(__high2half(h0));
    float lz = f.z - __half2float(__low2half(h1));
    float lw = f.w - __half2float(__high2half(h1));
    __half2 l0 = __floats2half2_rn(lx, ly);
    __half2 l1 = __floats2half2_rn(lz, lw);
    uint32_t hh01 = *(uint32_t*)&h0, hh23 = *(uint32_t*)&h1;
    uint32_t ll01 = *(uint32_t*)&l0, ll23 = *(uint32_t*)&l1;
    int chunk = k4 >> 1, half = k4 & 1;
    uint32_t off = (uint32_t)(row * 64 + ((chunk ^ ((row >> 1) & 3)) << 4) + half * 8);
    asm volatile("st.shared.v2.b32 [%0], {%1,%2};" :: "r"(hi_base + off), "r"(hh01), "r"(hh23));
    asm volatile("st.shared.v2.b32 [%0], {%1,%2};" :: "r"(lo_base + off), "r"(ll01), "r"(ll23));
}

// ---------------- bf16 3-term GEMM body (validated since R4) --------------
template<int BN, bool ACCUM>
__device__ __forceinline__ void gemm_body(
    const float* __restrict__ A, int lda,
    const float* __restrict__ B, int ldb,
    float*       __restrict__ C, int ldc,
    int K, float alpha, int m0, int n0)
{
    constexpr int WN    = BN / 4;
    constexpr int NA    = WN / 8;
    constexpr int NB4   = BN / 32;
    constexpr int A_LO  = 8192;
    constexpr int B_HI  = 16384;
    constexpr int BLO_D = BN * 64;
    constexpr int STAGE = 16384 + BN * 128;

    extern __shared__ char smem[];
    const uint32_t sb0 = smem_u32(smem);

    const int tid = threadIdx.x, lane = tid & 31, wid = tid >> 5;
    const int wm = wid & 1, wn = wid >> 1;

    uint32_t offA[4][2], offB[NA / 2][2];
    #pragma unroll
    for (int am = 0; am < 4; am++)
        #pragma unroll
        for (int kh = 0; kh < 2; kh++) {
            int mrow  = wm * 64 + am * 16 + (lane & 7) + ((lane >> 3) & 1) * 8;
            int chunk = kh * 2 + ((lane >> 4) & 1);
            offA[am][kh] = (uint32_t)(mrow * 64 + ((chunk ^ ((mrow >> 1) & 3)) << 4));
        }
    #pragma unroll
    for (int p = 0; p < NA / 2; p++)
        #pragma unroll
        for (int kh = 0; kh < 2; kh++) {
            int nrow  = wn * WN + p * 16 + (lane & 7) + ((lane >> 4) & 1) * 8;
            int chunk = kh * 2 + ((lane >> 3) & 1);
            offB[p][kh] = (uint32_t)(B_HI + nrow * 64 + ((chunk ^ ((nrow >> 1) & 3)) << 4));
        }

    float acc[4][NA][4];
    #pragma unroll
    for (int i = 0; i < 4; i++)
        #pragma unroll
        for (int j = 0; j < NA; j++)
            #pragma unroll
            for (int e = 0; e < 4; e++) acc[i][j][e] = 0.0f;

    float4 pa[4], pb[NB4];
    auto LOADG = [&](int k0) {
        #pragma unroll
        for (int i = 0; i < 4; i++) {
            int idx = i * 256 + tid, row = idx >> 3, k4 = idx & 7;
            pa[i] = *(const float4*)&A[(long)(m0 + row) * lda + k0 + k4 * 4];
        }
        #pragma unroll
        for (int i = 0; i < NB4; i++) {
            int idx = i * 256 + tid, row = idx >> 3, k4 = idx & 7;
            pb[i] = *(const float4*)&B[(long)(n0 + row) * ldb + k0 + k4 * 4];
        }
    };
    auto STORES = [&](uint32_t base) {
        #pragma unroll
        for (int i = 0; i < 4; i++) {
            int idx = i * 256 + tid, row = idx >> 3, k4 = idx & 7;
            split_store(base, base + A_LO, row, k4, pa[i]);
        }
        #pragma unroll
        for (int i = 0; i < NB4; i++) {
            int idx = i * 256 + tid, row = idx >> 3, k4 = idx & 7;
            split_store(base + B_HI, base + B_HI + BLO_D, row, k4, pb[i]);
        }
    };

    const int nk = K >> 5;
    LOADG(0);
    STORES(sb0);
    __syncthreads();

    for (int t = 0; t < nk; t++) {
        const uint32_t sb = sb0 + (uint32_t)(t & 1) * STAGE;
        if (t + 1 < nk) LOADG((t + 1) * 32);

        #pragma unroll
        for (int kh = 0; kh < 2; kh++) {
            uint32_t ah[4][4], al[4][4];
            #pragma unroll
            for (int am = 0; am < 4; am++) {
                ldm4(ah[am], sb + offA[am][kh]);
                ldm4(al[am], sb + offA[am][kh] + A_LO);
            }
            uint32_t bh[NA / 2][4], bl[NA / 2][4];
            #pragma unroll
            for (int p = 0; p < NA / 2; p++) {
                ldm4(bh[p], sb + offB[p][kh]);
                ldm4(bl[p], sb + offB[p][kh] + BLO_D);
            }
            #pragma unroll
            for (int am = 0; am < 4; am++)
                #pragma unroll
                for (int na = 0; na < NA; na++) {
                    const uint32_t* bhp = &bh[na >> 1][(na & 1) * 2];
                    const uint32_t* blp = &bl[na >> 1][(na & 1) * 2];
                    mma16816(acc[am][na], ah[am], bhp);
                    mma16816(acc[am][na], ah[am], blp);
                    mma16816(acc[am][na], al[am], bhp);
                }
        }

        if (t + 1 < nk) STORES(sb0 + (uint32_t)((t & 1) ^ 1) * STAGE);
        __syncthreads();
    }

    #pragma unroll
    for (int am = 0; am < 4; am++)
        #pragma unroll
        for (int na = 0; na < NA; na++) {
            int row = m0 + wm * 64 + am * 16 + (lane >> 2);
            int col = n0 + wn * WN + na * 8 + (lane & 3) * 2;
            float* base0 = &C[(long)row * ldc + col];
            float* base1 = &C[(long)(row + 8) * ldc + col];
            float2 r0 = { alpha * acc[am][na][0], alpha * acc[am][na][1] };
            float2 r1 = { alpha * acc[am][na][2], alpha * acc[am][na][3] };
            if (ACCUM) {
                float2 o0 = *(float2*)base0, o1 = *(float2*)base1;
                r0.x += o0.x; r0.y += o0.y; r1.x += o1.x; r1.y += o1.y;
            }
            *(float2*)base0 = r0;
            *(float2*)base1 = r1;
        }
}

template<int BN, bool ACCUM>
__global__ void __launch_bounds__(256, 1)
mma_gemm(const float* __restrict__ A, int lda,
         const float* __restrict__ B, int ldb,
         float*       __restrict__ C, int ldc,
         int K, float alpha)
{
    gemm_body<BN, ACCUM>(A, lda, B, ldb, C, ldc, K, alpha,
                         blockIdx.x * 128, blockIdx.y * BN);
}

struct P3 {
    const float *B0, *B1, *B2;
    float *C0, *C1, *C2;
};

__global__ void __launch_bounds__(256, 1)
mma_gemm_multi(const float* __restrict__ A, int lda, P3 p,
               int ldb, int ldc, int K, float alpha)
{
    const int z = blockIdx.z;
    const float* B = (z == 0) ? p.B0 : (z == 1) ? p.B1 : p.B2;
    float*       C = (z == 0) ? p.C0 : (z == 1) ? p.C1 : p.C2;
    gemm_body<128, false>(A, lda, B, ldb, C, ldc, K, alpha,
                          blockIdx.x * 128, blockIdx.y * 128);
}

// ------------ fp16 2-term GEMM body (A hi/lo fp16, B single fp16) ---------
// EPI: 0 = store, 1 = accumulate into C.
template<int EPI>
__device__ __forceinline__ void gemm2t_body(
    const float* __restrict__ A, int lda,
    const float* __restrict__ B, int ldb,
    float*       __restrict__ C, int ldc,
    int K, int m0, int n0)
{
    constexpr int A_LO  = 8192;
    constexpr int B_OFF = 16384;
    constexpr int STAGE = 24576;

    extern __shared__ char smem[];
    const uint32_t sb0 = smem_u32(smem);

    const int tid = threadIdx.x, lane = tid & 31, wid = tid >> 5;
    const int wm = wid & 1, wn = wid >> 1;

    uint32_t offA[4][2], offB[2][2];
    #pragma unroll
    for (int am = 0; am < 4; am++)
        #pragma unroll
        for (int kh = 0; kh < 2; kh++) {
            int mrow  = wm * 64 + am * 16 + (lane & 7) + ((lane >> 3) & 1) * 8;
            int chunk = kh * 2 + ((lane >> 4) & 1);
            offA[am][kh] = (uint32_t)(mrow * 64 + ((chunk ^ ((mrow >> 1) & 3)) << 4));
        }
    #pragma unroll
    for (int p = 0; p < 2; p++)
        #pragma unroll
        for (int kh = 0; kh < 2; kh++) {
            int nrow  = wn * 32 + p * 16 + (lane & 7) + ((lane >> 4) & 1) * 8;
            int chunk = kh * 2 + ((lane >> 3) & 1);
            offB[p][kh] = (uint32_t)(B_OFF + nrow * 64 + ((chunk ^ ((nrow >> 1) & 3)) << 4));
        }

    float acc[4][4][4];
    #pragma unroll
    for (int i = 0; i < 4; i++)
        #pragma unroll
        for (int j = 0; j < 4; j++)
            #pragma unroll
            for (int e = 0; e < 4; e++) acc[i][j][e] = 0.0f;

    float4 pa[4], pb[4];
    auto LOADG = [&](int k0) {
        #pragma unroll
        for (int i = 0; i < 4; i++) {
            int idx = i * 256 + tid, row = idx >> 3, k4 = idx & 7;
            pa[i] = *(const float4*)&A[(long)(m0 + row) * lda + k0 + k4 * 4];
        }
        #pragma unroll
        for (int i = 0; i < 4; i++) {
            int idx = i * 256 + tid, row = idx >> 3, k4 = idx & 7;
            pb[i] = *(const float4*)&B[(long)(n0 + row) * ldb + k0 + k4 * 4];
        }
    };
    auto STORES = [&](uint32_t base) {
        #pragma unroll
        for (int i = 0; i < 4; i++) {
            int idx = i * 256 + tid, row = idx >> 3, k4 = idx & 7;
            half_split_store(base, base + A_LO, row, k4, pa[i]);
        }
        #pragma unroll
        for (int i = 0; i < 4; i++) {
            int idx = i * 256 + tid, row = idx >> 3, k4 = idx & 7;
            half_store(base + B_OFF, row, k4, pb[i]);
        }
    };

    const int nk = K >> 5;
    LOADG(0);
    STORES(sb0);
    __syncthreads();

    for (int t = 0; t < nk; t++) {
        const uint32_t sb = sb0 + (uint32_t)(t & 1) * STAGE;
        if (t + 1 < nk) LOADG((t + 1) * 32);

        #pragma unroll
        for (int kh = 0; kh < 2; kh++) {
            uint32_t ah[4][4], al[4][4];
            #pragma unroll
            for (int am = 0; am < 4; am++) {
                ldm4(ah[am], sb + offA[am][kh]);
                ldm4(al[am], sb + offA[am][kh] + A_LO);
            }
            uint32_t bh[2][4];
            #pragma unroll
            for (int p = 0; p < 2; p++)
                ldm4(bh[p], sb + offB[p][kh]);
            #pragma unroll
            for (int am = 0; am < 4; am++)
                #pragma unroll
                for (int na = 0; na < 4; na++) {
                    const uint32_t* bp = &bh[na >> 1][(na & 1) * 2];
                    mma16816h(acc[am][na], ah[am], bp);
                    mma16816h(acc[am][na], al[am], bp);
                }
        }

        if (t + 1 < nk) STORES(sb0 + (uint32_t)((t & 1) ^ 1) * STAGE);
        __syncthreads();
    }

    #pragma unroll
    for (int am = 0; am < 4; am++)
        #pragma unroll
        for (int na = 0; na < 4; na++) {
            int row = m0 + wm * 64 + am * 16 + (lane >> 2);
            int col = n0 + wn * 32 + na * 8 + (lane & 3) * 2;
            float* base0 = &C[(long)row * ldc + col];
            float* base1 = &C[(long)(row + 8) * ldc + col];
            float2 r0 = { acc[am][na][0], acc[am][na][1] };
            float2 r1 = { acc[am][na][2], acc[am][na][3] };
            if (EPI == 1) {
                float2 o0 = *(float2*)base0, o1 = *(float2*)base1;
                r0.x += o0.x; r0.y += o0.y; r1.x += o1.x; r1.y += o1.y;
            }
            *(float2*)base0 = r0;
            *(float2*)base1 = r1;
        }
}

// fused gate/up (z selects Wg/Wu), validated R14
__global__ void __launch_bounds__(256, 1)
mma_gemm_multi_2t(const float* __restrict__ A, int lda,
                  const float* __restrict__ B0g, const float* __restrict__ B1g,
                  float* __restrict__ C0g, float* __restrict__ C1g,
                  int ldb, int ldc, int K)
{
    const float* B = (blockIdx.z == 0) ? B0g : B1g;
    float*       C = (blockIdx.z == 0) ? C0g : C1g;
    gemm2t_body<0>(A, lda, B, ldb, C, ldc, K, blockIdx.x * 128, blockIdx.y * 128);
}

// Wd down-projection: h += gate @ Wd^T (2-term, accumulate)
__global__ void __launch_bounds__(256, 1)
mma_gemm_2t_acc(const float* __restrict__ A, int lda,
                const float* __restrict__ B, int ldb,
                float* __restrict__ C, int ldc, int K)
{
    gemm2t_body<1>(A, lda, B, ldb, C, ldc, K, blockIdx.x * 128, blockIdx.y * 128);
}

// ---------------- fp16 single-term GEMM (lm_head, validated R13) ----------
__global__ void __launch_bounds__(256, 1)
mma_gemm_h(const float* __restrict__ A, int lda,
           const float* __restrict__ B, int ldb,
           float*       __restrict__ C, int ldc,
           int K)
{
    constexpr int B_OFF = 8192;
    constexpr int STAGE = 16384;

    extern __shared__ char smem[];
    const uint32_t sb0 = smem_u32(smem);

    const int tid = threadIdx.x, lane = tid & 31, wid = tid >> 5;
    const int wm = wid & 1, wn = wid >> 1;
    const int m0 = blockIdx.x * 128;
    const int n0 = blockIdx.y * 128;

    uint32_t offA[4][2], offB[2][2];
    #pragma unroll
    for (int am = 0; am < 4; am++)
        #pragma unroll
        for (int kh = 0; kh < 2; kh++) {
            int mrow  = wm * 64 + am * 16 + (lane & 7) + ((lane >> 3) & 1) * 8;
            int chunk = kh * 2 + ((lane >> 4) & 1);
            offA[am][kh] = (uint32_t)(mrow * 64 + ((chunk ^ ((mrow >> 1) & 3)) << 4));
        }
    #pragma unroll
    for (int p = 0; p < 2; p++)
        #pragma unroll
        for (int kh = 0; kh < 2; kh++) {
            int nrow  = wn * 32 + p * 16 + (lane & 7) + ((lane >> 4) & 1) * 8;
            int chunk = kh * 2 + ((lane >> 3) & 1);
            offB[p][kh] = (uint32_t)(B_OFF + nrow * 64 + ((chunk ^ ((nrow >> 1) & 3)) << 4));
        }

    float acc[4][4][4];
    #pragma unroll
    for (int i = 0; i < 4; i++)
        #pragma unroll
        for (int j = 0; j < 4; j++)
            #pragma unroll
            for (int e = 0; e < 4; e++) acc[i][j][e] = 0.0f;

    float4 pa[4], pb[4];
    auto LOADG = [&](int k0) {
        #pragma unroll
        for (int i = 0; i < 4; i++) {
            int idx = i * 256 + tid, row = idx >> 3, k4 = idx & 7;
            pa[i] = *(const float4*)&A[(long)(m0 + row) * lda + k0 + k4 * 4];
        }
        #pragma unroll
        for (int i = 0; i < 4; i++) {
            int idx = i * 256 + tid, row = idx >> 3, k4 = idx & 7;
            pb[i] = *(const float4*)&B[(long)(n0 + row) * ldb + k0 + k4 * 4];
        }
    };
    auto STORES = [&](uint32_t base) {
        #pragma unroll
        for (int i = 0; i < 4; i++) {
            int idx = i * 256 + tid, row = idx >> 3, k4 = idx & 7;
            half_store(base, row, k4, pa[i]);
        }
        #pragma unroll
        for (int i = 0; i < 4; i++) {
            int idx = i * 256 + tid, row = idx >> 3, k4 = idx & 7;
            half_store(base + B_OFF, row, k4, pb[i]);
        }
    };

    const int nk = K >> 5;
    LOADG(0);
    STORES(sb0);
    __syncthreads();

    for (int t = 0; t < nk; t++) {
        const uint32_t sb = sb0 + (uint32_t)(t & 1) * STAGE;
        if (t + 1 < nk) LOADG((t + 1) * 32);

        #pragma unroll
        for (int kh = 0; kh < 2; kh++) {
            uint32_t ah[4][4];
            #pragma unroll
            for (int am = 0; am < 4; am++)
                ldm4(ah[am], sb + offA[am][kh]);
            uint32_t bh[2][4];
            #pragma unroll
            for (int p = 0; p < 2; p++)
                ldm4(bh[p], sb + offB[p][kh]);
            #pragma unroll
            for (int am = 0; am < 4; am++)
                #pragma unroll
                for (int na = 0; na < 4; na++)
                    mma16816h(acc[am][na], ah[am], &bh[na >> 1][(na & 1) * 2]);
        }

        if (t + 1 < nk) STORES(sb0 + (uint32_t)((t & 1) ^ 1) * STAGE);
        __syncthreads();
    }

    #pragma unroll
    for (int am = 0; am < 4; am++)
        #pragma unroll
        for (int na = 0; na < 4; na++) {
            int row = m0 + wm * 64 + am * 16 + (lane >> 2);
            int col = n0 + wn * 32 + na * 8 + (lane & 3) * 2;
            float2 r0 = { acc[am][na][0], acc[am][na][1] };
            float2 r1 = { acc[am][na][2], acc[am][na][3] };
            *(float2*)&C[(long)row * ldc + col] = r0;
            *(float2*)&C[(long)(row + 8) * ldc + col] = r1;
        }
}

// ================= flash attention, s-tile 64, 2 CTAs/SM (validated R12) ==
#define FA_QH  0
#define FA_QL  16384
#define FA_KH  32768
#define FA_KL  40960
#define FA_VH  49152
#define FA_VL  57344
#define FA_PH  65536
#define FA_PL  81920
#define FA_SMX 98304
#define FA_SSM 100352
#define FA_BYTES 102400

__global__ void __launch_bounds__(256, 2)
flash_attn(const float* __restrict__ q, const float* __restrict__ k,
           const float* __restrict__ vt, float* __restrict__ y)
{
    extern __shared__ char smem[];
    const uint32_t sb = smem_u32(smem);
    float* smx = (float*)(smem + FA_SMX);
    float* ssm = (float*)(smem + FA_SSM);

    const int tid = threadIdx.x, lane = tid & 31, wid = tid >> 5;
    const int wm = wid & 1, wn = wid >> 1;
    const int bh = blockIdx.z, b = bh >> 4, hh = bh & 15;
    const int q0 = blockIdx.x * 128;

    uint32_t offA[4][2];
    #pragma unroll
    for (int am = 0; am < 4; am++)
        #pragma unroll
        for (int khi = 0; khi < 2; khi++) {
            int arow  = wm * 64 + am * 16 + (lane & 7) + ((lane >> 3) & 1) * 8;
            int chunk = khi * 2 + ((lane >> 4) & 1);
            offA[am][khi] = (uint32_t)(arow * 64 + ((chunk ^ ((arow >> 1) & 3)) << 4));
        }
    uint32_t offK[2], offV[2];
    #pragma unroll
    for (int khi = 0; khi < 2; khi++) {
        int brow  = wn * 16 + (lane & 7) + ((lane >> 4) & 1) * 8;
        int chunk = khi * 2 + ((lane >> 3) & 1);
        uint32_t o = (uint32_t)(brow * 64 + ((chunk ^ ((brow >> 1) & 3)) << 4));
        offK[khi] = o;
        offV[khi] = o;
    }

    #pragma unroll
    for (int i = 0; i < 8; i++) {
        int idx = i * 256 + tid, row = idx >> 4, k4 = idx & 15;
        float4 f = *(const float4*)&q[(long)(b * SEQ + q0 + row) * DIMN + hh * 64 + k4 * 4];
        f.x *= 0.125f; f.y *= 0.125f; f.z *= 0.125f; f.w *= 0.125f;
        split_store(sb + FA_QH + (k4 >> 3) * 8192, sb + FA_QL + (k4 >> 3) * 8192,
                    row, k4 & 7, f);
    }

    float o[4][2][4];
    float m_r[4][2], l_r[4][2];
    #pragma unroll
    for (int am = 0; am < 4; am++) {
        m_r[am][0] = m_r[am][1] = -1e30f;
        l_r[am][0] = l_r[am][1] = 0.0f;
        #pragma unroll
        for (int na = 0; na < 2; na++)
            #pragma unroll
            for (int e = 0; e < 4; e++) o[am][na][e] = 0.0f;
    }

    const int rb = wm * 64 + (lane >> 2);

    for (int s0 = 0; s0 < SEQ; s0 += 64) {
        __syncthreads();

        #pragma unroll
        for (int i = 0; i < 4; i++) {
            int idx = i * 256 + tid, row = idx >> 4, k4 = idx & 15;
            float4 f = *(const float4*)&k[(long)(b * SEQ + s0 + row) * DIMN + hh * 64 + k4 * 4];
            split_store(sb + FA_KH + (k4 >> 3) * 4096, sb + FA_KL + (k4 >> 3) * 4096,
                        row, k4 & 7, f);
        }
        #pragma unroll
        for (int i = 0; i < 4; i++) {
            int idx = i * 256 + tid, row = idx >> 4, s4 = idx & 15;
            float4 f = *(const float4*)&vt[((long)bh * 64 + row) * SEQ + s0 + s4 * 4];
            split_store(sb + FA_VH + (s4 >> 3) * 4096, sb + FA_VL + (s4 >> 3) * 4096,
                        row, s4 & 7, f);
        }
        __syncthreads();

        float sf[4][2][4];
        #pragma unroll
        for (int am = 0; am < 4; am++)
            #pragma unroll
            for (int na = 0; na < 2; na++)
                #pragma unroll
                for (int e = 0; e < 4; e++) sf[am][na][e] = 0.0f;

        #pragma unroll
        for (int kb = 0; kb < 2; kb++)
            #pragma unroll
            for (int khi = 0; khi < 2; khi++) {
                uint32_t ah[4][4], al[4][4];
                #pragma unroll
                for (int am = 0; am < 4; am++) {
                    ldm4(ah[am], sb + FA_QH + kb * 8192 + offA[am][khi]);
                    ldm4(al[am], sb + FA_QL + kb * 8192 + offA[am][khi]);
                }
                uint32_t bhf[4], blf[4];
                ldm4(bhf, sb + FA_KH + kb * 4096 + offK[khi]);
                ldm4(blf, sb + FA_KL + kb * 4096 + offK[khi]);
                #pragma unroll
                for (int am = 0; am < 4; am++)
                    #pragma unroll
                    for (int na = 0; na < 2; na++) {
                        const uint32_t* bhp = &bhf[na * 2];
                        const uint32_t* blp = &blf[na * 2];
                        mma16816(sf[am][na], ah[am], bhp);
                        mma16816(sf[am][na], ah[am], blp);
                        mma16816(sf[am][na], al[am], bhp);
                    }
            }

        #pragma unroll
        for (int am = 0; am < 4; am++) {
            float v0 = -1e30f, v1 = -1e30f;
            #pragma unroll
            for (int na = 0; na < 2; na++) {
                v0 = fmaxf(v0, fmaxf(sf[am][na][0], sf[am][na][1]));
                v1 = fmaxf(v1, fmaxf(sf[am][na][2], sf[am][na][3]));
            }
            v0 = fmaxf(v0, __shfl_xor_sync(0xFFFFFFFFu, v0, 1));
            v0 = fmaxf(v0, __shfl_xor_sync(0xFFFFFFFFu, v0, 2));
            v1 = fmaxf(v1, __shfl_xor_sync(0xFFFFFFFFu, v1, 1));
            v1 = fmaxf(v1, __shfl_xor_sync(0xFFFFFFFFu, v1, 2));
            if ((lane & 3) == 0) {
                smx[(rb + am * 16) * 4 + wn] = v0;
                smx[(rb + am * 16 + 8) * 4 + wn] = v1;
            }
        }
        __syncthreads();

        float csc[4][2];
        #pragma unroll
        for (int am = 0; am < 4; am++) {
            int r0 = rb + am * 16, r1 = r0 + 8;
            float tm0 = fmaxf(fmaxf(smx[r0 * 4 + 0], smx[r0 * 4 + 1]),
                              fmaxf(smx[r0 * 4 + 2], smx[r0 * 4 + 3]));
            float tm1 = fmaxf(fmaxf(smx[r1 * 4 + 0], smx[r1 * 4 + 1]),
                              fmaxf(smx[r1 * 4 + 2], smx[r1 * 4 + 3]));
            float mn0 = fmaxf(m_r[am][0], tm0);
            float mn1 = fmaxf(m_r[am][1], tm1);
            csc[am][0] = __expf(m_r[am][0] - mn0);
            csc[am][1] = __expf(m_r[am][1] - mn1);
            m_r[am][0] = mn0; m_r[am][1] = mn1;

            float rs0 = 0.0f, rs1 = 0.0f;
            #pragma unroll
            for (int na = 0; na < 2; na++) {
                float p0 = __expf(sf[am][na][0] - mn0);
                float p1 = __expf(sf[am][na][1] - mn0);
                float p2 = __expf(sf[am][na][2] - mn1);
                float p3 = __expf(sf[am][na][3] - mn1);
                rs0 += p0 + p1; rs1 += p2 + p3;
                int c0col = wn * 16 + na * 8 + (lane & 3) * 2;
                int kb = c0col >> 5, cc = c0col & 31;
                uint32_t o0 = (uint32_t)(kb * 8192 + r0 * 64 +
                              (((cc >> 3) ^ ((r0 >> 1) & 3)) << 4) +
                              ((cc >> 2) & 1) * 8 + (cc & 3) * 2);
                uint32_t o1 = (uint32_t)(kb * 8192 + r1 * 64 +
                              (((cc >> 3) ^ ((r1 >> 1) & 3)) << 4) +
                              ((cc >> 2) & 1) * 8 + (cc & 3) * 2);
                *(uint32_t*)(smem + FA_PH + o0) = pk_hi(p0, p1);
                *(uint32_t*)(smem + FA_PL + o0) = pk_lo(p0, p1);
                *(uint32_t*)(smem + FA_PH + o1) = pk_hi(p2, p3);
                *(uint32_t*)(smem + FA_PL + o1) = pk_lo(p2, p3);
            }
            rs0 += __shfl_xor_sync(0xFFFFFFFFu, rs0, 1);
            rs0 += __shfl_xor_sync(0xFFFFFFFFu, rs0, 2);
            rs1 += __shfl_xor_sync(0xFFFFFFFFu, rs1, 1);
            rs1 += __shfl_xor_sync(0xFFFFFFFFu, rs1, 2);
            if ((lane & 3) == 0) {
                ssm[r0 * 4 + wn] = rs0;
                ssm[r1 * 4 + wn] = rs1;
            }
        }
        __syncthreads();

        #pragma unroll
        for (int am = 0; am < 4; am++) {
            int r0 = rb + am * 16, r1 = r0 + 8;
            float s0s = ssm[r0 * 4 + 0] + ssm[r0 * 4 + 1] + ssm[r0 * 4 + 2] + ssm[r0 * 4 + 3];
            float s1s = ssm[r1 * 4 + 0] + ssm[r1 * 4 + 1] + ssm[r1 * 4 + 2] + ssm[r1 * 4 + 3];
            l_r[am][0] = l_r[am][0] * csc[am][0] + s0s;
            l_r[am][1] = l_r[am][1] * csc[am][1] + s1s;
            #pragma unroll
            for (int na = 0; na < 2; na++) {
                o[am][na][0] *= csc[am][0]; o[am][na][1] *= csc[am][0];
                o[am][na][2] *= csc[am][1]; o[am][na][3] *= csc[am][1];
            }
        }

        #pragma unroll
        for (int kb = 0; kb < 2; kb++)
            #pragma unroll
            for (int khi = 0; khi < 2; khi++) {
                uint32_t ah[4][4], al[4][4];
                #pragma unroll
                for (int am = 0; am < 4; am++) {
                    ldm4(ah[am], sb + FA_PH + kb * 8192 + offA[am][khi]);
                    ldm4(al[am], sb + FA_PL + kb * 8192 + offA[am][khi]);
                }
                uint32_t bhf[4], blf[4];
                ldm4(bhf, sb + FA_VH + kb * 4096 + offV[khi]);
                ldm4(blf, sb + FA_VL + kb * 4096 + offV[khi]);
                #pragma unroll
                for (int am = 0; am < 4; am++)
                    #pragma unroll
                    for (int na = 0; na < 2; na++) {
                        const uint32_t* bhp = &bhf[na * 2];
                        const uint32_t* blp = &blf[na * 2];
                        mma16816(o[am][na], ah[am], bhp);
                        mma16816(o[am][na], ah[am], blp);
                        mma16816(o[am][na], al[am], bhp);
                    }
            }
    }

    #pragma unroll
    for (int am = 0; am < 4; am++) {
        float inv0 = 1.0f / l_r[am][0];
        float inv1 = 1.0f / l_r[am][1];
        long tok0 = (long)(b * SEQ + q0 + wm * 64 + am * 16 + (lane >> 2));
        #pragma unroll
        for (int na = 0; na < 2; na++) {
            int col = hh * 64 + wn * 16 + na * 8 + (lane & 3) * 2;
            float2 r0 = { o[am][na][0] * inv0, o[am][na][1] * inv0 };
            float2 r1 = { o[am][na][2] * inv1, o[am][na][3] * inv1 };
            *(float2*)&y[tok0 * DIMN + col] = r0;
            *(float2*)&y[(tok0 + 8) * DIMN + col] = r1;
        }
    }
}

// ---------------- elementwise kernels ----------------
__global__ void embed_kernel(const int* __restrict__ tokens,
                             const float* __restrict__ embed,
                             float* __restrict__ h)
{
    int row = blockIdx.x;
    int tok = tokens[row];
    ((float4*)(h + (long)row * DIMN))[threadIdx.x] =
        ((const float4*)(embed + (long)tok * DIMN))[threadIdx.x];
}

__global__ void rmsnorm_kernel(const float* __restrict__ x,
                               const float* __restrict__ w,
                               float* __restrict__ out)
{
    int row = blockIdx.x;
    float4 v = ((const float4*)(x + (long)row * DIMN))[threadIdx.x];
    float ss = v.x*v.x + v.y*v.y + v.z*v.z + v.w*v.w;
    __shared__ float red[8];
    #pragma unroll
    for (int o = 16; o > 0; o >>= 1) ss += __shfl_xor_sync(0xFFFFFFFFu, ss, o);
    if ((threadIdx.x & 31) == 0) red[threadIdx.x >> 5] = ss;
    __syncthreads();
    if (threadIdx.x < 8) {
        float s = red[threadIdx.x];
        #pragma unroll
        for (int o = 4; o > 0; o >>= 1) s += __shfl_xor_sync(0xFFu, s, o);
        if (threadIdx.x == 0) red[0] = s;
    }
    __syncthreads();
    float scale = rsqrtf(red[0] * (1.0f / DIMN) + EPS);
    float4 wv = ((const float4*)w)[threadIdx.x];
    float4 o4 = { v.x*scale*wv.x, v.y*scale*wv.y, v.z*scale*wv.z, v.w*scale*wv.w };
    ((float4*)(out + (long)row * DIMN))[threadIdx.x] = o4;
}

__global__ void silu_mul_kernel(float4* __restrict__ g, const float4* __restrict__ u)
{
    long i = (long)blockIdx.x * blockDim.x + threadIdx.x;
    float4 gv = g[i], uv = u[i];
    gv.x = gv.x / (1.0f + __expf(-gv.x)) * uv.x;
    gv.y = gv.y / (1.0f + __expf(-gv.y)) * uv.y;
    gv.z = gv.z / (1.0f + __expf(-gv.z)) * uv.z;
    gv.w = gv.w / (1.0f + __expf(-gv.w)) * uv.w;
    g[i] = gv;
}

// vt[(b*H+h)][d][s] = v[b*SEQ+s][h*64+d]
__global__ void transpose_v_kernel(const float* __restrict__ v, float* __restrict__ vt)
{
    __shared__ float t[32][33];
    int bh = blockIdx.z, b = bh >> 4, hh = bh & 15;
    int s0 = blockIdx.x * 32, d0 = blockIdx.y * 32;
    int tx = threadIdx.x, ty = threadIdx.y;    // 32 x 8
    #pragma unroll
    for (int j = 0; j < 32; j += 8)
        t[ty + j][tx] = v[(long)(b * SEQ + s0 + ty + j) * DIMN + hh * HEAD_DIM + d0 + tx];
    __syncthreads();
    #pragma unroll
    for (int j = 0; j < 32; j += 8)
        vt[((long)bh * HEAD_DIM + d0 + ty + j) * SEQ + s0 + tx] = t[tx][ty + j];
}

// ---------------- launcher ----------------
extern "C" void kernel_launch(void* const* d_in, const int* in_sizes, int n_in,
                              void* d_out, int out_size)
{
    const int*   tokens  = (const int*)  d_in[0];
    const float* embed   = (const float*)d_in[1];
    const float* Wq      = (const float*)d_in[2];
    const float* Wk      = (const float*)d_in[3];
    const float* Wv      = (const float*)d_in[4];
    const float* Wo      = (const float*)d_in[5];
    const float* Wg      = (const float*)d_in[6];
    const float* Wu      = (const float*)d_in[7];
    const float* Wd      = (const float*)d_in[8];
    const float* ln1     = (const float*)d_in[9];
    const float* ln2     = (const float*)d_in[10];
    const float* norm_w  = (const float*)d_in[11];
    const float* lm_head = (const float*)d_in[12];
    float* out = (float*)d_out;

    float *h, *x, *q, *k, *v, *vt, *y, *gate, *up;
    cudaGetSymbolAddress((void**)&h,    g_h);
    cudaGetSymbolAddress((void**)&x,    g_x);
    cudaGetSymbolAddress((void**)&q,    g_q);
    cudaGetSymbolAddress((void**)&k,    g_k);
    cudaGetSymbolAddress((void**)&v,    g_v);
    cudaGetSymbolAddress((void**)&vt,   g_vt);
    cudaGetSymbolAddress((void**)&y,    g_y);
    cudaGetSymbolAddress((void**)&gate, g_gate);
    cudaGetSymbolAddress((void**)&up,   g_up);

    const int DYN128 = 2 * (16384 + 128 * 128);   // 65536
    const int DYNH   = 2 * 16384;                 // 32768
    const int DYN2T  = 2 * 24576;                 // 49152
    cudaFuncSetAttribute(mma_gemm<128, false>, cudaFuncAttributeMaxDynamicSharedMemorySize, DYN128);
    cudaFuncSetAttribute(mma_gemm<128, true>,  cudaFuncAttributeMaxDynamicSharedMemorySize, DYN128);
    cudaFuncSetAttribute(mma_gemm_multi,       cudaFuncAttributeMaxDynamicSharedMemorySize, DYN128);
    cudaFuncSetAttribute(mma_gemm_multi_2t,    cudaFuncAttributeMaxDynamicSharedMemorySize, DYN2T);
    cudaFuncSetAttribute(mma_gemm_2t_acc,      cudaFuncAttributeMaxDynamicSharedMemorySize, DYN2T);
    cudaFuncSetAttribute(mma_gemm_h,           cudaFuncAttributeMaxDynamicSharedMemorySize, DYNH);
    cudaFuncSetAttribute(flash_attn, cudaFuncAttributeMaxDynamicSharedMemorySize, FA_BYTES);

    embed_kernel<<<MTOK, 256>>>(tokens, embed, h);

    dim3 gQKV (MTOK / 128, DIMN / 128, 3);
    dim3 gGU  (MTOK / 128, HIDDEN / 128, 2);
    dim3 gProj(MTOK / 128, DIMN / 128, 1);
    dim3 gHead(MTOK / 128, VOCAB / 128, 1);
    dim3 gFa  (SEQ / 128, 1, BATCH * HEADS);
    dim3 gTr  (SEQ / 32, HEAD_DIM / 32, BATCH * HEADS);

    for (int l = 0; l < LAYERS; l++) {
        const float* wq = Wq + (long)l * DIMN * DIMN;
        const float* wk = Wk + (long)l * DIMN * DIMN;
        const float* wv = Wv + (long)l * DIMN * DIMN;
        const float* wo = Wo + (long)l * DIMN * DIMN;
        const float* wg = Wg + (long)l * HIDDEN * DIMN;
        const float* wu = Wu + (long)l * HIDDEN * DIMN;
        const float* wd = Wd + (long)l * DIMN * HIDDEN;

        rmsnorm_kernel<<<MTOK, 256>>>(h, ln1 + (long)l * DIMN, x);

        {
            P3 p = { wq, wk, wv, q, k, v };
            mma_gemm_multi<<<gQKV, 256, DYN128>>>(x, DIMN, p, DIMN, DIMN, DIMN, 1.0f);
        }

        transpose_v_kernel<<<gTr, dim3(32, 8)>>>(v, vt);
        flash_attn<<<gFa, 256, FA_BYTES>>>(q, k, vt, y);

        // h += y @ Wo^T   (3-term bf16: attention path stays high precision)
        mma_gemm<128, true><<<gProj, 256, DYN128>>>(y, DIMN, wo, DIMN,
                                                    h, DIMN, DIMN, 1.0f);

        rmsnorm_kernel<<<MTOK, 256>>>(h, ln2 + (long)l * DIMN, x);

        // fused gate,up = x @ {Wg,Wu}^T — fp16 2-term
        mma_gemm_multi_2t<<<gGU, 256, DYN2T>>>(x, DIMN, wg, wu, gate, up,
                                               DIMN, HIDDEN, DIMN);

        silu_mul_kernel<<<(MTOK * (long)HIDDEN / 4) / 256, 256>>>((float4*)gate, (const float4*)up);

        // h += gate @ Wd^T — fp16 2-term accumulate
        mma_gemm_2t_acc<<<gProj, 256, DYN2T>>>(gate, HIDDEN, wd, HIDDEN,
                                               h, DIMN, HIDDEN);
    }

    rmsnorm_kernel<<<MTOK, 256>>>(h, norm_w, x);
    mma_gemm_h<<<gHead, 256, DYNH>>>(x, DIMN, lm_head, DIMN, out, VOCAB, DIMN);
}

// round 16
// speedup vs baseline: 1.4082x; 1.0042x over previous
#include <cuda_runtime.h>
#include <cuda_fp16.h>
#include <math.h>
#include <stdint.h>

// ---------------- problem constants ----------------
#define DIMN     1024
#define HEADS    16
#define HEAD_DIM 64
#define LAYERS   4
#define HIDDEN   4096
#define VOCAB    32000
#define BATCH    2
#define SEQ      1024
#define MTOK     (BATCH*SEQ)
#define EPS      1e-6f

// ---------------- scratch ----------------
__device__ float g_h   [MTOK*DIMN];
__device__ float g_x   [MTOK*DIMN];
__device__ float g_q   [MTOK*DIMN];
__device__ float g_k   [MTOK*DIMN];
__device__ float g_v   [MTOK*DIMN];
__device__ float g_vt  [MTOK*DIMN];
__device__ float g_y   [MTOK*DIMN];
__device__ float g_gate[MTOK*HIDDEN];
__device__ float g_up  [MTOK*HIDDEN];

// ---------------- PTX helpers ----------------
__device__ __forceinline__ uint32_t smem_u32(const void* p) {
    uint32_t a;
    asm("{ .reg .u64 t; cvta.to.shared.u64 t, %1; cvt.u32.u64 %0, t; }"
        : "=r"(a) : "l"(p));
    return a;
}

__device__ __forceinline__ void ldm4(uint32_t* r, uint32_t addr) {
    asm volatile("ldmatrix.sync.aligned.m8n8.x4.shared.b16 {%0,%1,%2,%3}, [%4];"
                 : "=r"(r[0]), "=r"(r[1]), "=r"(r[2]), "=r"(r[3]) : "r"(addr));
}

__device__ __forceinline__ void mma16816(float* c, const uint32_t* a, const uint32_t* b) {
    asm volatile("mma.sync.aligned.m16n8k16.row.col.f32.bf16.bf16.f32 "
                 "{%0,%1,%2,%3}, {%4,%5,%6,%7}, {%8,%9}, {%0,%1,%2,%3};"
                 : "+f"(c[0]), "+f"(c[1]), "+f"(c[2]), "+f"(c[3])
                 : "r"(a[0]), "r"(a[1]), "r"(a[2]), "r"(a[3]),
                   "r"(b[0]), "r"(b[1]));
}

__device__ __forceinline__ void mma16816h(float* c, const uint32_t* a, const uint32_t* b) {
    asm volatile("mma.sync.aligned.m16n8k16.row.col.f32.f16.f16.f32 "
                 "{%0,%1,%2,%3}, {%4,%5,%6,%7}, {%8,%9}, {%0,%1,%2,%3};"
                 : "+f"(c[0]), "+f"(c[1]), "+f"(c[2]), "+f"(c[3])
                 : "r"(a[0]), "r"(a[1]), "r"(a[2]), "r"(a[3]),
                   "r"(b[0]), "r"(b[1]));
}

__device__ __forceinline__ uint32_t pk_hi(float a, float b) {
    return __byte_perm(__float_as_uint(a), __float_as_uint(b), 0x7632);
}
__device__ __forceinline__ uint32_t pk_lo(float a, float b) {
    float la = a - __uint_as_float(__float_as_uint(a) & 0xFFFF0000u);
    float lb = b - __uint_as_float(__float_as_uint(b) & 0xFFFF0000u);
    return __byte_perm(__float_as_uint(la), __float_as_uint(lb), 0x7632);
}

__device__ __forceinline__ void split_store(uint32_t hi_base, uint32_t lo_base,
                                            int row, int k4, float4 f) {
    uint32_t h01 = pk_hi(f.x, f.y), h23 = pk_hi(f.z, f.w);
    uint32_t l01 = pk_lo(f.x, f.y), l23 = pk_lo(f.z, f.w);
    int chunk = k4 >> 1, half = k4 & 1;
    uint32_t off = (uint32_t)(row * 64 + ((chunk ^ ((row >> 1) & 3)) << 4) + half * 8);
    asm volatile("st.shared.v2.b32 [%0], {%1,%2};" :: "r"(hi_base + off), "r"(h01), "r"(h23));
    asm volatile("st.shared.v2.b32 [%0], {%1,%2};" :: "r"(lo_base + off), "r"(l01), "r"(l23));
}

__device__ __forceinline__ void half_store(uint32_t base, int row, int k4, float4 f) {
    __half2 a = __floats2half2_rn(f.x, f.y);
    __half2 b = __floats2half2_rn(f.z, f.w);
    uint32_t h01 = *(uint32_t*)&a, h23 = *(uint32_t*)&b;
    int chunk = k4 >> 1, half = k4 & 1;
    uint32_t off = (uint32_t)(row * 64 + ((chunk ^ ((row >> 1) & 3)) << 4) + half * 8);
    asm volatile("st.shared.v2.b32 [%0], {%1,%2};" :: "r"(base + off), "r"(h01), "r"(h23));
}

__device__ __forceinline__ void half_split_store(uint32_t hi_base, uint32_t lo_base,
                                                 int row, int k4, float4 f) {
    __half2 h0 = __floats2half2_rn(f.x, f.y);
    __half2 h1 = __floats2half2_rn(f.z, f.w);
    float lx = f.x - __half2float(__low2half(h0));
    float ly = f.y - __half2float(__high2half(h0));
    float lz = f.z - __half2float(__low2half(h1));
    float lw = f.w - __half2float(__high2half(h1));
    __half2 l0 = __floats2half2_rn(lx, ly);
    __half2 l1 = __floats2half2_rn(lz, lw);
    uint32_t hh01 = *(uint32_t*)&h0, hh23 = *(uint32_t*)&h1;
    uint32_t ll01 = *(uint32_t*)&l0, ll23 = *(uint32_t*)&l1;
    int chunk = k4 >> 1, half = k4 & 1;
    uint32_t off = (uint32_t)(row * 64 + ((chunk ^ ((row >> 1) & 3)) << 4) + half * 8);
    asm volatile("st.shared.v2.b32 [%0], {%1,%2};" :: "r"(hi_base + off), "r"(hh01), "r"(hh23));
    asm volatile("st.shared.v2.b32 [%0], {%1,%2};" :: "r"(lo_base + off), "r"(ll01), "r"(ll23));
}

// ---------------- bf16 3-term GEMM body (validated since R4) --------------
template<int BN, bool ACCUM>
__device__ __forceinline__ void gemm_body(
    const float* __restrict__ A, int lda,
    const float* __restrict__ B, int ldb,
    float*       __restrict__ C, int ldc,
    int K, float alpha, int m0, int n0)
{
    constexpr int WN    = BN / 4;
    constexpr int NA    = WN / 8;
    constexpr int NB4   = BN / 32;
    constexpr int A_LO  = 8192;
    constexpr int B_HI  = 16384;
    constexpr int BLO_D = BN * 64;
    constexpr int STAGE = 16384 + BN * 128;

    extern __shared__ char smem[];
    const uint32_t sb0 = smem_u32(smem);

    const int tid = threadIdx.x, lane = tid & 31, wid = tid >> 5;
    const int wm = wid & 1, wn = wid >> 1;

    uint32_t offA[4][2], offB[NA / 2][2];
    #pragma unroll
    for (int am = 0; am < 4; am++)
        #pragma unroll
        for (int kh = 0; kh < 2; kh++) {
            int mrow  = wm * 64 + am * 16 + (lane & 7) + ((lane >> 3) & 1) * 8;
            int chunk = kh * 2 + ((lane >> 4) & 1);
            offA[am][kh] = (uint32_t)(mrow * 64 + ((chunk ^ ((mrow >> 1) & 3)) << 4));
        }
    #pragma unroll
    for (int p = 0; p < NA / 2; p++)
        #pragma unroll
        for (int kh = 0; kh < 2; kh++) {
            int nrow  = wn * WN + p * 16 + (lane & 7) + ((lane >> 4) & 1) * 8;
            int chunk = kh * 2 + ((lane >> 3) & 1);
            offB[p][kh] = (uint32_t)(B_HI + nrow * 64 + ((chunk ^ ((nrow >> 1) & 3)) << 4));
        }

    float acc[4][NA][4];
    #pragma unroll
    for (int i = 0; i < 4; i++)
        #pragma unroll
        for (int j = 0; j < NA; j++)
            #pragma unroll
            for (int e = 0; e < 4; e++) acc[i][j][e] = 0.0f;

    float4 pa[4], pb[NB4];
    auto LOADG = [&](int k0) {
        #pragma unroll
        for (int i = 0; i < 4; i++) {
            int idx = i * 256 + tid, row = idx >> 3, k4 = idx & 7;
            pa[i] = *(const float4*)&A[(long)(m0 + row) * lda + k0 + k4 * 4];
        }
        #pragma unroll
        for (int i = 0; i < NB4; i++) {
            int idx = i * 256 + tid, row = idx >> 3, k4 = idx & 7;
            pb[i] = *(const float4*)&B[(long)(n0 + row) * ldb + k0 + k4 * 4];
        }
    };
    auto STORES = [&](uint32_t base) {
        #pragma unroll
        for (int i = 0; i < 4; i++) {
            int idx = i * 256 + tid, row = idx >> 3, k4 = idx & 7;
            split_store(base, base + A_LO, row, k4, pa[i]);
        }
        #pragma unroll
        for (int i = 0; i < NB4; i++) {
            int idx = i * 256 + tid, row = idx >> 3, k4 = idx & 7;
            split_store(base + B_HI, base + B_HI + BLO_D, row, k4, pb[i]);
        }
    };

    const int nk = K >> 5;
    LOADG(0);
    STORES(sb0);
    __syncthreads();

    for (int t = 0; t < nk; t++) {
        const uint32_t sb = sb0 + (uint32_t)(t & 1) * STAGE;
        if (t + 1 < nk) LOADG((t + 1) * 32);

        #pragma unroll
        for (int kh = 0; kh < 2; kh++) {
            uint32_t ah[4][4], al[4][4];
            #pragma unroll
            for (int am = 0; am < 4; am++) {
                ldm4(ah[am], sb + offA[am][kh]);
                ldm4(al[am], sb + offA[am][kh] + A_LO);
            }
            uint32_t bh[NA / 2][4], bl[NA / 2][4];
            #pragma unroll
            for (int p = 0; p < NA / 2; p++) {
                ldm4(bh[p], sb + offB[p][kh]);
                ldm4(bl[p], sb + offB[p][kh] + BLO_D);
            }
            #pragma unroll
            for (int am = 0; am < 4; am++)
                #pragma unroll
                for (int na = 0; na < NA; na++) {
                    const uint32_t* bhp = &bh[na >> 1][(na & 1) * 2];
                    const uint32_t* blp = &bl[na >> 1][(na & 1) * 2];
                    mma16816(acc[am][na], ah[am], bhp);
                    mma16816(acc[am][na], ah[am], blp);
                    mma16816(acc[am][na], al[am], bhp);
                }
        }

        if (t + 1 < nk) STORES(sb0 + (uint32_t)((t & 1) ^ 1) * STAGE);
        __syncthreads();
    }

    #pragma unroll
    for (int am = 0; am < 4; am++)
        #pragma unroll
        for (int na = 0; na < NA; na++) {
            int row = m0 + wm * 64 + am * 16 + (lane >> 2);
            int col = n0 + wn * WN + na * 8 + (lane & 3) * 2;
            float* base0 = &C[(long)row * ldc + col];
            float* base1 = &C[(long)(row + 8) * ldc + col];
            float2 r0 = { alpha * acc[am][na][0], alpha * acc[am][na][1] };
            float2 r1 = { alpha * acc[am][na][2], alpha * acc[am][na][3] };
            if (ACCUM) {
                float2 o0 = *(float2*)base0, o1 = *(float2*)base1;
                r0.x += o0.x; r0.y += o0.y; r1.x += o1.x; r1.y += o1.y;
            }
            *(float2*)base0 = r0;
            *(float2*)base1 = r1;
        }
}

template<int BN, bool ACCUM>
__global__ void __launch_bounds__(256, 1)
mma_gemm(const float* __restrict__ A, int lda,
         const float* __restrict__ B, int ldb,
         float*       __restrict__ C, int ldc,
         int K, float alpha)
{
    gemm_body<BN, ACCUM>(A, lda, B, ldb, C, ldc, K, alpha,
                         blockIdx.x * 128, blockIdx.y * BN);
}

struct P3 {
    const float *B0, *B1, *B2;
    float *C0, *C1, *C2;
};

__global__ void __launch_bounds__(256, 1)
mma_gemm_multi(const float* __restrict__ A, int lda, P3 p,
               int ldb, int ldc, int K, float alpha)
{
    const int z = blockIdx.z;
    const float* B = (z == 0) ? p.B0 : (z == 1) ? p.B1 : p.B2;
    float*       C = (z == 0) ? p.C0 : (z == 1) ? p.C1 : p.C2;
    gemm_body<128, false>(A, lda, B, ldb, C, ldc, K, alpha,
                          blockIdx.x * 128, blockIdx.y * 128);
}

// ------------ fp16 2-term GEMM body (A hi/lo fp16, B single fp16) ---------
// EPI: 0 = store, 1 = accumulate into C.
template<int EPI>
__device__ __forceinline__ void gemm2t_body(
    const float* __restrict__ A, int lda,
    const float* __restrict__ B, int ldb,
    float*       __restrict__ C, int ldc,
    int K, int m0, int n0)
{
    constexpr int A_LO  = 8192;
    constexpr int B_OFF = 16384;
    constexpr int STAGE = 24576;

    extern __shared__ char smem[];
    const uint32_t sb0 = smem_u32(smem);

    const int tid = threadIdx.x, lane = tid & 31, wid = tid >> 5;
    const int wm = wid & 1, wn = wid >> 1;

    uint32_t offA[4][2], offB[2][2];
    #pragma unroll
    for (int am = 0; am < 4; am++)
        #pragma unroll
        for (int kh = 0; kh < 2; kh++) {
            int mrow  = wm * 64 + am * 16 + (lane & 7) + ((lane >> 3) & 1) * 8;
            int chunk = kh * 2 + ((lane >> 4) & 1);
            offA[am][kh] = (uint32_t)(mrow * 64 + ((chunk ^ ((mrow >> 1) & 3)) << 4));
        }
    #pragma unroll
    for (int p = 0; p < 2; p++)
        #pragma unroll
        for (int kh = 0; kh < 2; kh++) {
            int nrow  = wn * 32 + p * 16 + (lane & 7) + ((lane >> 4) & 1) * 8;
            int chunk = kh * 2 + ((lane >> 3) & 1);
            offB[p][kh] = (uint32_t)(B_OFF + nrow * 64 + ((chunk ^ ((nrow >> 1) & 3)) << 4));
        }

    float acc[4][4][4];
    #pragma unroll
    for (int i = 0; i < 4; i++)
        #pragma unroll
        for (int j = 0; j < 4; j++)
            #pragma unroll
            for (int e = 0; e < 4; e++) acc[i][j][e] = 0.0f;

    float4 pa[4], pb[4];
    auto LOADG = [&](int k0) {
        #pragma unroll
        for (int i = 0; i < 4; i++) {
            int idx = i * 256 + tid, row = idx >> 3, k4 = idx & 7;
            pa[i] = *(const float4*)&A[(long)(m0 + row) * lda + k0 + k4 * 4];
        }
        #pragma unroll
        for (int i = 0; i < 4; i++) {
            int idx = i * 256 + tid, row = idx >> 3, k4 = idx & 7;
            pb[i] = *(const float4*)&B[(long)(n0 + row) * ldb + k0 + k4 * 4];
        }
    };
    auto STORES = [&](uint32_t base) {
        #pragma unroll
        for (int i = 0; i < 4; i++) {
            int idx = i * 256 + tid, row = idx >> 3, k4 = idx & 7;
            half_split_store(base, base + A_LO, row, k4, pa[i]);
        }
        #pragma unroll
        for (int i = 0; i < 4; i++) {
            int idx = i * 256 + tid, row = idx >> 3, k4 = idx & 7;
            half_store(base + B_OFF, row, k4, pb[i]);
        }
    };

    const int nk = K >> 5;
    LOADG(0);
    STORES(sb0);
    __syncthreads();

    for (int t = 0; t < nk; t++) {
        const uint32_t sb = sb0 + (uint32_t)(t & 1) * STAGE;
        if (t + 1 < nk) LOADG((t + 1) * 32);

        #pragma unroll
        for (int kh = 0; kh < 2; kh++) {
            uint32_t ah[4][4], al[4][4];
            #pragma unroll
            for (int am = 0; am < 4; am++) {
                ldm4(ah[am], sb + offA[am][kh]);
                ldm4(al[am], sb + offA[am][kh] + A_LO);
            }
            uint32_t bh[2][4];
            #pragma unroll
            for (int p = 0; p < 2; p++)
                ldm4(bh[p], sb + offB[p][kh]);
            #pragma unroll
            for (int am = 0; am < 4; am++)
                #pragma unroll
                for (int na = 0; na < 4; na++) {
                    const uint32_t* bp = &bh[na >> 1][(na & 1) * 2];
                    mma16816h(acc[am][na], ah[am], bp);
                    mma16816h(acc[am][na], al[am], bp);
                }
        }

        if (t + 1 < nk) STORES(sb0 + (uint32_t)((t & 1) ^ 1) * STAGE);
        __syncthreads();
    }

    #pragma unroll
    for (int am = 0; am < 4; am++)
        #pragma unroll
        for (int na = 0; na < 4; na++) {
            int row = m0 + wm * 64 + am * 16 + (lane >> 2);
            int col = n0 + wn * 32 + na * 8 + (lane & 3) * 2;
            float* base0 = &C[(long)row * ldc + col];
            float* base1 = &C[(long)(row + 8) * ldc + col];
            float2 r0 = { acc[am][na][0], acc[am][na][1] };
            float2 r1 = { acc[am][na][2], acc[am][na][3] };
            if (EPI == 1) {
                float2 o0 = *(float2*)base0, o1 = *(float2*)base1;
                r0.x += o0.x; r0.y += o0.y; r1.x += o1.x; r1.y += o1.y;
            }
            *(float2*)base0 = r0;
            *(float2*)base1 = r1;
        }
}

// fused gate/up (z selects Wg/Wu), validated R14
__global__ void __launch_bounds__(256, 1)
mma_gemm_multi_2t(const float* __restrict__ A, int lda,
                  const float* __restrict__ B0g, const float* __restrict__ B1g,
                  float* __restrict__ C0g, float* __restrict__ C1g,
                  int ldb, int ldc, int K)
{
    const float* B = (blockIdx.z == 0) ? B0g : B1g;
    float*       C = (blockIdx.z == 0) ? C0g : C1g;
    gemm2t_body<0>(A, lda, B, ldb, C, ldc, K, blockIdx.x * 128, blockIdx.y * 128);
}

// 2-term accumulate (validated R15 on Wd; now also Wo): C += A @ B^T
__global__ void __launch_bounds__(256, 1)
mma_gemm_2t_acc(const float* __restrict__ A, int lda,
                const float* __restrict__ B, int ldb,
                float* __restrict__ C, int ldc, int K)
{
    gemm2t_body<1>(A, lda, B, ldb, C, ldc, K, blockIdx.x * 128, blockIdx.y * 128);
}

// ---------------- fp16 single-term GEMM (lm_head, validated R13) ----------
__global__ void __launch_bounds__(256, 1)
mma_gemm_h(const float* __restrict__ A, int lda,
           const float* __restrict__ B, int ldb,
           float*       __restrict__ C, int ldc,
           int K)
{
    constexpr int B_OFF = 8192;
    constexpr int STAGE = 16384;

    extern __shared__ char smem[];
    const uint32_t sb0 = smem_u32(smem);

    const int tid = threadIdx.x, lane = tid & 31, wid = tid >> 5;
    const int wm = wid & 1, wn = wid >> 1;
    const int m0 = blockIdx.x * 128;
    const int n0 = blockIdx.y * 128;

    uint32_t offA[4][2], offB[2][2];
    #pragma unroll
    for (int am = 0; am < 4; am++)
        #pragma unroll
        for (int kh = 0; kh < 2; kh++) {
            int mrow  = wm * 64 + am * 16 + (lane & 7) + ((lane >> 3) & 1) * 8;
            int chunk = kh * 2 + ((lane >> 4) & 1);
            offA[am][kh] = (uint32_t)(mrow * 64 + ((chunk ^ ((mrow >> 1) & 3)) << 4));
        }
    #pragma unroll
    for (int p = 0; p < 2; p++)
        #pragma unroll
        for (int kh = 0; kh < 2; kh++) {
            int nrow  = wn * 32 + p * 16 + (lane & 7) + ((lane >> 4) & 1) * 8;
            int chunk = kh * 2 + ((lane >> 3) & 1);
            offB[p][kh] = (uint32_t)(B_OFF + nrow * 64 + ((chunk ^ ((nrow >> 1) & 3)) << 4));
        }

    float acc[4][4][4];
    #pragma unroll
    for (int i = 0; i < 4; i++)
        #pragma unroll
        for (int j = 0; j < 4; j++)
            #pragma unroll
            for (int e = 0; e < 4; e++) acc[i][j][e] = 0.0f;

    float4 pa[4], pb[4];
    auto LOADG = [&](int k0) {
        #pragma unroll
        for (int i = 0; i < 4; i++) {
            int idx = i * 256 + tid, row = idx >> 3, k4 = idx & 7;
            pa[i] = *(const float4*)&A[(long)(m0 + row) * lda + k0 + k4 * 4];
        }
        #pragma unroll
        for (int i = 0; i < 4; i++) {
            int idx = i * 256 + tid, row = idx >> 3, k4 = idx & 7;
            pb[i] = *(const float4*)&B[(long)(n0 + row) * ldb + k0 + k4 * 4];
        }
    };
    auto STORES = [&](uint32_t base) {
        #pragma unroll
        for (int i = 0; i < 4; i++) {
            int idx = i * 256 + tid, row = idx >> 3, k4 = idx & 7;
            half_store(base, row, k4, pa[i]);
        }
        #pragma unroll
        for (int i = 0; i < 4; i++) {
            int idx = i * 256 + tid, row = idx >> 3, k4 = idx & 7;
            half_store(base + B_OFF, row, k4, pb[i]);
        }
    };

    const int nk = K >> 5;
    LOADG(0);
    STORES(sb0);
    __syncthreads();

    for (int t = 0; t < nk; t++) {
        const uint32_t sb = sb0 + (uint32_t)(t & 1) * STAGE;
        if (t + 1 < nk) LOADG((t + 1) * 32);

        #pragma unroll
        for (int kh = 0; kh < 2; kh++) {
            uint32_t ah[4][4];
            #pragma unroll
            for (int am = 0; am < 4; am++)
                ldm4(ah[am], sb + offA[am][kh]);
            uint32_t bh[2][4];
            #pragma unroll
            for (int p = 0; p < 2; p++)
                ldm4(bh[p], sb + offB[p][kh]);
            #pragma unroll
            for (int am = 0; am < 4; am++)
                #pragma unroll
                for (int na = 0; na < 4; na++)
                    mma16816h(acc[am][na], ah[am], &bh[na >> 1][(na & 1) * 2]);
        }

        if (t + 1 < nk) STORES(sb0 + (uint32_t)((t & 1) ^ 1) * STAGE);
        __syncthreads();
    }

    #pragma unroll
    for (int am = 0; am < 4; am++)
        #pragma unroll
        for (int na = 0; na < 4; na++) {
            int row = m0 + wm * 64 + am * 16 + (lane >> 2);
            int col = n0 + wn * 32 + na * 8 + (lane & 3) * 2;
            float2 r0 = { acc[am][na][0], acc[am][na][1] };
            float2 r1 = { acc[am][na][2], acc[am][na][3] };
            *(float2*)&C[(long)row * ldc + col] = r0;
            *(float2*)&C[(long)(row + 8) * ldc + col] = r1;
        }
}

// ================= flash attention, s-tile 64, 2 CTAs/SM (validated R12) ==
#define FA_QH  0
#define FA_QL  16384
#define FA_KH  32768
#define FA_KL  40960
#define FA_VH  49152
#define FA_VL  57344
#define FA_PH  65536
#define FA_PL  81920
#define FA_SMX 98304
#define FA_SSM 100352
#define FA_BYTES 102400

__global__ void __launch_bounds__(256, 2)
flash_attn(const float* __restrict__ q, const float* __restrict__ k,
           const float* __restrict__ vt, float* __restrict__ y)
{
    extern __shared__ char smem[];
    const uint32_t sb = smem_u32(smem);
    float* smx = (float*)(smem + FA_SMX);
    float* ssm = (float*)(smem + FA_SSM);

    const int tid = threadIdx.x, lane = tid & 31, wid = tid >> 5;
    const int wm = wid & 1, wn = wid >> 1;
    const int bh = blockIdx.z, b = bh >> 4, hh = bh & 15;
    const int q0 = blockIdx.x * 128;

    uint32_t offA[4][2];
    #pragma unroll
    for (int am = 0; am < 4; am++)
        #pragma unroll
        for (int khi = 0; khi < 2; khi++) {
            int arow  = wm * 64 + am * 16 + (lane & 7) + ((lane >> 3) & 1) * 8;
            int chunk = khi * 2 + ((lane >> 4) & 1);
            offA[am][khi] = (uint32_t)(arow * 64 + ((chunk ^ ((arow >> 1) & 3)) << 4));
        }
    uint32_t offK[2], offV[2];
    #pragma unroll
    for (int khi = 0; khi < 2; khi++) {
        int brow  = wn * 16 + (lane & 7) + ((lane >> 4) & 1) * 8;
        int chunk = khi * 2 + ((lane >> 3) & 1);
        uint32_t o = (uint32_t)(brow * 64 + ((chunk ^ ((brow >> 1) & 3)) << 4));
        offK[khi] = o;
        offV[khi] = o;
    }

    #pragma unroll
    for (int i = 0; i < 8; i++) {
        int idx = i * 256 + tid, row = idx >> 4, k4 = idx & 15;
        float4 f = *(const float4*)&q[(long)(b * SEQ + q0 + row) * DIMN + hh * 64 + k4 * 4];
        f.x *= 0.125f; f.y *= 0.125f; f.z *= 0.125f; f.w *= 0.125f;
        split_store(sb + FA_QH + (k4 >> 3) * 8192, sb + FA_QL + (k4 >> 3) * 8192,
                    row, k4 & 7, f);
    }

    float o[4][2][4];
    float m_r[4][2], l_r[4][2];
    #pragma unroll
    for (int am = 0; am < 4; am++) {
        m_r[am][0] = m_r[am][1] = -1e30f;
        l_r[am][0] = l_r[am][1] = 0.0f;
        #pragma unroll
        for (int na = 0; na < 2; na++)
            #pragma unroll
            for (int e = 0; e < 4; e++) o[am][na][e] = 0.0f;
    }

    const int rb = wm * 64 + (lane >> 2);

    for (int s0 = 0; s0 < SEQ; s0 += 64) {
        __syncthreads();

        #pragma unroll
        for (int i = 0; i < 4; i++) {
            int idx = i * 256 + tid, row = idx >> 4, k4 = idx & 15;
            float4 f = *(const float4*)&k[(long)(b * SEQ + s0 + row) * DIMN + hh * 64 + k4 * 4];
            split_store(sb + FA_KH + (k4 >> 3) * 4096, sb + FA_KL + (k4 >> 3) * 4096,
                        row, k4 & 7, f);
        }
        #pragma unroll
        for (int i = 0; i < 4; i++) {
            int idx = i * 256 + tid, row = idx >> 4, s4 = idx & 15;
            float4 f = *(const float4*)&vt[((long)bh * 64 + row) * SEQ + s0 + s4 * 4];
            split_store(sb + FA_VH + (s4 >> 3) * 4096, sb + FA_VL + (s4 >> 3) * 4096,
                        row, s4 & 7, f);
        }
        __syncthreads();

        float sf[4][2][4];
        #pragma unroll
        for (int am = 0; am < 4; am++)
            #pragma unroll
            for (int na = 0; na < 2; na++)
                #pragma unroll
                for (int e = 0; e < 4; e++) sf[am][na][e] = 0.0f;

        #pragma unroll
        for (int kb = 0; kb < 2; kb++)
            #pragma unroll
            for (int khi = 0; khi < 2; khi++) {
                uint32_t ah[4][4], al[4][4];
                #pragma unroll
                for (int am = 0; am < 4; am++) {
                    ldm4(ah[am], sb + FA_QH + kb * 8192 + offA[am][khi]);
                    ldm4(al[am], sb + FA_QL + kb * 8192 + offA[am][khi]);
                }
                uint32_t bhf[4], blf[4];
                ldm4(bhf, sb + FA_KH + kb * 4096 + offK[khi]);
                ldm4(blf, sb + FA_KL + kb * 4096 + offK[khi]);
                #pragma unroll
                for (int am = 0; am < 4; am++)
                    #pragma unroll
                    for (int na = 0; na < 2; na++) {
                        const uint32_t* bhp = &bhf[na * 2];
                        const uint32_t* blp = &blf[na * 2];
                        mma16816(sf[am][na], ah[am], bhp);
                        mma16816(sf[am][na], ah[am], blp);
                        mma16816(sf[am][na], al[am], bhp);
                    }
            }

        #pragma unroll
        for (int am = 0; am < 4; am++) {
            float v0 = -1e30f, v1 = -1e30f;
            #pragma unroll
            for (int na = 0; na < 2; na++) {
                v0 = fmaxf(v0, fmaxf(sf[am][na][0], sf[am][na][1]));
                v1 = fmaxf(v1, fmaxf(sf[am][na][2], sf[am][na][3]));
            }
            v0 = fmaxf(v0, __shfl_xor_sync(0xFFFFFFFFu, v0, 1));
            v0 = fmaxf(v0, __shfl_xor_sync(0xFFFFFFFFu, v0, 2));
            v1 = fmaxf(v1, __shfl_xor_sync(0xFFFFFFFFu, v1, 1));
            v1 = fmaxf(v1, __shfl_xor_sync(0xFFFFFFFFu, v1, 2));
            if ((lane & 3) == 0) {
                smx[(rb + am * 16) * 4 + wn] = v0;
                smx[(rb + am * 16 + 8) * 4 + wn] = v1;
            }
        }
        __syncthreads();

        float csc[4][2];
        #pragma unroll
        for (int am = 0; am < 4; am++) {
            int r0 = rb + am * 16, r1 = r0 + 8;
            float tm0 = fmaxf(fmaxf(smx[r0 * 4 + 0], smx[r0 * 4 + 1]),
                              fmaxf(smx[r0 * 4 + 2], smx[r0 * 4 + 3]));
            float tm1 = fmaxf(fmaxf(smx[r1 * 4 + 0], smx[r1 * 4 + 1]),
                              fmaxf(smx[r1 * 4 + 2], smx[r1 * 4 + 3]));
            float mn0 = fmaxf(m_r[am][0], tm0);
            float mn1 = fmaxf(m_r[am][1], tm1);
            csc[am][0] = __expf(m_r[am][0] - mn0);
            csc[am][1] = __expf(m_r[am][1] - mn1);
            m_r[am][0] = mn0; m_r[am][1] = mn1;

            float rs0 = 0.0f, rs1 = 0.0f;
            #pragma unroll
            for (int na = 0; na < 2; na++) {
                float p0 = __expf(sf[am][na][0] - mn0);
                float p1 = __expf(sf[am][na][1] - mn0);
                float p2 = __expf(sf[am][na][2] - mn1);
                float p3 = __expf(sf[am][na][3] - mn1);
                rs0 += p0 + p1; rs1 += p2 + p3;
                int c0col = wn * 16 + na * 8 + (lane & 3) * 2;
                int kb = c0col >> 5, cc = c0col & 31;
                uint32_t o0 = (uint32_t)(kb * 8192 + r0 * 64 +
                              (((cc >> 3) ^ ((r0 >> 1) & 3)) << 4) +
                              ((cc >> 2) & 1) * 8 + (cc & 3) * 2);
                uint32_t o1 = (uint32_t)(kb * 8192 + r1 * 64 +
                              (((cc >> 3) ^ ((r1 >> 1) & 3)) << 4) +
                              ((cc >> 2) & 1) * 8 + (cc & 3) * 2);
                *(uint32_t*)(smem + FA_PH + o0) = pk_hi(p0, p1);
                *(uint32_t*)(smem + FA_PL + o0) = pk_lo(p0, p1);
                *(uint32_t*)(smem + FA_PH + o1) = pk_hi(p2, p3);
                *(uint32_t*)(smem + FA_PL + o1) = pk_lo(p2, p3);
            }
            rs0 += __shfl_xor_sync(0xFFFFFFFFu, rs0, 1);
            rs0 += __shfl_xor_sync(0xFFFFFFFFu, rs0, 2);
            rs1 += __shfl_xor_sync(0xFFFFFFFFu, rs1, 1);
            rs1 += __shfl_xor_sync(0xFFFFFFFFu, rs1, 2);
            if ((lane & 3) == 0) {
                ssm[r0 * 4 + wn] = rs0;
                ssm[r1 * 4 + wn] = rs1;
            }
        }
        __syncthreads();

        #pragma unroll
        for (int am = 0; am < 4; am++) {
            int r0 = rb + am * 16, r1 = r0 + 8;
            float s0s = ssm[r0 * 4 + 0] + ssm[r0 * 4 + 1] + ssm[r0 * 4 + 2] + ssm[r0 * 4 + 3];
            float s1s = ssm[r1 * 4 + 0] + ssm[r1 * 4 + 1] + ssm[r1 * 4 + 2] + ssm[r1 * 4 + 3];
            l_r[am][0] = l_r[am][0] * csc[am][0] + s0s;
            l_r[am][1] = l_r[am][1] * csc[am][1] + s1s;
            #pragma unroll
            for (int na = 0; na < 2; na++) {
                o[am][na][0] *= csc[am][0]; o[am][na][1] *= csc[am][0];
                o[am][na][2] *= csc[am][1]; o[am][na][3] *= csc[am][1];
            }
        }

        #pragma unroll
        for (int kb = 0; kb < 2; kb++)
            #pragma unroll
            for (int khi = 0; khi < 2; khi++) {
                uint32_t ah[4][4], al[4][4];
                #pragma unroll
                for (int am = 0; am < 4; am++) {
                    ldm4(ah[am], sb + FA_PH + kb * 8192 + offA[am][khi]);
                    ldm4(al[am], sb + FA_PL + kb * 8192 + offA[am][khi]);
                }
                uint32_t bhf[4], blf[4];
                ldm4(bhf, sb + FA_VH + kb * 4096 + offV[khi]);
                ldm4(blf, sb + FA_VL + kb * 4096 + offV[khi]);
                #pragma unroll
                for (int am = 0; am < 4; am++)
                    #pragma unroll
                    for (int na = 0; na < 2; na++) {
                        const uint32_t* bhp = &bhf[na * 2];
                        const uint32_t* blp = &blf[na * 2];
                        mma16816(o[am][na], ah[am], bhp);
                        mma16816(o[am][na], ah[am], blp);
                        mma16816(o[am][na], al[am], bhp);
                    }
            }
    }

    #pragma unroll
    for (int am = 0; am < 4; am++) {
        float inv0 = 1.0f / l_r[am][0];
        float inv1 = 1.0f / l_r[am][1];
        long tok0 = (long)(b * SEQ + q0 + wm * 64 + am * 16 + (lane >> 2));
        #pragma unroll
        for (int na = 0; na < 2; na++) {
            int col = hh * 64 + wn * 16 + na * 8 + (lane & 3) * 2;
            float2 r0 = { o[am][na][0] * inv0, o[am][na][1] * inv0 };
            float2 r1 = { o[am][na][2] * inv1, o[am][na][3] * inv1 };
            *(float2*)&y[tok0 * DIMN + col] = r0;
            *(float2*)&y[(tok0 + 8) * DIMN + col] = r1;
        }
    }
}

// ---------------- elementwise kernels ----------------
__global__ void embed_kernel(const int* __restrict__ tokens,
                             const float* __restrict__ embed,
                             float* __restrict__ h)
{
    int row = blockIdx.x;
    int tok = tokens[row];
    ((float4*)(h + (long)row * DIMN))[threadIdx.x] =
        ((const float4*)(embed + (long)tok * DIMN))[threadIdx.x];
}

__global__ void rmsnorm_kernel(const float* __restrict__ x,
                               const float* __restrict__ w,
                               float* __restrict__ out)
{
    int row = blockIdx.x;
    float4 v = ((const float4*)(x + (long)row * DIMN))[threadIdx.x];
    float ss = v.x*v.x + v.y*v.y + v.z*v.z + v.w*v.w;
    __shared__ float red[8];
    #pragma unroll
    for (int o = 16; o > 0; o >>= 1) ss += __shfl_xor_sync(0xFFFFFFFFu, ss, o);
    if ((threadIdx.x & 31) == 0) red[threadIdx.x >> 5] = ss;
    __syncthreads();
    if (threadIdx.x < 8) {
        float s = red[threadIdx.x];
        #pragma unroll
        for (int o = 4; o > 0; o >>= 1) s += __shfl_xor_sync(0xFFu, s, o);
        if (threadIdx.x == 0) red[0] = s;
    }
    __syncthreads();
    float scale = rsqrtf(red[0] * (1.0f / DIMN) + EPS);
    float4 wv = ((const float4*)w)[threadIdx.x];
    float4 o4 = { v.x*scale*wv.x, v.y*scale*wv.y, v.z*scale*wv.z, v.w*scale*wv.w };
    ((float4*)(out + (long)row * DIMN))[threadIdx.x] = o4;
}

__global__ void silu_mul_kernel(float4* __restrict__ g, const float4* __restrict__ u)
{
    long i = (long)blockIdx.x * blockDim.x + threadIdx.x;
    float4 gv = g[i], uv = u[i];
    gv.x = gv.x / (1.0f + __expf(-gv.x)) * uv.x;
    gv.y = gv.y / (1.0f + __expf(-gv.y)) * uv.y;
    gv.z = gv.z / (1.0f + __expf(-gv.z)) * uv.z;
    gv.w = gv.w / (1.0f + __expf(-gv.w)) * uv.w;
    g[i] = gv;
}

// vt[(b*H+h)][d][s] = v[b*SEQ+s][h*64+d]
__global__ void transpose_v_kernel(const float* __restrict__ v, float* __restrict__ vt)
{
    __shared__ float t[32][33];
    int bh = blockIdx.z, b = bh >> 4, hh = bh & 15;
    int s0 = blockIdx.x * 32, d0 = blockIdx.y * 32;
    int tx = threadIdx.x, ty = threadIdx.y;    // 32 x 8
    #pragma unroll
    for (int j = 0; j < 32; j += 8)
        t[ty + j][tx] = v[(long)(b * SEQ + s0 + ty + j) * DIMN + hh * HEAD_DIM + d0 + tx];
    __syncthreads();
    #pragma unroll
    for (int j = 0; j < 32; j += 8)
        vt[((long)bh * HEAD_DIM + d0 + ty + j) * SEQ + s0 + tx] = t[tx][ty + j];
}

// ---------------- launcher ----------------
extern "C" void kernel_launch(void* const* d_in, const int* in_sizes, int n_in,
                              void* d_out, int out_size)
{
    const int*   tokens  = (const int*)  d_in[0];
    const float* embed   = (const float*)d_in[1];
    const float* Wq      = (const float*)d_in[2];
    const float* Wk      = (const float*)d_in[3];
    const float* Wv      = (const float*)d_in[4];
    const float* Wo      = (const float*)d_in[5];
    const float* Wg      = (const float*)d_in[6];
    const float* Wu      = (const float*)d_in[7];
    const float* Wd      = (const float*)d_in[8];
    const float* ln1     = (const float*)d_in[9];
    const float* ln2     = (const float*)d_in[10];
    const float* norm_w  = (const float*)d_in[11];
    const float* lm_head = (const float*)d_in[12];
    float* out = (float*)d_out;

    float *h, *x, *q, *k, *v, *vt, *y, *gate, *up;
    cudaGetSymbolAddress((void**)&h,    g_h);
    cudaGetSymbolAddress((void**)&x,    g_x);
    cudaGetSymbolAddress((void**)&q,    g_q);
    cudaGetSymbolAddress((void**)&k,    g_k);
    cudaGetSymbolAddress((void**)&v,    g_v);
    cudaGetSymbolAddress((void**)&vt,   g_vt);
    cudaGetSymbolAddress((void**)&y,    g_y);
    cudaGetSymbolAddress((void**)&gate, g_gate);
    cudaGetSymbolAddress((void**)&up,   g_up);

    const int DYN128 = 2 * (16384 + 128 * 128);   // 65536
    const int DYNH   = 2 * 16384;                 // 32768
    const int DYN2T  = 2 * 24576;                 // 49152
    cudaFuncSetAttribute(mma_gemm<128, false>, cudaFuncAttributeMaxDynamicSharedMemorySize, DYN128);
    cudaFuncSetAttribute(mma_gemm<128, true>,  cudaFuncAttributeMaxDynamicSharedMemorySize, DYN128);
    cudaFuncSetAttribute(mma_gemm_multi,       cudaFuncAttributeMaxDynamicSharedMemorySize, DYN128);
    cudaFuncSetAttribute(mma_gemm_multi_2t,    cudaFuncAttributeMaxDynamicSharedMemorySize, DYN2T);
    cudaFuncSetAttribute(mma_gemm_2t_acc,      cudaFuncAttributeMaxDynamicSharedMemorySize, DYN2T);
    cudaFuncSetAttribute(mma_gemm_h,           cudaFuncAttributeMaxDynamicSharedMemorySize, DYNH);
    cudaFuncSetAttribute(flash_attn, cudaFuncAttributeMaxDynamicSharedMemorySize, FA_BYTES);

    embed_kernel<<<MTOK, 256>>>(tokens, embed, h);

    dim3 gQKV (MTOK / 128, DIMN / 128, 3);
    dim3 gGU  (MTOK / 128, HIDDEN / 128, 2);
    dim3 gProj(MTOK / 128, DIMN / 128, 1);
    dim3 gHead(MTOK / 128, VOCAB / 128, 1);
    dim3 gFa  (SEQ / 128, 1, BATCH * HEADS);
    dim3 gTr  (SEQ / 32, HEAD_DIM / 32, BATCH * HEADS);

    for (int l = 0; l < LAYERS; l++) {
        const float* wq = Wq + (long)l * DIMN * DIMN;
        const float* wk = Wk + (long)l * DIMN * DIMN;
        const float* wv = Wv + (long)l * DIMN * DIMN;
        const float* wo = Wo + (long)l * DIMN * DIMN;
        const float* wg = Wg + (long)l * HIDDEN * DIMN;
        const float* wu = Wu + (long)l * HIDDEN * DIMN;
        const float* wd = Wd + (long)l * DIMN * HIDDEN;

        rmsnorm_kernel<<<MTOK, 256>>>(h, ln1 + (long)l * DIMN, x);

        // QKV stays 3-term bf16 (softmax-sensitive path — do not degrade)
        {
            P3 p = { wq, wk, wv, q, k, v };
            mma_gemm_multi<<<gQKV, 256, DYN128>>>(x, DIMN, p, DIMN, DIMN, DIMN, 1.0f);
        }

        transpose_v_kernel<<<gTr, dim3(32, 8)>>>(v, vt);
        flash_attn<<<gFa, 256, FA_BYTES>>>(q, k, vt, y);

        // h += y @ Wo^T — fp16 2-term accumulate (new this round)
        mma_gemm_2t_acc<<<gProj, 256, DYN2T>>>(y, DIMN, wo, DIMN,
                                               h, DIMN, DIMN);

        rmsnorm_kernel<<<MTOK, 256>>>(h, ln2 + (long)l * DIMN, x);

        // fused gate,up = x @ {Wg,Wu}^T — fp16 2-term
        mma_gemm_multi_2t<<<gGU, 256, DYN2T>>>(x, DIMN, wg, wu, gate, up,
                                               DIMN, HIDDEN, DIMN);

        silu_mul_kernel<<<(MTOK * (long)HIDDEN / 4) / 256, 256>>>((float4*)gate, (const float4*)up);

        // h += gate @ Wd^T — fp16 2-term accumulate
        mma_gemm_2t_acc<<<gProj, 256, DYN2T>>>(gate, HIDDEN, wd, HIDDEN,
                                               h, DIMN, HIDDEN);
    }

    rmsnorm_kernel<<<MTOK, 256>>>(h, norm_w, x);
    mma_gemm_h<<<gHead, 256, DYNH>>>(x, DIMN, lm_head, DIMN, out, VOCAB, DIMN);
}

// round 17
// speedup vs baseline: 1.4179x; 1.0069x over previous
#include <cuda_runtime.h>
#include <cuda_fp16.h>
#include <math.h>
#include <stdint.h>

// ---------------- problem constants ----------------
#define DIMN     1024
#define HEADS    16
#define HEAD_DIM 64
#define LAYERS   4
#define HIDDEN   4096
#define VOCAB    32000
#define BATCH    2
#define SEQ      1024
#define MTOK     (BATCH*SEQ)
#define EPS      1e-6f

// ---------------- scratch ----------------
__device__ float g_h   [MTOK*DIMN];
__device__ float g_x   [MTOK*DIMN];
__device__ float g_q   [MTOK*DIMN];
__device__ float g_k   [MTOK*DIMN];
__device__ float g_v   [MTOK*DIMN];
__device__ float g_vt  [MTOK*DIMN];
__device__ float g_y   [MTOK*DIMN];
__device__ float g_gate[MTOK*HIDDEN];
__device__ float g_up  [MTOK*HIDDEN];

// ---------------- PTX helpers ----------------
__device__ __forceinline__ uint32_t smem_u32(const void* p) {
    uint32_t a;
    asm("{ .reg .u64 t; cvta.to.shared.u64 t, %1; cvt.u32.u64 %0, t; }"
        : "=r"(a) : "l"(p));
    return a;
}

__device__ __forceinline__ void ldm4(uint32_t* r, uint32_t addr) {
    asm volatile("ldmatrix.sync.aligned.m8n8.x4.shared.b16 {%0,%1,%2,%3}, [%4];"
                 : "=r"(r[0]), "=r"(r[1]), "=r"(r[2]), "=r"(r[3]) : "r"(addr));
}

__device__ __forceinline__ void mma16816(float* c, const uint32_t* a, const uint32_t* b) {
    asm volatile("mma.sync.aligned.m16n8k16.row.col.f32.bf16.bf16.f32 "
                 "{%0,%1,%2,%3}, {%4,%5,%6,%7}, {%8,%9}, {%0,%1,%2,%3};"
                 : "+f"(c[0]), "+f"(c[1]), "+f"(c[2]), "+f"(c[3])
                 : "r"(a[0]), "r"(a[1]), "r"(a[2]), "r"(a[3]),
                   "r"(b[0]), "r"(b[1]));
}

__device__ __forceinline__ void mma16816h(float* c, const uint32_t* a, const uint32_t* b) {
    asm volatile("mma.sync.aligned.m16n8k16.row.col.f32.f16.f16.f32 "
                 "{%0,%1,%2,%3}, {%4,%5,%6,%7}, {%8,%9}, {%0,%1,%2,%3};"
                 : "+f"(c[0]), "+f"(c[1]), "+f"(c[2]), "+f"(c[3])
                 : "r"(a[0]), "r"(a[1]), "r"(a[2]), "r"(a[3]),
                   "r"(b[0]), "r"(b[1]));
}

__device__ __forceinline__ uint32_t pk_hi(float a, float b) {
    return __byte_perm(__float_as_uint(a), __float_as_uint(b), 0x7632);
}
__device__ __forceinline__ uint32_t pk_lo(float a, float b) {
    float la = a - __uint_as_float(__float_as_uint(a) & 0xFFFF0000u);
    float lb = b - __uint_as_float(__float_as_uint(b) & 0xFFFF0000u);
    return __byte_perm(__float_as_uint(la), __float_as_uint(lb), 0x7632);
}

// pack two floats to fp16x2; return residuals for hi/lo splitting
__device__ __forceinline__ uint32_t pkh(float a, float b) {
    __half2 h = __floats2half2_rn(a, b);
    return *(uint32_t*)&h;
}
__device__ __forceinline__ uint32_t pkh_res(float a, float b, float* ra, float* rb) {
    __half2 h = __floats2half2_rn(a, b);
    *ra = a - __half2float(__low2half(h));
    *rb = b - __half2float(__high2half(h));
    return *(uint32_t*)&h;
}

__device__ __forceinline__ void split_store(uint32_t hi_base, uint32_t lo_base,
                                            int row, int k4, float4 f) {
    uint32_t h01 = pk_hi(f.x, f.y), h23 = pk_hi(f.z, f.w);
    uint32_t l01 = pk_lo(f.x, f.y), l23 = pk_lo(f.z, f.w);
    int chunk = k4 >> 1, half = k4 & 1;
    uint32_t off = (uint32_t)(row * 64 + ((chunk ^ ((row >> 1) & 3)) << 4) + half * 8);
    asm volatile("st.shared.v2.b32 [%0], {%1,%2};" :: "r"(hi_base + off), "r"(h01), "r"(h23));
    asm volatile("st.shared.v2.b32 [%0], {%1,%2};" :: "r"(lo_base + off), "r"(l01), "r"(l23));
}

__device__ __forceinline__ void half_store(uint32_t base, int row, int k4, float4 f) {
    uint32_t h01 = pkh(f.x, f.y), h23 = pkh(f.z, f.w);
    int chunk = k4 >> 1, half = k4 & 1;
    uint32_t off = (uint32_t)(row * 64 + ((chunk ^ ((row >> 1) & 3)) << 4) + half * 8);
    asm volatile("st.shared.v2.b32 [%0], {%1,%2};" :: "r"(base + off), "r"(h01), "r"(h23));
}

__device__ __forceinline__ void half_split_store(uint32_t hi_base, uint32_t lo_base,
                                                 int row, int k4, float4 f) {
    float lx, ly, lz, lw;
    uint32_t hh01 = pkh_res(f.x, f.y, &lx, &ly);
    uint32_t hh23 = pkh_res(f.z, f.w, &lz, &lw);
    uint32_t ll01 = pkh(lx, ly), ll23 = pkh(lz, lw);
    int chunk = k4 >> 1, half = k4 & 1;
    uint32_t off = (uint32_t)(row * 64 + ((chunk ^ ((row >> 1) & 3)) << 4) + half * 8);
    asm volatile("st.shared.v2.b32 [%0], {%1,%2};" :: "r"(hi_base + off), "r"(hh01), "r"(hh23));
    asm volatile("st.shared.v2.b32 [%0], {%1,%2};" :: "r"(lo_base + off), "r"(ll01), "r"(ll23));
}

// ---------------- bf16 3-term GEMM body (validated since R4) --------------
template<int BN, bool ACCUM>
__device__ __forceinline__ void gemm_body(
    const float* __restrict__ A, int lda,
    const float* __restrict__ B, int ldb,
    float*       __restrict__ C, int ldc,
    int K, float alpha, int m0, int n0)
{
    constexpr int WN    = BN / 4;
    constexpr int NA    = WN / 8;
    constexpr int NB4   = BN / 32;
    constexpr int A_LO  = 8192;
    constexpr int B_HI  = 16384;
    constexpr int BLO_D = BN * 64;
    constexpr int STAGE = 16384 + BN * 128;

    extern __shared__ char smem[];
    const uint32_t sb0 = smem_u32(smem);

    const int tid = threadIdx.x, lane = tid & 31, wid = tid >> 5;
    const int wm = wid & 1, wn = wid >> 1;

    uint32_t offA[4][2], offB[NA / 2][2];
    #pragma unroll
    for (int am = 0; am < 4; am++)
        #pragma unroll
        for (int kh = 0; kh < 2; kh++) {
            int mrow  = wm * 64 + am * 16 + (lane & 7) + ((lane >> 3) & 1) * 8;
            int chunk = kh * 2 + ((lane >> 4) & 1);
            offA[am][kh] = (uint32_t)(mrow * 64 + ((chunk ^ ((mrow >> 1) & 3)) << 4));
        }
    #pragma unroll
    for (int p = 0; p < NA / 2; p++)
        #pragma unroll
        for (int kh = 0; kh < 2; kh++) {
            int nrow  = wn * WN + p * 16 + (lane & 7) + ((lane >> 4) & 1) * 8;
            int chunk = kh * 2 + ((lane >> 3) & 1);
            offB[p][kh] = (uint32_t)(B_HI + nrow * 64 + ((chunk ^ ((nrow >> 1) & 3)) << 4));
        }

    float acc[4][NA][4];
    #pragma unroll
    for (int i = 0; i < 4; i++)
        #pragma unroll
        for (int j = 0; j < NA; j++)
            #pragma unroll
            for (int e = 0; e < 4; e++) acc[i][j][e] = 0.0f;

    float4 pa[4], pb[NB4];
    auto LOADG = [&](int k0) {
        #pragma unroll
        for (int i = 0; i < 4; i++) {
            int idx = i * 256 + tid, row = idx >> 3, k4 = idx & 7;
            pa[i] = *(const float4*)&A[(long)(m0 + row) * lda + k0 + k4 * 4];
        }
        #pragma unroll
        for (int i = 0; i < NB4; i++) {
            int idx = i * 256 + tid, row = idx >> 3, k4 = idx & 7;
            pb[i] = *(const float4*)&B[(long)(n0 + row) * ldb + k0 + k4 * 4];
        }
    };
    auto STORES = [&](uint32_t base) {
        #pragma unroll
        for (int i = 0; i < 4; i++) {
            int idx = i * 256 + tid, row = idx >> 3, k4 = idx & 7;
            split_store(base, base + A_LO, row, k4, pa[i]);
        }
        #pragma unroll
        for (int i = 0; i < NB4; i++) {
            int idx = i * 256 + tid, row = idx >> 3, k4 = idx & 7;
            split_store(base + B_HI, base + B_HI + BLO_D, row, k4, pb[i]);
        }
    };

    const int nk = K >> 5;
    LOADG(0);
    STORES(sb0);
    __syncthreads();

    for (int t = 0; t < nk; t++) {
        const uint32_t sb = sb0 + (uint32_t)(t & 1) * STAGE;
        if (t + 1 < nk) LOADG((t + 1) * 32);

        #pragma unroll
        for (int kh = 0; kh < 2; kh++) {
            uint32_t ah[4][4], al[4][4];
            #pragma unroll
            for (int am = 0; am < 4; am++) {
                ldm4(ah[am], sb + offA[am][kh]);
                ldm4(al[am], sb + offA[am][kh] + A_LO);
            }
            uint32_t bh[NA / 2][4], bl[NA / 2][4];
            #pragma unroll
            for (int p = 0; p < NA / 2; p++) {
                ldm4(bh[p], sb + offB[p][kh]);
                ldm4(bl[p], sb + offB[p][kh] + BLO_D);
            }
            #pragma unroll
            for (int am = 0; am < 4; am++)
                #pragma unroll
                for (int na = 0; na < NA; na++) {
                    const uint32_t* bhp = &bh[na >> 1][(na & 1) * 2];
                    const uint32_t* blp = &bl[na >> 1][(na & 1) * 2];
                    mma16816(acc[am][na], ah[am], bhp);
                    mma16816(acc[am][na], ah[am], blp);
                    mma16816(acc[am][na], al[am], bhp);
                }
        }

        if (t + 1 < nk) STORES(sb0 + (uint32_t)((t & 1) ^ 1) * STAGE);
        __syncthreads();
    }

    #pragma unroll
    for (int am = 0; am < 4; am++)
        #pragma unroll
        for (int na = 0; na < NA; na++) {
            int row = m0 + wm * 64 + am * 16 + (lane >> 2);
            int col = n0 + wn * WN + na * 8 + (lane & 3) * 2;
            float* base0 = &C[(long)row * ldc + col];
            float* base1 = &C[(long)(row + 8) * ldc + col];
            float2 r0 = { alpha * acc[am][na][0], alpha * acc[am][na][1] };
            float2 r1 = { alpha * acc[am][na][2], alpha * acc[am][na][3] };
            if (ACCUM) {
                float2 o0 = *(float2*)base0, o1 = *(float2*)base1;
                r0.x += o0.x; r0.y += o0.y; r1.x += o1.x; r1.y += o1.y;
            }
            *(float2*)base0 = r0;
            *(float2*)base1 = r1;
        }
}

template<int BN, bool ACCUM>
__global__ void __launch_bounds__(256, 1)
mma_gemm(const float* __restrict__ A, int lda,
         const float* __restrict__ B, int ldb,
         float*       __restrict__ C, int ldc,
         int K, float alpha)
{
    gemm_body<BN, ACCUM>(A, lda, B, ldb, C, ldc, K, alpha,
                         blockIdx.x * 128, blockIdx.y * BN);
}

struct P3 {
    const float *B0, *B1, *B2;
    float *C0, *C1, *C2;
};

__global__ void __launch_bounds__(256, 1)
mma_gemm_multi(const float* __restrict__ A, int lda, P3 p,
               int ldb, int ldc, int K, float alpha)
{
    const int z = blockIdx.z;
    const float* B = (z == 0) ? p.B0 : (z == 1) ? p.B1 : p.B2;
    float*       C = (z == 0) ? p.C0 : (z == 1) ? p.C1 : p.C2;
    gemm_body<128, false>(A, lda, B, ldb, C, ldc, K, alpha,
                          blockIdx.x * 128, blockIdx.y * 128);
}

// ------------ fp16 2-term GEMM body (A hi/lo fp16, B single fp16) ---------
// EPI: 0 = store, 1 = accumulate into C.
template<int EPI>
__device__ __forceinline__ void gemm2t_body(
    const float* __restrict__ A, int lda,
    const float* __restrict__ B, int ldb,
    float*       __restrict__ C, int ldc,
    int K, int m0, int n0)
{
    constexpr int A_LO  = 8192;
    constexpr int B_OFF = 16384;
    constexpr int STAGE = 24576;

    extern __shared__ char smem[];
    const uint32_t sb0 = smem_u32(smem);

    const int tid = threadIdx.x, lane = tid & 31, wid = tid >> 5;
    const int wm = wid & 1, wn = wid >> 1;

    uint32_t offA[4][2], offB[2][2];
    #pragma unroll
    for (int am = 0; am < 4; am++)
        #pragma unroll
        for (int kh = 0; kh < 2; kh++) {
            int mrow  = wm * 64 + am * 16 + (lane & 7) + ((lane >> 3) & 1) * 8;
            int chunk = kh * 2 + ((lane >> 4) & 1);
            offA[am][kh] = (uint32_t)(mrow * 64 + ((chunk ^ ((mrow >> 1) & 3)) << 4));
        }
    #pragma unroll
    for (int p = 0; p < 2; p++)
        #pragma unroll
        for (int kh = 0; kh < 2; kh++) {
            int nrow  = wn * 32 + p * 16 + (lane & 7) + ((lane >> 4) & 1) * 8;
            int chunk = kh * 2 + ((lane >> 3) & 1);
            offB[p][kh] = (uint32_t)(B_OFF + nrow * 64 + ((chunk ^ ((nrow >> 1) & 3)) << 4));
        }

    float acc[4][4][4];
    #pragma unroll
    for (int i = 0; i < 4; i++)
        #pragma unroll
        for (int j = 0; j < 4; j++)
            #pragma unroll
            for (int e = 0; e < 4; e++) acc[i][j][e] = 0.0f;

    float4 pa[4], pb[4];
    auto LOADG = [&](int k0) {
        #pragma unroll
        for (int i = 0; i < 4; i++) {
            int idx = i * 256 + tid, row = idx >> 3, k4 = idx & 7;
            pa[i] = *(const float4*)&A[(long)(m0 + row) * lda + k0 + k4 * 4];
        }
        #pragma unroll
        for (int i = 0; i < 4; i++) {
            int idx = i * 256 + tid, row = idx >> 3, k4 = idx & 7;
            pb[i] = *(const float4*)&B[(long)(n0 + row) * ldb + k0 + k4 * 4];
        }
    };
    auto STORES = [&](uint32_t base) {
        #pragma unroll
        for (int i = 0; i < 4; i++) {
            int idx = i * 256 + tid, row = idx >> 3, k4 = idx & 7;
            half_split_store(base, base + A_LO, row, k4, pa[i]);
        }
        #pragma unroll
        for (int i = 0; i < 4; i++) {
            int idx = i * 256 + tid, row = idx >> 3, k4 = idx & 7;
            half_store(base + B_OFF, row, k4, pb[i]);
        }
    };

    const int nk = K >> 5;
    LOADG(0);
    STORES(sb0);
    __syncthreads();

    for (int t = 0; t < nk; t++) {
        const uint32_t sb = sb0 + (uint32_t)(t & 1) * STAGE;
        if (t + 1 < nk) LOADG((t + 1) * 32);

        #pragma unroll
        for (int kh = 0; kh < 2; kh++) {
            uint32_t ah[4][4], al[4][4];
            #pragma unroll
            for (int am = 0; am < 4; am++) {
                ldm4(ah[am], sb + offA[am][kh]);
                ldm4(al[am], sb + offA[am][kh] + A_LO);
            }
            uint32_t bh[2][4];
            #pragma unroll
            for (int p = 0; p < 2; p++)
                ldm4(bh[p], sb + offB[p][kh]);
            #pragma unroll
            for (int am = 0; am < 4; am++)
                #pragma unroll
                for (int na = 0; na < 4; na++) {
                    const uint32_t* bp = &bh[na >> 1][(na & 1) * 2];
                    mma16816h(acc[am][na], ah[am], bp);
                    mma16816h(acc[am][na], al[am], bp);
                }
        }

        if (t + 1 < nk) STORES(sb0 + (uint32_t)((t & 1) ^ 1) * STAGE);
        __syncthreads();
    }

    #pragma unroll
    for (int am = 0; am < 4; am++)
        #pragma unroll
        for (int na = 0; na < 4; na++) {
            int row = m0 + wm * 64 + am * 16 + (lane >> 2);
            int col = n0 + wn * 32 + na * 8 + (lane & 3) * 2;
            float* base0 = &C[(long)row * ldc + col];
            float* base1 = &C[(long)(row + 8) * ldc + col];
            float2 r0 = { acc[am][na][0], acc[am][na][1] };
            float2 r1 = { acc[am][na][2], acc[am][na][3] };
            if (EPI == 1) {
                float2 o0 = *(float2*)base0, o1 = *(float2*)base1;
                r0.x += o0.x; r0.y += o0.y; r1.x += o1.x; r1.y += o1.y;
            }
            *(float2*)base0 = r0;
            *(float2*)base1 = r1;
        }
}

__global__ void __launch_bounds__(256, 1)
mma_gemm_multi_2t(const float* __restrict__ A, int lda,
                  const float* __restrict__ B0g, const float* __restrict__ B1g,
                  float* __restrict__ C0g, float* __restrict__ C1g,
                  int ldb, int ldc, int K)
{
    const float* B = (blockIdx.z == 0) ? B0g : B1g;
    float*       C = (blockIdx.z == 0) ? C0g : C1g;
    gemm2t_body<0>(A, lda, B, ldb, C, ldc, K, blockIdx.x * 128, blockIdx.y * 128);
}

__global__ void __launch_bounds__(256, 1)
mma_gemm_2t_acc(const float* __restrict__ A, int lda,
                const float* __restrict__ B, int ldb,
                float* __restrict__ C, int ldc, int K)
{
    gemm2t_body<1>(A, lda, B, ldb, C, ldc, K, blockIdx.x * 128, blockIdx.y * 128);
}

// ---------------- fp16 single-term GEMM (lm_head, validated R13) ----------
__global__ void __launch_bounds__(256, 1)
mma_gemm_h(const float* __restrict__ A, int lda,
           const float* __restrict__ B, int ldb,
           float*       __restrict__ C, int ldc,
           int K)
{
    constexpr int B_OFF = 8192;
    constexpr int STAGE = 16384;

    extern __shared__ char smem[];
    const uint32_t sb0 = smem_u32(smem);

    const int tid = threadIdx.x, lane = tid & 31, wid = tid >> 5;
    const int wm = wid & 1, wn = wid >> 1;
    const int m0 = blockIdx.x * 128;
    const int n0 = blockIdx.y * 128;

    uint32_t offA[4][2], offB[2][2];
    #pragma unroll
    for (int am = 0; am < 4; am++)
        #pragma unroll
        for (int kh = 0; kh < 2; kh++) {
            int mrow  = wm * 64 + am * 16 + (lane & 7) + ((lane >> 3) & 1) * 8;
            int chunk = kh * 2 + ((lane >> 4) & 1);
            offA[am][kh] = (uint32_t)(mrow * 64 + ((chunk ^ ((mrow >> 1) & 3)) << 4));
        }
    #pragma unroll
    for (int p = 0; p < 2; p++)
        #pragma unroll
        for (int kh = 0; kh < 2; kh++) {
            int nrow  = wn * 32 + p * 16 + (lane & 7) + ((lane >> 4) & 1) * 8;
            int chunk = kh * 2 + ((lane >> 3) & 1);
            offB[p][kh] = (uint32_t)(B_OFF + nrow * 64 + ((chunk ^ ((nrow >> 1) & 3)) << 4));
        }

    float acc[4][4][4];
    #pragma unroll
    for (int i = 0; i < 4; i++)
        #pragma unroll
        for (int j = 0; j < 4; j++)
            #pragma unroll
            for (int e = 0; e < 4; e++) acc[i][j][e] = 0.0f;

    float4 pa[4], pb[4];
    auto LOADG = [&](int k0) {
        #pragma unroll
        for (int i = 0; i < 4; i++) {
            int idx = i * 256 + tid, row = idx >> 3, k4 = idx & 7;
            pa[i] = *(const float4*)&A[(long)(m0 + row) * lda + k0 + k4 * 4];
        }
        #pragma unroll
        for (int i = 0; i < 4; i++) {
            int idx = i * 256 + tid, row = idx >> 3, k4 = idx & 7;
            pb[i] = *(const float4*)&B[(long)(n0 + row) * ldb + k0 + k4 * 4];
        }
    };
    auto STORES = [&](uint32_t base) {
        #pragma unroll
        for (int i = 0; i < 4; i++) {
            int idx = i * 256 + tid, row = idx >> 3, k4 = idx & 7;
            half_store(base, row, k4, pa[i]);
        }
        #pragma unroll
        for (int i = 0; i < 4; i++) {
            int idx = i * 256 + tid, row = idx >> 3, k4 = idx & 7;
            half_store(base + B_OFF, row, k4, pb[i]);
        }
    };

    const int nk = K >> 5;
    LOADG(0);
    STORES(sb0);
    __syncthreads();

    for (int t = 0; t < nk; t++) {
        const uint32_t sb = sb0 + (uint32_t)(t & 1) * STAGE;
        if (t + 1 < nk) LOADG((t + 1) * 32);

        #pragma unroll
        for (int kh = 0; kh < 2; kh++) {
            uint32_t ah[4][4];
            #pragma unroll
            for (int am = 0; am < 4; am++)
                ldm4(ah[am], sb + offA[am][kh]);
            uint32_t bh[2][4];
            #pragma unroll
            for (int p = 0; p < 2; p++)
                ldm4(bh[p], sb + offB[p][kh]);
            #pragma unroll
            for (int am = 0; am < 4; am++)
                #pragma unroll
                for (int na = 0; na < 4; na++)
                    mma16816h(acc[am][na], ah[am], &bh[na >> 1][(na & 1) * 2]);
        }

        if (t + 1 < nk) STORES(sb0 + (uint32_t)((t & 1) ^ 1) * STAGE);
        __syncthreads();
    }

    #pragma unroll
    for (int am = 0; am < 4; am++)
        #pragma unroll
        for (int na = 0; na < 4; na++) {
            int row = m0 + wm * 64 + am * 16 + (lane >> 2);
            int col = n0 + wn * 32 + na * 8 + (lane & 3) * 2;
            float2 r0 = { acc[am][na][0], acc[am][na][1] };
            float2 r1 = { acc[am][na][2], acc[am][na][3] };
            *(float2*)&C[(long)row * ldc + col] = r0;
            *(float2*)&C[(long)(row + 8) * ldc + col] = r1;
        }
}

// ================= flash attention, s-tile 64, 2 CTAs/SM ==================
// QK^T: bf16 3-term (unchanged). P V: fp16 2-term (P hi/lo fp16, V single).
#define FA_QH  0
#define FA_QL  16384
#define FA_KH  32768
#define FA_KL  40960
#define FA_VH  49152
#define FA_PH  65536
#define FA_PL  81920
#define FA_SMX 98304
#define FA_SSM 100352
#define FA_BYTES 102400

__global__ void __launch_bounds__(256, 2)
flash_attn(const float* __restrict__ q, const float* __restrict__ k,
           const float* __restrict__ vt, float* __restrict__ y)
{
    extern __shared__ char smem[];
    const uint32_t sb = smem_u32(smem);
    float* smx = (float*)(smem + FA_SMX);
    float* ssm = (float*)(smem + FA_SSM);

    const int tid = threadIdx.x, lane = tid & 31, wid = tid >> 5;
    const int wm = wid & 1, wn = wid >> 1;
    const int bh = blockIdx.z, b = bh >> 4, hh = bh & 15;
    const int q0 = blockIdx.x * 128;

    uint32_t offA[4][2];
    #pragma unroll
    for (int am = 0; am < 4; am++)
        #pragma unroll
        for (int khi = 0; khi < 2; khi++) {
            int arow  = wm * 64 + am * 16 + (lane & 7) + ((lane >> 3) & 1) * 8;
            int chunk = khi * 2 + ((lane >> 4) & 1);
            offA[am][khi] = (uint32_t)(arow * 64 + ((chunk ^ ((arow >> 1) & 3)) << 4));
        }
    uint32_t offK[2], offV[2];
    #pragma unroll
    for (int khi = 0; khi < 2; khi++) {
        int brow  = wn * 16 + (lane & 7) + ((lane >> 4) & 1) * 8;
        int chunk = khi * 2 + ((lane >> 3) & 1);
        uint32_t o = (uint32_t)(brow * 64 + ((chunk ^ ((brow >> 1) & 3)) << 4));
        offK[khi] = o;
        offV[khi] = o;
    }

    #pragma unroll
    for (int i = 0; i < 8; i++) {
        int idx = i * 256 + tid, row = idx >> 4, k4 = idx & 15;
        float4 f = *(const float4*)&q[(long)(b * SEQ + q0 + row) * DIMN + hh * 64 + k4 * 4];
        f.x *= 0.125f; f.y *= 0.125f; f.z *= 0.125f; f.w *= 0.125f;
        split_store(sb + FA_QH + (k4 >> 3) * 8192, sb + FA_QL + (k4 >> 3) * 8192,
                    row, k4 & 7, f);
    }

    float o[4][2][4];
    float m_r[4][2], l_r[4][2];
    #pragma unroll
    for (int am = 0; am < 4; am++) {
        m_r[am][0] = m_r[am][1] = -1e30f;
        l_r[am][0] = l_r[am][1] = 0.0f;
        #pragma unroll
        for (int na = 0; na < 2; na++)
            #pragma unroll
            for (int e = 0; e < 4; e++) o[am][na][e] = 0.0f;
    }

    const int rb = wm * 64 + (lane >> 2);

    for (int s0 = 0; s0 < SEQ; s0 += 64) {
        __syncthreads();

        #pragma unroll
        for (int i = 0; i < 4; i++) {
            int idx = i * 256 + tid, row = idx >> 4, k4 = idx & 15;
            float4 f = *(const float4*)&k[(long)(b * SEQ + s0 + row) * DIMN + hh * 64 + k4 * 4];
            split_store(sb + FA_KH + (k4 >> 3) * 4096, sb + FA_KL + (k4 >> 3) * 4096,
                        row, k4 & 7, f);
        }
        #pragma unroll
        for (int i = 0; i < 4; i++) {     // V: single fp16 plane
            int idx = i * 256 + tid, row = idx >> 4, s4 = idx & 15;
            float4 f = *(const float4*)&vt[((long)bh * 64 + row) * SEQ + s0 + s4 * 4];
            half_store(sb + FA_VH + (s4 >> 3) * 4096, row, s4 & 7, f);
        }
        __syncthreads();

        float sf[4][2][4];
        #pragma unroll
        for (int am = 0; am < 4; am++)
            #pragma unroll
            for (int na = 0; na < 2; na++)
                #pragma unroll
                for (int e = 0; e < 4; e++) sf[am][na][e] = 0.0f;

        #pragma unroll
        for (int kb = 0; kb < 2; kb++)
            #pragma unroll
            for (int khi = 0; khi < 2; khi++) {
                uint32_t ah[4][4], al[4][4];
                #pragma unroll
                for (int am = 0; am < 4; am++) {
                    ldm4(ah[am], sb + FA_QH + kb * 8192 + offA[am][khi]);
                    ldm4(al[am], sb + FA_QL + kb * 8192 + offA[am][khi]);
                }
                uint32_t bhf[4], blf[4];
                ldm4(bhf, sb + FA_KH + kb * 4096 + offK[khi]);
                ldm4(blf, sb + FA_KL + kb * 4096 + offK[khi]);
                #pragma unroll
                for (int am = 0; am < 4; am++)
                    #pragma unroll
                    for (int na = 0; na < 2; na++) {
                        const uint32_t* bhp = &bhf[na * 2];
                        const uint32_t* blp = &blf[na * 2];
                        mma16816(sf[am][na], ah[am], bhp);
                        mma16816(sf[am][na], ah[am], blp);
                        mma16816(sf[am][na], al[am], bhp);
                    }
            }

        #pragma unroll
        for (int am = 0; am < 4; am++) {
            float v0 = -1e30f, v1 = -1e30f;
            #pragma unroll
            for (int na = 0; na < 2; na++) {
                v0 = fmaxf(v0, fmaxf(sf[am][na][0], sf[am][na][1]));
                v1 = fmaxf(v1, fmaxf(sf[am][na][2], sf[am][na][3]));
            }
            v0 = fmaxf(v0, __shfl_xor_sync(0xFFFFFFFFu, v0, 1));
            v0 = fmaxf(v0, __shfl_xor_sync(0xFFFFFFFFu, v0, 2));
            v1 = fmaxf(v1, __shfl_xor_sync(0xFFFFFFFFu, v1, 1));
            v1 = fmaxf(v1, __shfl_xor_sync(0xFFFFFFFFu, v1, 2));
            if ((lane & 3) == 0) {
                smx[(rb + am * 16) * 4 + wn] = v0;
                smx[(rb + am * 16 + 8) * 4 + wn] = v1;
            }
        }
        __syncthreads();

        float csc[4][2];
        #pragma unroll
        for (int am = 0; am < 4; am++) {
            int r0 = rb + am * 16, r1 = r0 + 8;
            float tm0 = fmaxf(fmaxf(smx[r0 * 4 + 0], smx[r0 * 4 + 1]),
                              fmaxf(smx[r0 * 4 + 2], smx[r0 * 4 + 3]));
            float tm1 = fmaxf(fmaxf(smx[r1 * 4 + 0], smx[r1 * 4 + 1]),
                              fmaxf(smx[r1 * 4 + 2], smx[r1 * 4 + 3]));
            float mn0 = fmaxf(m_r[am][0], tm0);
            float mn1 = fmaxf(m_r[am][1], tm1);
            csc[am][0] = __expf(m_r[am][0] - mn0);
            csc[am][1] = __expf(m_r[am][1] - mn1);
            m_r[am][0] = mn0; m_r[am][1] = mn1;

            float rs0 = 0.0f, rs1 = 0.0f;
            #pragma unroll
            for (int na = 0; na < 2; na++) {
                float p0 = __expf(sf[am][na][0] - mn0);
                float p1 = __expf(sf[am][na][1] - mn0);
                float p2 = __expf(sf[am][na][2] - mn1);
                float p3 = __expf(sf[am][na][3] - mn1);
                rs0 += p0 + p1; rs1 += p2 + p3;
                int c0col = wn * 16 + na * 8 + (lane & 3) * 2;
                int kb = c0col >> 5, cc = c0col & 31;
                uint32_t o0 = (uint32_t)(kb * 8192 + r0 * 64 +
                              (((cc >> 3) ^ ((r0 >> 1) & 3)) << 4) +
                              ((cc >> 2) & 1) * 8 + (cc & 3) * 2);
                uint32_t o1 = (uint32_t)(kb * 8192 + r1 * 64 +
                              (((cc >> 3) ^ ((r1 >> 1) & 3)) << 4) +
                              ((cc >> 2) & 1) * 8 + (cc & 3) * 2);
                // P as fp16 hi/lo (exact in [0,1] to 22 bits)
                float ra, rb2, rc, rd;
                uint32_t hi01 = pkh_res(p0, p1, &ra, &rb2);
                uint32_t hi23 = pkh_res(p2, p3, &rc, &rd);
                *(uint32_t*)(smem + FA_PH + o0) = hi01;
                *(uint32_t*)(smem + FA_PL + o0) = pkh(ra, rb2);
                *(uint32_t*)(smem + FA_PH + o1) = hi23;
                *(uint32_t*)(smem + FA_PL + o1) = pkh(rc, rd);
            }
            rs0 += __shfl_xor_sync(0xFFFFFFFFu, rs0, 1);
            rs0 += __shfl_xor_sync(0xFFFFFFFFu, rs0, 2);
            rs1 += __shfl_xor_sync(0xFFFFFFFFu, rs1, 1);
            rs1 += __shfl_xor_sync(0xFFFFFFFFu, rs1, 2);
            if ((lane & 3) == 0) {
                ssm[r0 * 4 + wn] = rs0;
                ssm[r1 * 4 + wn] = rs1;
            }
        }
        __syncthreads();

        #pragma unroll
        for (int am = 0; am < 4; am++) {
            int r0 = rb + am * 16, r1 = r0 + 8;
            float s0s = ssm[r0 * 4 + 0] + ssm[r0 * 4 + 1] + ssm[r0 * 4 + 2] + ssm[r0 * 4 + 3];
            float s1s = ssm[r1 * 4 + 0] + ssm[r1 * 4 + 1] + ssm[r1 * 4 + 2] + ssm[r1 * 4 + 3];
            l_r[am][0] = l_r[am][0] * csc[am][0] + s0s;
            l_r[am][1] = l_r[am][1] * csc[am][1] + s1s;
            #pragma unroll
            for (int na = 0; na < 2; na++) {
                o[am][na][0] *= csc[am][0]; o[am][na][1] *= csc[am][0];
                o[am][na][2] *= csc[am][1]; o[am][na][3] *= csc[am][1];
            }
        }

        // O += P V   (fp16 2-term: Ph*V + Pl*V)
        #pragma unroll
        for (int kb = 0; kb < 2; kb++)
            #pragma unroll
            for (int khi = 0; khi < 2; khi++) {
                uint32_t ah[4][4], al[4][4];
                #pragma unroll
                for (int am = 0; am < 4; am++) {
                    ldm4(ah[am], sb + FA_PH + kb * 8192 + offA[am][khi]);
                    ldm4(al[am], sb + FA_PL + kb * 8192 + offA[am][khi]);
                }
                uint32_t bhf[4];
                ldm4(bhf, sb + FA_VH + kb * 4096 + offV[khi]);
                #pragma unroll
                for (int am = 0; am < 4; am++)
                    #pragma unroll
                    for (int na = 0; na < 2; na++) {
                        const uint32_t* bhp = &bhf[na * 2];
                        mma16816h(o[am][na], ah[am], bhp);
                        mma16816h(o[am][na], al[am], bhp);
                    }
            }
    }

    #pragma unroll
    for (int am = 0; am < 4; am++) {
        float inv0 = 1.0f / l_r[am][0];
        float inv1 = 1.0f / l_r[am][1];
        long tok0 = (long)(b * SEQ + q0 + wm * 64 + am * 16 + (lane >> 2));
        #pragma unroll
        for (int na = 0; na < 2; na++) {
            int col = hh * 64 + wn * 16 + na * 8 + (lane & 3) * 2;
            float2 r0 = { o[am][na][0] * inv0, o[am][na][1] * inv0 };
            float2 r1 = { o[am][na][2] * inv1, o[am][na][3] * inv1 };
            *(float2*)&y[tok0 * DIMN + col] = r0;
            *(float2*)&y[(tok0 + 8) * DIMN + col] = r1;
        }
    }
}

// ---------------- elementwise kernels ----------------
__global__ void embed_kernel(const int* __restrict__ tokens,
                             const float* __restrict__ embed,
                             float* __restrict__ h)
{
    int row = blockIdx.x;
    int tok = tokens[row];
    ((float4*)(h + (long)row * DIMN))[threadIdx.x] =
        ((const float4*)(embed + (long)tok * DIMN))[threadIdx.x];
}

__global__ void rmsnorm_kernel(const float* __restrict__ x,
                               const float* __restrict__ w,
                               float* __restrict__ out)
{
    int row = blockIdx.x;
    float4 v = ((const float4*)(x + (long)row * DIMN))[threadIdx.x];
    float ss = v.x*v.x + v.y*v.y + v.z*v.z + v.w*v.w;
    __shared__ float red[8];
    #pragma unroll
    for (int o = 16; o > 0; o >>= 1) ss += __shfl_xor_sync(0xFFFFFFFFu, ss, o);
    if ((threadIdx.x & 31) == 0) red[threadIdx.x >> 5] = ss;
    __syncthreads();
    if (threadIdx.x < 8) {
        float s = red[threadIdx.x];
        #pragma unroll
        for (int o = 4; o > 0; o >>= 1) s += __shfl_xor_sync(0xFFu, s, o);
        if (threadIdx.x == 0) red[0] = s;
    }
    __syncthreads();
    float scale = rsqrtf(red[0] * (1.0f / DIMN) + EPS);
    float4 wv = ((const float4*)w)[threadIdx.x];
    float4 o4 = { v.x*scale*wv.x, v.y*scale*wv.y, v.z*scale*wv.z, v.w*scale*wv.w };
    ((float4*)(out + (long)row * DIMN))[threadIdx.x] = o4;
}

__global__ void silu_mul_kernel(float4* __restrict__ g, const float4* __restrict__ u)
{
    long i = (long)blockIdx.x * blockDim.x + threadIdx.x;
    float4 gv = g[i], uv = u[i];
    gv.x = gv.x / (1.0f + __expf(-gv.x)) * uv.x;
    gv.y = gv.y / (1.0f + __expf(-gv.y)) * uv.y;
    gv.z = gv.z / (1.0f + __expf(-gv.z)) * uv.z;
    gv.w = gv.w / (1.0f + __expf(-gv.w)) * uv.w;
    g[i] = gv;
}

// vt[(b*H+h)][d][s] = v[b*SEQ+s][h*64+d]
__global__ void transpose_v_kernel(const float* __restrict__ v, float* __restrict__ vt)
{
    __shared__ float t[32][33];
    int bh = blockIdx.z, b = bh >> 4, hh = bh & 15;
    int s0 = blockIdx.x * 32, d0 = blockIdx.y * 32;
    int tx = threadIdx.x, ty = threadIdx.y;    // 32 x 8
    #pragma unroll
    for (int j = 0; j < 32; j += 8)
        t[ty + j][tx] = v[(long)(b * SEQ + s0 + ty + j) * DIMN + hh * HEAD_DIM + d0 + tx];
    __syncthreads();
    #pragma unroll
    for (int j = 0; j < 32; j += 8)
        vt[((long)bh * HEAD_DIM + d0 + ty + j) * SEQ + s0 + tx] = t[tx][ty + j];
}

// ---------------- launcher ----------------
extern "C" void kernel_launch(void* const* d_in, const int* in_sizes, int n_in,
                              void* d_out, int out_size)
{
    const int*   tokens  = (const int*)  d_in[0];
    const float* embed   = (const float*)d_in[1];
    const float* Wq      = (const float*)d_in[2];
    const float* Wk      = (const float*)d_in[3];
    const float* Wv      = (const float*)d_in[4];
    const float* Wo      = (const float*)d_in[5];
    const float* Wg      = (const float*)d_in[6];
    const float* Wu      = (const float*)d_in[7];
    const float* Wd      = (const float*)d_in[8];
    const float* ln1     = (const float*)d_in[9];
    const float* ln2     = (const float*)d_in[10];
    const float* norm_w  = (const float*)d_in[11];
    const float* lm_head = (const float*)d_in[12];
    float* out = (float*)d_out;

    float *h, *x, *q, *k, *v, *vt, *y, *gate, *up;
    cudaGetSymbolAddress((void**)&h,    g_h);
    cudaGetSymbolAddress((void**)&x,    g_x);
    cudaGetSymbolAddress((void**)&q,    g_q);
    cudaGetSymbolAddress((void**)&k,    g_k);
    cudaGetSymbolAddress((void**)&v,    g_v);
    cudaGetSymbolAddress((void**)&vt,   g_vt);
    cudaGetSymbolAddress((void**)&y,    g_y);
    cudaGetSymbolAddress((void**)&gate, g_gate);
    cudaGetSymbolAddress((void**)&up,   g_up);

    const int DYN128 = 2 * (16384 + 128 * 128);   // 65536
    const int DYNH   = 2 * 16384;                 // 32768
    const int DYN2T  = 2 * 24576;                 // 49152
    cudaFuncSetAttribute(mma_gemm<128, false>, cudaFuncAttributeMaxDynamicSharedMemorySize, DYN128);
    cudaFuncSetAttribute(mma_gemm<128, true>,  cudaFuncAttributeMaxDynamicSharedMemorySize, DYN128);
    cudaFuncSetAttribute(mma_gemm_multi,       cudaFuncAttributeMaxDynamicSharedMemorySize, DYN128);
    cudaFuncSetAttribute(mma_gemm_multi_2t,    cudaFuncAttributeMaxDynamicSharedMemorySize, DYN2T);
    cudaFuncSetAttribute(mma_gemm_2t_acc,      cudaFuncAttributeMaxDynamicSharedMemorySize, DYN2T);
    cudaFuncSetAttribute(mma_gemm_h,           cudaFuncAttributeMaxDynamicSharedMemorySize, DYNH);
    cudaFuncSetAttribute(flash_attn, cudaFuncAttributeMaxDynamicSharedMemorySize, FA_BYTES);

    embed_kernel<<<MTOK, 256>>>(tokens, embed, h);

    dim3 gQKV (MTOK / 128, DIMN / 128, 3);
    dim3 gGU  (MTOK / 128, HIDDEN / 128, 2);
    dim3 gProj(MTOK / 128, DIMN / 128, 1);
    dim3 gHead(MTOK / 128, VOCAB / 128, 1);
    dim3 gFa  (SEQ / 128, 1, BATCH * HEADS);
    dim3 gTr  (SEQ / 32, HEAD_DIM / 32, BATCH * HEADS);

    for (int l = 0; l < LAYERS; l++) {
        const float* wq = Wq + (long)l * DIMN * DIMN;
        const float* wk = Wk + (long)l * DIMN * DIMN;
        const float* wv = Wv + (long)l * DIMN * DIMN;
        const float* wo = Wo + (long)l * DIMN * DIMN;
        const float* wg = Wg + (long)l * HIDDEN * DIMN;
        const float* wu = Wu + (long)l * HIDDEN * DIMN;
        const float* wd = Wd + (long)l * DIMN * HIDDEN;

        rmsnorm_kernel<<<MTOK, 256>>>(h, ln1 + (long)l * DIMN, x);

        // QKV stays 3-term bf16 (softmax-sensitive path — do not degrade)
        {
            P3 p = { wq, wk, wv, q, k, v };
            mma_gemm_multi<<<gQKV, 256, DYN128>>>(x, DIMN, p, DIMN, DIMN, DIMN, 1.0f);
        }

        transpose_v_kernel<<<gTr, dim3(32, 8)>>>(v, vt);
        flash_attn<<<gFa, 256, FA_BYTES>>>(q, k, vt, y);

        // h += y @ Wo^T — fp16 2-term accumulate
        mma_gemm_2t_acc<<<gProj, 256, DYN2T>>>(y, DIMN, wo, DIMN,
                                               h, DIMN, DIMN);

        rmsnorm_kernel<<<MTOK, 256>>>(h, ln2 + (long)l * DIMN, x);

        // fused gate,up = x @ {Wg,Wu}^T — fp16 2-term
        mma_gemm_multi_2t<<<gGU, 256, DYN2T>>>(x, DIMN, wg, wu, gate, up,
                                               DIMN, HIDDEN, DIMN);

        silu_mul_kernel<<<(MTOK * (long)HIDDEN / 4) / 256, 256>>>((float4*)gate, (const float4*)up);

        // h += gate @ Wd^T — fp16 2-term accumulate
        mma_gemm_2t_acc<<<gProj, 256, DYN2T>>>(gate, HIDDEN, wd, HIDDEN,
                                               h, DIMN, HIDDEN);
    }

    rmsnorm_kernel<<<MTOK, 256>>>(h, norm_w, x);
    mma_gemm_h<<<gHead, 256, DYNH>>>(x, DIMN, lm_head, DIMN, out, VOCAB, DIMN);
}